// round 7
// baseline (speedup 1.0000x reference)
#include <cuda_runtime.h>
#include <math.h>

#define BB 8
#define NPTS 2048
#define KNB 32
#define MSEL 1024
#define CF 128
#define LRELU 0.2f
#define ATTN_SCALE 0.088388347648318447f

// ---------------- static device scratch ----------------
static __device__ float g_big[(size_t)BB*NPTS*NPTS];
static __device__ float g_h[(size_t)BB*256*NPTS];
static __device__ float g_hfull[(size_t)BB*CF*NPTS];
static __device__ float g_bq[(size_t)BB*CF*NPTS];
static __device__ float g_bk[(size_t)BB*CF*NPTS];
static __device__ float g_bv[(size_t)BB*CF*NPTS];
static __device__ float g_ba[(size_t)BB*CF*NPTS];
static __device__ float g_by[(size_t)BB*CF*NPTS];
static __device__ float g_f1[(size_t)BB*512*NPTS];
static __device__ float g_s1[(size_t)BB*CF*NPTS];
static __device__ float g_s2[(size_t)BB*CF*NPTS];
static __device__ float g_hd[(size_t)BB*CF*MSEL];
static __device__ float g_hu[(size_t)BB*CF*NPTS];
static __device__ float g_xtmp[(size_t)BB*CF*NPTS];
static __device__ float g_xh[(size_t)BB*1024*NPTS];
static __device__ float g_xc[(size_t)BB*1024*NPTS];
static __device__ float g_xc2[(size_t)BB*256*NPTS];
static __device__ float g_sqn[(size_t)BB*NPTS];
static __device__ float g_score[(size_t)BB*NPTS];
static __device__ float g_gv[(size_t)BB*2112];
static __device__ float g_bias[(size_t)BB*1024];
static __device__ float g_mu[1024];
static __device__ float g_rstd[1024];
static __device__ int   g_idx[(size_t)BB*NPTS*KNB];
static __device__ int   g_sel[(size_t)BB*MSEL];

// ---------------- generic strided batched GEMM (128x128 tile, 8x8 microtile) ----------------
// O[bz*o_b + i*o_i + j] = sum_k A[bz*a_b + i*a_i + k*a_k] * B[bz*b_b + k*b_k + j*b_j]
// Per-output accumulation is a single accumulator over strictly ascending k
// (bitwise-identical to previous rounds' kernel).
__global__ void __launch_bounds__(256)
gemm_kernel(const float* __restrict__ A, const float* __restrict__ Bm,
            float* __restrict__ O, int I, int J, int Kd,
            long a_b, long a_i, long a_k,
            long b_b, long b_k, long b_j,
            long o_b, long o_i)
{
    __shared__ float As[8][132];
    __shared__ float Bs[8][132];
    int bz = blockIdx.z;
    const float* Ab = A + (long)bz*a_b;
    const float* Bb = Bm + (long)bz*b_b;
    int i0 = blockIdx.y*128, j0 = blockIdx.x*128;
    int tid = threadIdx.x;
    int tx = tid & 15, ty = tid >> 4;
    float acc[8][8] = {};
    for (int k0 = 0; k0 < Kd; k0 += 8) {
        #pragma unroll
        for (int r = 0; r < 4; r++) {
            int e = tid*4 + r;
            int ii, kk;
            if (a_k == 1) { ii = e >> 3; kk = e & 7; }
            else          { kk = e >> 7; ii = e & 127; }
            float v = 0.f;
            if (i0+ii < I && k0+kk < Kd) v = Ab[(long)(i0+ii)*a_i + (long)(k0+kk)*a_k];
            As[kk][ii] = v;
        }
        #pragma unroll
        for (int r = 0; r < 4; r++) {
            int e = tid*4 + r;
            int jj, kk;
            if (b_j == 1) { jj = e & 127; kk = e >> 7; }
            else          { jj = e >> 3;  kk = e & 7; }
            float v = 0.f;
            if (j0+jj < J && k0+kk < Kd) v = Bb[(long)(k0+kk)*b_k + (long)(j0+jj)*b_j];
            Bs[kk][jj] = v;
        }
        __syncthreads();
        #pragma unroll
        for (int kk = 0; kk < 8; kk++) {
            float4 a0 = *(const float4*)&As[kk][ty*8];
            float4 a1 = *(const float4*)&As[kk][ty*8+4];
            float4 b0 = *(const float4*)&Bs[kk][tx*8];
            float4 b1 = *(const float4*)&Bs[kk][tx*8+4];
            float av[8] = {a0.x,a0.y,a0.z,a0.w,a1.x,a1.y,a1.z,a1.w};
            float bw[8] = {b0.x,b0.y,b0.z,b0.w,b1.x,b1.y,b1.z,b1.w};
            #pragma unroll
            for (int u = 0; u < 8; u++)
                #pragma unroll
                for (int v = 0; v < 8; v++) acc[u][v] += av[u]*bw[v];
        }
        __syncthreads();
    }
    #pragma unroll
    for (int u = 0; u < 8; u++) {
        int i = i0 + ty*8 + u;
        if (i >= I) continue;
        #pragma unroll
        for (int v = 0; v < 8; v++) {
            int j = j0 + tx*8 + v;
            if (j < J) O[(long)bz*o_b + (long)i*o_i + j] = acc[u][v];
        }
    }
}

static void gemm_launch(const float* A, const float* B, float* O,
                        int Bn, int I, int J, int Kd,
                        long a_b, long a_i, long a_k,
                        long b_b, long b_k, long b_j,
                        long o_b, long o_i)
{
    dim3 grid((J+127)/128, (I+127)/128, Bn);
    gemm_kernel<<<grid, 256>>>(A,B,O,I,J,Kd,a_b,a_i,a_k,b_b,b_k,b_j,o_b,o_i);
}
static void gemmW(const float* W, int Oc, int Kd, int rowlen,
                  const float* X, long xbs, int Np, float* O, long obs)
{
    gemm_launch(W, X, O, BB, Oc, Np, Kd, 0, rowlen, 1, xbs, Np, 1, obs, Np);
}
static void gemmTN(const float* X, long xbs, int Np,
                   const float* Y, long ybs, int Mp, int Cin, float* S)
{
    gemm_launch(X, Y, S, BB, Np, Mp, Cin, xbs, 1, Np, ybs, Mp, 1, (long)Np*Mp, Mp);
}

// ---------------- helper kernels ----------------
__global__ void sqnorm_kernel(const float* __restrict__ x, float* __restrict__ sq,
                              int Cin, int Np, long bstride)
{
    int b = blockIdx.y;
    int n = blockIdx.x*256 + threadIdx.x;
    if (n >= Np) return;
    const float* p = x + (long)b*bstride + n;
    float s = 0.f;
    for (int c = 0; c < Cin; c++) { float v = p[(long)c*Np]; s += v*v; }
    sq[(long)b*Np + n] = s;
}

// Register-resident warp-chunk top-32 selection. Distances computed with the
// identical expression as before; lexicographic (d, idx) comparisons everywhere,
// so selected indices are identical to previous rounds.
__global__ void knn_topk_kernel(const float* __restrict__ inner, const float* __restrict__ sq,
                                int* __restrict__ idxout, int Np)
{
    __shared__ float sv[8][32];
    __shared__ int   si[8][32];
    int row = blockIdx.x;
    int b = row / Np, n = row % Np;
    int t = threadIdx.x, w = t >> 5, lane = t & 31;
    int chunk = Np >> 3;           // 256 (N) or 128 (M)
    int per = chunk >> 5;          // 8 or 4
    const float* ir = inner + ((size_t)b*Np + n)*Np;
    const float* sqb = sq + (size_t)b*Np;
    float sn = sqb[n];
    int base = w*chunk;
    float dv[8];
    #pragma unroll
    for (int j = 0; j < 8; j++) {
        if (j < per) {
            int m = base + j*32 + lane;
            dv[j] = sn - 2.0f*ir[m] + sqb[m];
        } else dv[j] = 3.4e38f;
    }
    // each warp: 32 lex-min selections from its chunk
    for (int k = 0; k < KNB; k++) {
        float bv = 3.4e38f; int bj = 0;
        #pragma unroll
        for (int j = 0; j < 8; j++) if (dv[j] < bv) { bv = dv[j]; bj = j; }
        int bi = base + bj*32 + lane;
        #pragma unroll
        for (int o = 16; o; o >>= 1) {
            float ov = __shfl_xor_sync(0xffffffffu, bv, o);
            int   oi = __shfl_xor_sync(0xffffffffu, bi, o);
            if (ov < bv || (ov == bv && oi < bi)) { bv = ov; bi = oi; }
        }
        if ((bi & 31) == lane) dv[(bi - base) >> 5] = 3.4e38f;
        if (lane == 0) { sv[w][k] = bv; si[w][k] = bi; }
    }
    __syncthreads();
    // warp 0 merges the 8 sorted candidate lists (256 candidates, unique indices)
    if (w == 0) {
        float cv[8]; int ci[8];
        #pragma unroll
        for (int j = 0; j < 8; j++) {
            int c = lane*8 + j;
            cv[j] = sv[c >> 5][c & 31];
            ci[j] = si[c >> 5][c & 31];
        }
        int* op = idxout + (size_t)row*KNB;
        for (int k = 0; k < KNB; k++) {
            float bv = 3.4e38f; int bi = 0x7fffffff; int bj = -1;
            #pragma unroll
            for (int j = 0; j < 8; j++) {
                if (cv[j] < bv || (cv[j] == bv && ci[j] < bi)) { bv = cv[j]; bi = ci[j]; bj = j; }
            }
            float rbv = bv; int rbi = bi;
            #pragma unroll
            for (int o = 16; o; o >>= 1) {
                float ov = __shfl_xor_sync(0xffffffffu, rbv, o);
                int   oi = __shfl_xor_sync(0xffffffffu, rbi, o);
                if (ov < rbv || (ov == rbv && oi < rbi)) { rbv = ov; rbi = oi; }
            }
            if (bj >= 0 && rbi == bi) cv[bj] = 3.4e38f;   // candidate indices unique
            if (lane == 0) op[k] = rbi;
        }
    }
}

// v_k = A - Bm + Bm[idx_k]; max -> pre, sum/sumsq -> s1/s2
__global__ void edge_pass1_kernel(const float* __restrict__ A, const float* __restrict__ Bm,
                                  const int* __restrict__ idx, float* __restrict__ pre,
                                  float* __restrict__ s1, float* __restrict__ s2,
                                  int Np, long pre_bs)
{
    size_t i = (size_t)blockIdx.x*256 + threadIdx.x;
    if (i >= (size_t)BB*CF*Np) return;
    int n = (int)(i % Np); size_t tt = i / Np;
    int o = (int)(tt % CF); int b = (int)(tt / CF);
    size_t base = ((size_t)b*CF + o)*Np;
    float a = A[base+n], bm = Bm[base+n];
    float diff = a - bm;
    const int* ip = idx + ((size_t)b*Np + n)*KNB;
    const float* Br = Bm + base;
    float s = 0.f, ss = 0.f, mx = -3.4e38f;
    #pragma unroll 4
    for (int k = 0; k < KNB; k++) {
        float v = diff + Br[ip[k]];
        s += v; ss += v*v; mx = fmaxf(mx, v);
    }
    pre[(size_t)b*pre_bs + (size_t)o*Np + n] = mx;
    s1[i] = s; s2[i] = ss;
}

__global__ void bn_stats_kernel(const float* __restrict__ x, float* __restrict__ mu,
                                float* __restrict__ rstd, long bstride, int Np, double invcount)
{
    int o = blockIdx.x, t = threadIdx.x;
    double s = 0.0, ss = 0.0;
    for (int b = 0; b < BB; b++) {
        const float* p = x + (long)b*bstride + (long)o*Np;
        for (int n = t; n < Np; n += 256) { double v = p[n]; s += v; ss += v*v; }
    }
    __shared__ double sh1[256], sh2[256];
    sh1[t] = s; sh2[t] = ss; __syncthreads();
    for (int st = 128; st; st >>= 1) {
        if (t < st) { sh1[t] += sh1[t+st]; sh2[t] += sh2[t+st]; }
        __syncthreads();
    }
    if (!t) {
        double m = sh1[0]*invcount;
        double var = sh2[0]*invcount - m*m;
        mu[o] = (float)m;
        rstd[o] = (float)(1.0/sqrt(var + 1e-5));
    }
}

__global__ void bn_stats2_kernel(const float* __restrict__ s1, const float* __restrict__ s2,
                                 float* __restrict__ mu, float* __restrict__ rstd,
                                 long bstride, int Np, double invcount)
{
    int o = blockIdx.x, t = threadIdx.x;
    double s = 0.0, ss = 0.0;
    for (int b = 0; b < BB; b++) {
        const float* p1 = s1 + (long)b*bstride + (long)o*Np;
        const float* p2 = s2 + (long)b*bstride + (long)o*Np;
        for (int n = t; n < Np; n += 256) { s += (double)p1[n]; ss += (double)p2[n]; }
    }
    __shared__ double sh1[256], sh2[256];
    sh1[t] = s; sh2[t] = ss; __syncthreads();
    for (int st = 128; st; st >>= 1) {
        if (t < st) { sh1[t] += sh1[t+st]; sh2[t] += sh2[t+st]; }
        __syncthreads();
    }
    if (!t) {
        double m = sh1[0]*invcount;
        double var = sh2[0]*invcount - m*m;
        mu[o] = (float)m;
        rstd[o] = (float)(1.0/sqrt(var + 1e-5));
    }
}

__global__ void bn_apply_kernel(const float* __restrict__ x, const float* __restrict__ res,
                                float* __restrict__ out, const float* __restrict__ mu,
                                const float* __restrict__ rstd, size_t total,
                                int Np, int Cch, long bstride)
{
    size_t i = (size_t)blockIdx.x*256 + threadIdx.x;
    if (i >= total) return;
    int n = (int)(i % Np); size_t tt = i / Np;
    int o = (int)(tt % Cch); int b = (int)(tt / Cch);
    size_t off = (size_t)b*bstride + (size_t)o*Np + n;
    float v = (x[off] - mu[o]) * rstd[o];
    v = v >= 0.f ? v : LRELU*v;
    out[off] = (res ? res[off] : 0.f) + v;
}

__global__ void attn_kernel(const float* __restrict__ q, const float* __restrict__ Km,
                            const float* __restrict__ Vm, const int* __restrict__ idx,
                            float* __restrict__ out, int Np)
{
    int bn = blockIdx.x;
    int b = bn / Np, n = bn % Np;
    int t = threadIdx.x, w = t >> 5, lane = t & 31;
    size_t base = (size_t)b*CF*Np;
    __shared__ int   sidx[KNB];
    __shared__ float part[4][KNB];
    __shared__ float aw[KNB];
    if (t < KNB) sidx[t] = idx[(size_t)bn*KNB + t];
    __syncthreads();
    float qc = q[base + (size_t)t*Np + n];
    const float* Kb = Km + base + (size_t)t*Np;
    for (int k = 0; k < KNB; k++) {
        float v = qc * Kb[sidx[k]];
        #pragma unroll
        for (int o = 16; o; o >>= 1) v += __shfl_down_sync(0xffffffffu, v, o);
        if (lane == 0) part[w][k] = v;
    }
    __syncthreads();
    if (w == 0) {
        float l = (part[0][lane] + part[1][lane] + part[2][lane] + part[3][lane]) * ATTN_SCALE;
        float m = l;
        #pragma unroll
        for (int o = 16; o; o >>= 1) m = fmaxf(m, __shfl_xor_sync(0xffffffffu, m, o));
        float e = expf(l - m);
        float s = e;
        #pragma unroll
        for (int o = 16; o; o >>= 1) s += __shfl_xor_sync(0xffffffffu, s, o);
        aw[lane] = e / s;
    }
    __syncthreads();
    const float* Vb = Vm + base + (size_t)t*Np;
    float acc = 0.f;
    for (int k = 0; k < KNB; k++) acc += aw[k]*Vb[sidx[k]];
    out[base + (size_t)t*Np + n] = acc;
}

__global__ void softmax_kernel(float* __restrict__ S, int M, float scale)
{
    __shared__ float sh[NPTS];
    __shared__ float red[256];
    size_t row = blockIdx.x;
    float* r = S + row*(size_t)M;
    int t = threadIdx.x;
    float mx = -3.4e38f;
    for (int i = t; i < M; i += 256) { float v = r[i]*scale; sh[i] = v; mx = fmaxf(mx, v); }
    red[t] = mx; __syncthreads();
    for (int s = 128; s; s >>= 1) { if (t < s) red[t] = fmaxf(red[t], red[t+s]); __syncthreads(); }
    mx = red[0]; __syncthreads();
    float sum = 0.f;
    for (int i = t; i < M; i += 256) { float e = expf(sh[i] - mx); sh[i] = e; sum += e; }
    red[t] = sum; __syncthreads();
    for (int s = 128; s; s >>= 1) { if (t < s) red[t] += red[t+s]; __syncthreads(); }
    float inv = 1.0f/red[0];
    for (int i = t; i < M; i += 256) r[i] = sh[i]*inv;
}

__global__ void colmean_kernel(const float* __restrict__ S, float* __restrict__ score, int R, int M)
{
    int b = blockIdx.y;
    int m = blockIdx.x*256 + threadIdx.x;
    if (m >= M) return;
    const float* p = S + (size_t)b*R*M + m;
    float s = 0.f;
    for (int n = 0; n < R; n++) s += p[(size_t)n*M];
    score[(size_t)b*M + m] = s / (float)R;
}

__global__ void topm_kernel(const float* __restrict__ score, int* __restrict__ sel)
{
    __shared__ float v[NPTS];
    __shared__ int   id[NPTS];
    int b = blockIdx.x, t = threadIdx.x;
    for (int i = t; i < NPTS; i += 1024) { v[i] = score[(size_t)b*NPTS + i]; id[i] = i; }
    __syncthreads();
    for (int k = 2; k <= NPTS; k <<= 1) {
        for (int j = k >> 1; j > 0; j >>= 1) {
            for (int i = t; i < NPTS; i += 1024) {
                int p = i ^ j;
                if (p > i) {
                    bool up = ((i & k) == 0);
                    float vi = v[i], vp = v[p]; int ii = id[i], ip = id[p];
                    bool inOrder = (vi > vp) || (vi == vp && ii < ip);
                    if (up ? !inOrder : inOrder) { v[i]=vp; v[p]=vi; id[i]=ip; id[p]=ii; }
                }
            }
            __syncthreads();
        }
    }
    for (int i = t; i < MSEL; i += 1024) sel[(size_t)b*MSEL + i] = id[i];
}

__global__ void gather_kernel(const float* __restrict__ x, const int* __restrict__ sel,
                              float* __restrict__ out, int Np, int Ms)
{
    size_t i = (size_t)blockIdx.x*256 + threadIdx.x;
    if (i >= (size_t)BB*CF*Ms) return;
    int j = (int)(i % Ms); size_t tt = i / Ms;
    int c = (int)(tt % CF); int b = (int)(tt / CF);
    out[i] = x[((size_t)b*CF + c)*Np + sel[(size_t)b*Ms + j]];
}

__global__ void add_kernel(const float* __restrict__ a, const float* __restrict__ b,
                           float* __restrict__ o, size_t total)
{
    size_t i = (size_t)blockIdx.x*256 + threadIdx.x;
    if (i < total) o[i] = a[i] + b[i];
}

__global__ void maxmean_kernel(const float* __restrict__ xh, float* __restrict__ g, int Np)
{
    __shared__ float rm[256], rs[256];
    int bo = blockIdx.x;
    int b = bo >> 10, o = bo & 1023;
    const float* p = xh + ((size_t)b*1024 + o)*Np;
    int t = threadIdx.x;
    float mx = -3.4e38f, s = 0.f;
    for (int n = t; n < Np; n += 256) { float v = p[n]; mx = fmaxf(mx, v); s += v; }
    rm[t] = mx; rs[t] = s; __syncthreads();
    for (int st = 128; st; st >>= 1) {
        if (t < st) { rm[t] = fmaxf(rm[t], rm[t+st]); rs[t] += rs[t+st]; }
        __syncthreads();
    }
    if (!t) { g[(size_t)b*2112 + o] = rm[0]; g[(size_t)b*2112 + 1024 + o] = rs[0]/(float)Np; }
}

__global__ void cid_kernel(const float* __restrict__ cat, const float* __restrict__ Wc1,
                           float* __restrict__ g)
{
    int o = threadIdx.x;   // 64
    float y[BB];
    for (int b = 0; b < BB; b++) {
        float s = 0.f;
        for (int c = 0; c < 16; c++) s += Wc1[o*16+c]*cat[b*16+c];
        y[b] = s;
    }
    float mu = 0.f;
    for (int b = 0; b < BB; b++) mu += y[b];
    mu *= (1.0f/BB);
    float var = 0.f;
    for (int b = 0; b < BB; b++) { float dd = y[b]-mu; var += dd*dd; }
    var *= (1.0f/BB);
    float rs = rsqrtf(var + 1e-5f);
    for (int b = 0; b < BB; b++) {
        float v = (y[b]-mu)*rs;
        g[(size_t)b*2112 + 2048 + o] = v >= 0.f ? v : LRELU*v;
    }
}

__global__ void bias_kernel(const float* __restrict__ W, const float* __restrict__ g,
                            float* __restrict__ bias)
{
    int gw = blockIdx.x*8 + (threadIdx.x >> 5);
    if (gw >= BB*1024) return;
    int lane = threadIdx.x & 31;
    int b = gw >> 10, o = gw & 1023;
    const float* wr = W + (size_t)o*2240;
    const float* gb = g + (size_t)b*2112;
    float s = 0.f;
    for (int c = lane; c < 2112; c += 32) s += wr[c]*gb[c];
    #pragma unroll
    for (int off = 16; off; off >>= 1) s += __shfl_down_sync(0xffffffffu, s, off);
    if (!lane) bias[(size_t)b*1024 + o] = s;
}

__global__ void addbias_kernel(float* __restrict__ xc, const float* __restrict__ bias)
{
    size_t i = (size_t)blockIdx.x*256 + threadIdx.x;
    if (i >= (size_t)BB*1024*NPTS) return;
    size_t tt = i / NPTS;
    int o = (int)(tt % 1024); int b = (int)(tt / 1024);
    xc[i] += bias[(size_t)b*1024 + o];
}

// ---------------- host orchestration ----------------
struct Bufs {
    float *big,*h,*hfull,*bq,*bk,*bv,*ba,*by,*f1,*s1,*s2,*hd,*hu,*xtmp,*xh,*xc,*xc2;
    float *sq,*score,*gv,*bias,*mu,*rstd;
    int *idx,*sel;
};

static void getbufs(Bufs& P)
{
    cudaGetSymbolAddress((void**)&P.big, g_big);
    cudaGetSymbolAddress((void**)&P.h, g_h);
    cudaGetSymbolAddress((void**)&P.hfull, g_hfull);
    cudaGetSymbolAddress((void**)&P.bq, g_bq);
    cudaGetSymbolAddress((void**)&P.bk, g_bk);
    cudaGetSymbolAddress((void**)&P.bv, g_bv);
    cudaGetSymbolAddress((void**)&P.ba, g_ba);
    cudaGetSymbolAddress((void**)&P.by, g_by);
    cudaGetSymbolAddress((void**)&P.f1, g_f1);
    cudaGetSymbolAddress((void**)&P.s1, g_s1);
    cudaGetSymbolAddress((void**)&P.s2, g_s2);
    cudaGetSymbolAddress((void**)&P.hd, g_hd);
    cudaGetSymbolAddress((void**)&P.hu, g_hu);
    cudaGetSymbolAddress((void**)&P.xtmp, g_xtmp);
    cudaGetSymbolAddress((void**)&P.xh, g_xh);
    cudaGetSymbolAddress((void**)&P.xc, g_xc);
    cudaGetSymbolAddress((void**)&P.xc2, g_xc2);
    cudaGetSymbolAddress((void**)&P.sq, g_sqn);
    cudaGetSymbolAddress((void**)&P.score, g_score);
    cudaGetSymbolAddress((void**)&P.gv, g_gv);
    cudaGetSymbolAddress((void**)&P.bias, g_bias);
    cudaGetSymbolAddress((void**)&P.mu, g_mu);
    cudaGetSymbolAddress((void**)&P.rstd, g_rstd);
    cudaGetSymbolAddress((void**)&P.idx, g_idx);
    cudaGetSymbolAddress((void**)&P.sel, g_sel);
}

static inline size_t cdiv(size_t a, size_t b) { return (a + b - 1)/b; }

static void run_bn(float* x, const float* res, float* out, int Cch, int Np, long bstride, Bufs& P)
{
    bn_stats_kernel<<<Cch, 256>>>(x, P.mu, P.rstd, bstride, Np, 1.0/((double)BB*Np));
    size_t total = (size_t)BB*Cch*Np;
    bn_apply_kernel<<<(unsigned)cdiv(total,256), 256>>>(x, res, out, P.mu, P.rstd, total, Np, Cch, bstride);
}

static void run_knn(const float* xin, long xbs, int cin, int Np, Bufs& P)
{
    dim3 gs((Np+255)/256, BB);
    sqnorm_kernel<<<gs, 256>>>(xin, P.sq, cin, Np, xbs);
    gemmTN(xin, xbs, Np, xin, xbs, Np, cin, P.big);
    knn_topk_kernel<<<BB*Np, 256>>>(P.big, P.sq, P.idx, Np);
}

static void run_edge(const float* xin, long xbs, int cin, const float* W, int rowlen,
                     float* outslice, long out_bs, Bufs& P)
{
    run_knn(xin, xbs, cin, NPTS, P);
    gemmW(W,       CF, cin, rowlen, xin, xbs, NPTS, P.bq, (long)CF*NPTS);
    gemmW(W + cin, CF, cin, rowlen, xin, xbs, NPTS, P.bk, (long)CF*NPTS);
    size_t total = (size_t)BB*CF*NPTS;
    edge_pass1_kernel<<<(unsigned)cdiv(total,256), 256>>>(P.bq, P.bk, P.idx, outslice, P.s1, P.s2, NPTS, out_bs);
    bn_stats2_kernel<<<CF, 256>>>(P.s1, P.s2, P.mu, P.rstd, (long)CF*NPTS, NPTS,
                                  1.0/((double)BB*NPTS*KNB));
    bn_apply_kernel<<<(unsigned)cdiv(total,256), 256>>>(outslice, nullptr, outslice, P.mu, P.rstd,
                                                        total, NPTS, CF, out_bs);
}

static void run_n2p(const float* xin, long xbs, int cin, int Np,
                    const float* Wq, const float* Wk, const float* Wv, const float* Wo,
                    const float* Wf1, const float* Wf2, float* outp, Bufs& P)
{
    run_knn(xin, xbs, cin, Np, P);
    long fbs = (long)CF*Np;
    gemmW(Wq, CF, cin, cin, xin, xbs, Np, P.bq, fbs);
    gemmW(Wk, CF, cin, cin, xin, xbs, Np, P.bk, fbs);
    gemmW(Wv, CF, cin, cin, xin, xbs, Np, P.bv, fbs);
    attn_kernel<<<BB*Np, 128>>>(P.bq, P.bk, P.bv, P.idx, P.ba, Np);
    gemmW(Wo, CF, CF, CF, P.ba, fbs, Np, P.by, fbs);
    run_bn(P.by, nullptr, P.by, CF, Np, fbs, P);
    long f1bs = 512L*Np;
    gemmW(Wf1, 512, CF, CF, P.by, fbs, Np, P.f1, f1bs);
    run_bn(P.f1, nullptr, P.f1, 512, Np, f1bs, P);
    gemmW(Wf2, CF, 512, 512, P.f1, f1bs, Np, P.bq, fbs);
    bn_stats_kernel<<<CF, 256>>>(P.bq, P.mu, P.rstd, fbs, Np, 1.0/((double)BB*Np));
    size_t total = (size_t)BB*CF*Np;
    bn_apply_kernel<<<(unsigned)cdiv(total,256), 256>>>(P.bq, P.by, outp, P.mu, P.rstd,
                                                        total, Np, CF, fbs);
}

extern "C" void kernel_launch(void* const* d_in, const int* in_sizes, int n_in,
                              void* d_out, int out_size)
{
    const float* x    = (const float*)d_in[0];
    const float* cat  = (const float*)d_in[1];
    const float* We0  = (const float*)d_in[2];
    const float* We1  = (const float*)d_in[3];
    const float *Wq[3], *Wk[3], *Wv[3], *Wo[3], *Wf1[3], *Wf2[3];
    for (int l = 0; l < 3; l++) {
        Wq[l]  = (const float*)d_in[4 + 6*l];
        Wk[l]  = (const float*)d_in[5 + 6*l];
        Wv[l]  = (const float*)d_in[6 + 6*l];
        Wo[l]  = (const float*)d_in[7 + 6*l];
        Wf1[l] = (const float*)d_in[8 + 6*l];
        Wf2[l] = (const float*)d_in[9 + 6*l];
    }
    const float* Wdq = (const float*)d_in[22];
    const float* Wdk = (const float*)d_in[23];
    const float* Wuq = (const float*)d_in[24];
    const float* Wuk = (const float*)d_in[25];
    const float* Wuv = (const float*)d_in[26];
    const float* Wc  = (const float*)d_in[27];
    const float* Wc1 = (const float*)d_in[28];
    const float* Wc2 = (const float*)d_in[29];
    const float* Wc3 = (const float*)d_in[30];
    const float* Wc4 = (const float*)d_in[31];

    Bufs P; getbufs(P);
    const long HBS = 256L*NPTS;
    const long FBS = (long)CF*NPTS;

    // e0, e1 edge convs into concat buffer g_h
    run_edge(x,   3L*NPTS, 3,   We0, 6,   P.h,               HBS, P);
    run_edge(P.h, HBS,     128, We1, 256, P.h + 128L*NPTS,   HBS, P);

    // h_full = n2p_attn(concat)
    run_n2p(P.h, HBS, 256, NPTS, Wq[0], Wk[0], Wv[0], Wo[0], Wf1[0], Wf2[0], P.hfull, P);

    // down_global: select top-M columns by mean attention score
    gemmW(Wdq, CF, CF, CF, P.hfull, FBS, NPTS, P.bq, FBS);
    gemmW(Wdk, CF, CF, CF, P.hfull, FBS, NPTS, P.bk, FBS);
    gemmTN(P.bq, FBS, NPTS, P.bk, FBS, NPTS, CF, P.big);
    softmax_kernel<<<BB*NPTS, 256>>>(P.big, NPTS, ATTN_SCALE);
    {
        dim3 gs((NPTS+255)/256, BB);
        colmean_kernel<<<gs, 256>>>(P.big, P.score, NPTS, NPTS);
    }
    topm_kernel<<<BB, 1024>>>(P.score, P.sel);
    {
        size_t total = (size_t)BB*CF*MSEL;
        gather_kernel<<<(unsigned)cdiv(total,256), 256>>>(P.hfull, P.sel, P.hd, NPTS, MSEL);
    }

    // hd = n2p_attn(hd) on M=1024 points
    run_n2p(P.hd, (long)CF*MSEL, CF, MSEL, Wq[1], Wk[1], Wv[1], Wo[1], Wf1[1], Wf2[1], P.hd, P);

    // up_cross: hu = h_full + softmax(q k^T / sqrt(C)) v
    gemmW(Wuq, CF, CF, CF, P.hfull, FBS, NPTS, P.bq, FBS);
    gemmW(Wuk, CF, CF, CF, P.hd, (long)CF*MSEL, MSEL, P.bk, (long)CF*MSEL);
    gemmW(Wuv, CF, CF, CF, P.hd, (long)CF*MSEL, MSEL, P.bv, (long)CF*MSEL);
    gemmTN(P.bq, FBS, NPTS, P.bk, (long)CF*MSEL, MSEL, CF, P.big);   // (B,N,M)
    softmax_kernel<<<BB*NPTS, 256>>>(P.big, MSEL, ATTN_SCALE);
    gemm_launch(P.bv, P.big, P.hu, BB, CF, NPTS, MSEL,
                (long)CF*MSEL, MSEL, 1,
                (long)NPTS*MSEL, 1, MSEL,
                FBS, NPTS);
    {
        size_t total = (size_t)BB*CF*NPTS;
        add_kernel<<<(unsigned)cdiv(total,256), 256>>>(P.hfull, P.hu, P.hu, total);
    }

    // x_tmp = n2p_attn(hu)
    run_n2p(P.hu, FBS, CF, NPTS, Wq[2], Wk[2], Wv[2], Wo[2], Wf1[2], Wf2[2], P.xtmp, P);

    // xh = leaky(bn(Wc @ x_tmp))
    gemmW(Wc, 1024, CF, CF, P.xtmp, FBS, NPTS, P.xh, 1024L*NPTS);
    run_bn(P.xh, nullptr, P.xh, 1024, NPTS, 1024L*NPTS, P);

    // g vector: [max | mean | cid]
    maxmean_kernel<<<BB*1024, 256>>>(P.xh, P.gv, NPTS);
    cid_kernel<<<1, 64>>>(cat, Wc1, P.gv);
    bias_kernel<<<1024, 256>>>(Wc2, P.gv, P.bias);

    // xc = leaky(bn(Wc2[:,2112:] @ x_tmp + bias))
    gemmW(Wc2 + 2112, 1024, CF, 2240, P.xtmp, FBS, NPTS, P.xc, 1024L*NPTS);
    {
        size_t total = (size_t)BB*1024*NPTS;
        addbias_kernel<<<(unsigned)cdiv(total,256), 256>>>(P.xc, P.bias);
    }
    run_bn(P.xc, nullptr, P.xc, 1024, NPTS, 1024L*NPTS, P);

    // xc2 = leaky(bn(Wc3 @ xc))
    gemmW(Wc3, 256, 1024, 1024, P.xc, 1024L*NPTS, NPTS, P.xc2, 256L*NPTS);
    run_bn(P.xc2, nullptr, P.xc2, 256, NPTS, 256L*NPTS, P);

    // out = Wc4 @ xc2
    gemmW(Wc4, 50, 256, 256, P.xc2, 256L*NPTS, NPTS, (float*)d_out, 50L*NPTS);

    (void)in_sizes; (void)n_in; (void)out_size;
}

// round 9
// speedup vs baseline: 1.2463x; 1.2463x over previous
#include <cuda_runtime.h>
#include <math.h>

#define BB 8
#define NPTS 2048
#define KNB 32
#define MSEL 1024
#define CF 128
#define LRELU 0.2f
#define ATTN_SCALE 0.088388347648318447f

// ---------------- static device scratch ----------------
static __device__ float g_big[(size_t)BB*NPTS*NPTS];
static __device__ float g_h[(size_t)BB*256*NPTS];
static __device__ float g_hfull[(size_t)BB*CF*NPTS];
static __device__ float g_bq[(size_t)BB*CF*NPTS];
static __device__ float g_bk[(size_t)BB*CF*NPTS];
static __device__ float g_bv[(size_t)BB*CF*NPTS];
static __device__ float g_ba[(size_t)BB*CF*NPTS];
static __device__ float g_by[(size_t)BB*CF*NPTS];
static __device__ float g_f1[(size_t)BB*512*NPTS];
static __device__ float g_s1[(size_t)BB*CF*NPTS];
static __device__ float g_s2[(size_t)BB*CF*NPTS];
static __device__ float g_hd[(size_t)BB*CF*MSEL];
static __device__ float g_hu[(size_t)BB*CF*NPTS];
static __device__ float g_xtmp[(size_t)BB*CF*NPTS];
static __device__ float g_xh[(size_t)BB*1024*NPTS];
static __device__ float g_xc[(size_t)BB*1024*NPTS];
static __device__ float g_xc2[(size_t)BB*256*NPTS];
static __device__ float g_sqn[(size_t)BB*NPTS];
static __device__ float g_score[(size_t)BB*NPTS];
static __device__ float g_gv[(size_t)BB*2112];
static __device__ float g_bias[(size_t)BB*1024];
static __device__ float g_mu[1024];
static __device__ float g_rstd[1024];
static __device__ int   g_idx[(size_t)BB*NPTS*KNB];
static __device__ int   g_sel[(size_t)BB*MSEL];

// ---------------- generic strided batched GEMMs ----------------
// O[bz*o_b + i*o_i + j] = sum_k A[..] * B[..]; single accumulator, ascending k
// => bitwise identical across tile sizes.

// 128x128 tile, 8x8 microtile (for large grids)
__global__ void __launch_bounds__(256)
gemm_kernel128(const float* __restrict__ A, const float* __restrict__ Bm,
               float* __restrict__ O, int I, int J, int Kd,
               long a_b, long a_i, long a_k,
               long b_b, long b_k, long b_j,
               long o_b, long o_i)
{
    __shared__ float As[8][132];
    __shared__ float Bs[8][132];
    int bz = blockIdx.z;
    const float* Ab = A + (long)bz*a_b;
    const float* Bb = Bm + (long)bz*b_b;
    int i0 = blockIdx.y*128, j0 = blockIdx.x*128;
    int tid = threadIdx.x;
    int tx = tid & 15, ty = tid >> 4;
    float acc[8][8] = {};
    for (int k0 = 0; k0 < Kd; k0 += 8) {
        #pragma unroll
        for (int r = 0; r < 4; r++) {
            int e = tid*4 + r;
            int ii, kk;
            if (a_k == 1) { ii = e >> 3; kk = e & 7; }
            else          { kk = e >> 7; ii = e & 127; }
            float v = 0.f;
            if (i0+ii < I && k0+kk < Kd) v = Ab[(long)(i0+ii)*a_i + (long)(k0+kk)*a_k];
            As[kk][ii] = v;
        }
        #pragma unroll
        for (int r = 0; r < 4; r++) {
            int e = tid*4 + r;
            int jj, kk;
            if (b_j == 1) { jj = e & 127; kk = e >> 7; }
            else          { jj = e >> 3;  kk = e & 7; }
            float v = 0.f;
            if (j0+jj < J && k0+kk < Kd) v = Bb[(long)(k0+kk)*b_k + (long)(j0+jj)*b_j];
            Bs[kk][jj] = v;
        }
        __syncthreads();
        #pragma unroll
        for (int kk = 0; kk < 8; kk++) {
            float4 a0 = *(const float4*)&As[kk][ty*8];
            float4 a1 = *(const float4*)&As[kk][ty*8+4];
            float4 b0 = *(const float4*)&Bs[kk][tx*8];
            float4 b1 = *(const float4*)&Bs[kk][tx*8+4];
            float av[8] = {a0.x,a0.y,a0.z,a0.w,a1.x,a1.y,a1.z,a1.w};
            float bw[8] = {b0.x,b0.y,b0.z,b0.w,b1.x,b1.y,b1.z,b1.w};
            #pragma unroll
            for (int u = 0; u < 8; u++)
                #pragma unroll
                for (int v = 0; v < 8; v++) acc[u][v] += av[u]*bw[v];
        }
        __syncthreads();
    }
    #pragma unroll
    for (int u = 0; u < 8; u++) {
        int i = i0 + ty*8 + u;
        if (i >= I) continue;
        #pragma unroll
        for (int v = 0; v < 8; v++) {
            int j = j0 + tx*8 + v;
            if (j < J) O[(long)bz*o_b + (long)i*o_i + j] = acc[u][v];
        }
    }
}

// 64x64 tile, 4x4 microtile (for small grids)
__global__ void __launch_bounds__(256)
gemm_kernel64(const float* __restrict__ A, const float* __restrict__ Bm,
              float* __restrict__ O, int I, int J, int Kd,
              long a_b, long a_i, long a_k,
              long b_b, long b_k, long b_j,
              long o_b, long o_i)
{
    __shared__ float As[16*65];
    __shared__ float Bs[16*65];
    int bz = blockIdx.z;
    const float* Ab = A + (long)bz*a_b;
    const float* Bb = Bm + (long)bz*b_b;
    int i0 = blockIdx.y*64, j0 = blockIdx.x*64;
    int tid = threadIdx.x;
    int tx = tid & 15, ty = tid >> 4;
    float acc[4][4] = {};
    for (int k0 = 0; k0 < Kd; k0 += 16) {
        #pragma unroll
        for (int r = 0; r < 4; r++) {
            int e = tid + r*256;
            int kk, ii;
            if (a_k == 1) { ii = e >> 4; kk = e & 15; } else { kk = e >> 6; ii = e & 63; }
            float v = 0.f;
            if (i0+ii < I && k0+kk < Kd) v = Ab[(long)(i0+ii)*a_i + (long)(k0+kk)*a_k];
            As[kk*65+ii] = v;
        }
        #pragma unroll
        for (int r = 0; r < 4; r++) {
            int e = tid + r*256;
            int kk, jj;
            if (b_j == 1) { kk = e >> 6; jj = e & 63; } else { jj = e >> 4; kk = e & 15; }
            float v = 0.f;
            if (j0+jj < J && k0+kk < Kd) v = Bb[(long)(k0+kk)*b_k + (long)(j0+jj)*b_j];
            Bs[kk*65+jj] = v;
        }
        __syncthreads();
        #pragma unroll
        for (int kk = 0; kk < 16; kk++) {
            float av[4], bv[4];
            #pragma unroll
            for (int u = 0; u < 4; u++) av[u] = As[kk*65 + ty*4 + u];
            #pragma unroll
            for (int v = 0; v < 4; v++) bv[v] = Bs[kk*65 + tx*4 + v];
            #pragma unroll
            for (int u = 0; u < 4; u++)
                #pragma unroll
                for (int v = 0; v < 4; v++) acc[u][v] += av[u]*bv[v];
        }
        __syncthreads();
    }
    #pragma unroll
    for (int u = 0; u < 4; u++) {
        int i = i0 + ty*4 + u;
        if (i >= I) continue;
        #pragma unroll
        for (int v = 0; v < 4; v++) {
            int j = j0 + tx*4 + v;
            if (j < J) O[(long)bz*o_b + (long)i*o_i + j] = acc[u][v];
        }
    }
}

static void gemm_launch(const float* A, const float* B, float* O,
                        int Bn, int I, int J, int Kd,
                        long a_b, long a_i, long a_k,
                        long b_b, long b_k, long b_j,
                        long o_b, long o_i)
{
    long ctas128 = (long)((J+127)/128)*((I+127)/128)*Bn;
    if (ctas128 >= 256) {
        dim3 grid((J+127)/128, (I+127)/128, Bn);
        gemm_kernel128<<<grid, 256>>>(A,B,O,I,J,Kd,a_b,a_i,a_k,b_b,b_k,b_j,o_b,o_i);
    } else {
        dim3 grid((J+63)/64, (I+63)/64, Bn);
        gemm_kernel64<<<grid, 256>>>(A,B,O,I,J,Kd,a_b,a_i,a_k,b_b,b_k,b_j,o_b,o_i);
    }
}
// c-major output: O[b, o, n]
static void gemmW(const float* W, int Oc, int Kd, int rowlen,
                  const float* X, long xbs, int Np, float* O, long obs)
{
    gemm_launch(W, X, O, BB, Oc, Np, Kd, 0, rowlen, 1, xbs, Np, 1, obs, Np);
}
// n-major output: O[b, n, o] (same dot-product order per element -> bitwise same values)
static void gemmWn(const float* W, int Oc, int Kd, int rowlen,
                   const float* X, long xbs, int Np, float* O)
{
    gemm_launch(X, W, O, BB, Np, Oc, Kd, xbs, 1, Np, 0, 1, rowlen, (long)Oc*Np, Oc);
}
static void gemmTN(const float* X, long xbs, int Np,
                   const float* Y, long ybs, int Mp, int Cin, float* S)
{
    gemm_launch(X, Y, S, BB, Np, Mp, Cin, xbs, 1, Np, ybs, Mp, 1, (long)Np*Mp, Mp);
}

// ---------------- helper kernels ----------------
__global__ void sqnorm_kernel(const float* __restrict__ x, float* __restrict__ sq,
                              int Cin, int Np, long bstride)
{
    int b = blockIdx.y;
    int n = blockIdx.x*256 + threadIdx.x;
    if (n >= Np) return;
    const float* p = x + (long)b*bstride + n;
    float s = 0.f;
    for (int c = 0; c < Cin; c++) { float v = p[(long)c*Np]; s += v*v; }
    sq[(long)b*Np + n] = s;
}

__global__ void knn_topk_kernel(const float* __restrict__ inner, const float* __restrict__ sq,
                                int* __restrict__ idxout, int Np)
{
    __shared__ float sv[8][32];
    __shared__ int   si[8][32];
    int row = blockIdx.x;
    int b = row / Np, n = row % Np;
    int t = threadIdx.x, w = t >> 5, lane = t & 31;
    int chunk = Np >> 3;
    int per = chunk >> 5;
    const float* ir = inner + ((size_t)b*Np + n)*Np;
    const float* sqb = sq + (size_t)b*Np;
    float sn = sqb[n];
    int base = w*chunk;
    float dv[8];
    #pragma unroll
    for (int j = 0; j < 8; j++) {
        if (j < per) {
            int m = base + j*32 + lane;
            dv[j] = sn - 2.0f*ir[m] + sqb[m];
        } else dv[j] = 3.4e38f;
    }
    for (int k = 0; k < KNB; k++) {
        float bv = 3.4e38f; int bj = 0;
        #pragma unroll
        for (int j = 0; j < 8; j++) if (dv[j] < bv) { bv = dv[j]; bj = j; }
        int bi = base + bj*32 + lane;
        #pragma unroll
        for (int o = 16; o; o >>= 1) {
            float ov = __shfl_xor_sync(0xffffffffu, bv, o);
            int   oi = __shfl_xor_sync(0xffffffffu, bi, o);
            if (ov < bv || (ov == bv && oi < bi)) { bv = ov; bi = oi; }
        }
        if ((bi & 31) == lane) dv[(bi - base) >> 5] = 3.4e38f;
        if (lane == 0) { sv[w][k] = bv; si[w][k] = bi; }
    }
    __syncthreads();
    if (w == 0) {
        float cv[8]; int ci[8];
        #pragma unroll
        for (int j = 0; j < 8; j++) {
            int c = lane*8 + j;
            cv[j] = sv[c >> 5][c & 31];
            ci[j] = si[c >> 5][c & 31];
        }
        int* op = idxout + (size_t)row*KNB;
        for (int k = 0; k < KNB; k++) {
            float bv = 3.4e38f; int bi = 0x7fffffff; int bj = -1;
            #pragma unroll
            for (int j = 0; j < 8; j++) {
                if (cv[j] < bv || (cv[j] == bv && ci[j] < bi)) { bv = cv[j]; bi = ci[j]; bj = j; }
            }
            float rbv = bv; int rbi = bi;
            #pragma unroll
            for (int o = 16; o; o >>= 1) {
                float ov = __shfl_xor_sync(0xffffffffu, rbv, o);
                int   oi = __shfl_xor_sync(0xffffffffu, rbi, o);
                if (ov < rbv || (ov == rbv && oi < rbi)) { rbv = ov; rbi = oi; }
            }
            if (bj >= 0 && rbi == bi) cv[bj] = 3.4e38f;
            if (lane == 0) op[k] = rbi;
        }
    }
}

// n-major inputs (An, Bn_ are [b, n, c]); c-major outputs at identical addresses
// and identical per-(b,o,n) op order as before -> bitwise same.
__global__ void edge_pass1_kernel(const float* __restrict__ An, const float* __restrict__ Bn_,
                                  const int* __restrict__ idx, float* __restrict__ pre,
                                  float* __restrict__ s1, float* __restrict__ s2,
                                  int Np, long pre_bs)
{
    int bn = blockIdx.x;
    int b = bn / Np, n = bn % Np;
    int t = threadIdx.x;   // channel
    size_t nb = (size_t)b*CF*Np;
    __shared__ int sidx[KNB];
    if (t < KNB) sidx[t] = idx[(size_t)bn*KNB + t];
    __syncthreads();
    float a  = An [nb + (size_t)n*CF + t];
    float bm = Bn_[nb + (size_t)n*CF + t];
    float diff = a - bm;
    const float* Br = Bn_ + nb;
    float s = 0.f, ss = 0.f, mx = -3.4e38f;
    #pragma unroll 4
    for (int k = 0; k < KNB; k++) {
        float v = diff + Br[(size_t)sidx[k]*CF + t];
        s += v; ss += v*v; mx = fmaxf(mx, v);
    }
    pre[(size_t)b*pre_bs + (size_t)t*Np + n] = mx;
    size_t ci = nb + (size_t)t*Np + n;
    s1[ci] = s; s2[ci] = ss;
}

__global__ void bn_stats_kernel(const float* __restrict__ x, float* __restrict__ mu,
                                float* __restrict__ rstd, long bstride, int Np, double invcount)
{
    int o = blockIdx.x, t = threadIdx.x;
    double s = 0.0, ss = 0.0;
    for (int b = 0; b < BB; b++) {
        const float* p = x + (long)b*bstride + (long)o*Np;
        for (int n = t; n < Np; n += 256) { double v = p[n]; s += v; ss += v*v; }
    }
    __shared__ double sh1[256], sh2[256];
    sh1[t] = s; sh2[t] = ss; __syncthreads();
    for (int st = 128; st; st >>= 1) {
        if (t < st) { sh1[t] += sh1[t+st]; sh2[t] += sh2[t+st]; }
        __syncthreads();
    }
    if (!t) {
        double m = sh1[0]*invcount;
        double var = sh2[0]*invcount - m*m;
        mu[o] = (float)m;
        rstd[o] = (float)(1.0/sqrt(var + 1e-5));
    }
}

__global__ void bn_stats2_kernel(const float* __restrict__ s1, const float* __restrict__ s2,
                                 float* __restrict__ mu, float* __restrict__ rstd,
                                 long bstride, int Np, double invcount)
{
    int o = blockIdx.x, t = threadIdx.x;
    double s = 0.0, ss = 0.0;
    for (int b = 0; b < BB; b++) {
        const float* p1 = s1 + (long)b*bstride + (long)o*Np;
        const float* p2 = s2 + (long)b*bstride + (long)o*Np;
        for (int n = t; n < Np; n += 256) { s += (double)p1[n]; ss += (double)p2[n]; }
    }
    __shared__ double sh1[256], sh2[256];
    sh1[t] = s; sh2[t] = ss; __syncthreads();
    for (int st = 128; st; st >>= 1) {
        if (t < st) { sh1[t] += sh1[t+st]; sh2[t] += sh2[t+st]; }
        __syncthreads();
    }
    if (!t) {
        double m = sh1[0]*invcount;
        double var = sh2[0]*invcount - m*m;
        mu[o] = (float)m;
        rstd[o] = (float)(1.0/sqrt(var + 1e-5));
    }
}

__global__ void bn_apply_kernel(const float* __restrict__ x, const float* __restrict__ res,
                                float* __restrict__ out, const float* __restrict__ mu,
                                const float* __restrict__ rstd, size_t total,
                                int Np, int Cch, long bstride)
{
    size_t i = (size_t)blockIdx.x*256 + threadIdx.x;
    if (i >= total) return;
    int n = (int)(i % Np); size_t tt = i / Np;
    int o = (int)(tt % Cch); int b = (int)(tt / Cch);
    size_t off = (size_t)b*bstride + (size_t)o*Np + n;
    float v = (x[off] - mu[o]) * rstd[o];
    v = v >= 0.f ? v : LRELU*v;
    out[off] = (res ? res[off] : 0.f) + v;
}

// q/K/V n-major ([b, n, c]); identical reduction structure as previous rounds
// (thread=channel, 4-warp shuffle tree, left-assoc part sum, ascending-k V acc).
__global__ void attn_kernel(const float* __restrict__ qn, const float* __restrict__ Kn,
                            const float* __restrict__ Vn, const int* __restrict__ idx,
                            float* __restrict__ out, int Np)
{
    int bn = blockIdx.x;
    int b = bn / Np, n = bn % Np;
    int t = threadIdx.x, w = t >> 5, lane = t & 31;
    size_t nb = (size_t)b*CF*Np;
    __shared__ int   sidx[KNB];
    __shared__ float part[4][KNB];
    __shared__ float aw[KNB];
    if (t < KNB) sidx[t] = idx[(size_t)bn*KNB + t];
    __syncthreads();
    float qc = qn[nb + (size_t)n*CF + t];
    const float* Kb = Kn + nb;
    for (int k = 0; k < KNB; k++) {
        float v = qc * Kb[(size_t)sidx[k]*CF + t];
        #pragma unroll
        for (int o = 16; o; o >>= 1) v += __shfl_down_sync(0xffffffffu, v, o);
        if (lane == 0) part[w][k] = v;
    }
    __syncthreads();
    if (w == 0) {
        float l = (part[0][lane] + part[1][lane] + part[2][lane] + part[3][lane]) * ATTN_SCALE;
        float m = l;
        #pragma unroll
        for (int o = 16; o; o >>= 1) m = fmaxf(m, __shfl_xor_sync(0xffffffffu, m, o));
        float e = expf(l - m);
        float s = e;
        #pragma unroll
        for (int o = 16; o; o >>= 1) s += __shfl_xor_sync(0xffffffffu, s, o);
        aw[lane] = e / s;
    }
    __syncthreads();
    const float* Vb = Vn + nb;
    float acc = 0.f;
    for (int k = 0; k < KNB; k++) acc += aw[k]*Vb[(size_t)sidx[k]*CF + t];
    out[nb + (size_t)t*Np + n] = acc;   // c-major output, same address as before
}

__global__ void softmax_kernel(float* __restrict__ S, int M, float scale)
{
    __shared__ float sh[NPTS];
    __shared__ float red[256];
    size_t row = blockIdx.x;
    float* r = S + row*(size_t)M;
    int t = threadIdx.x;
    float mx = -3.4e38f;
    for (int i = t; i < M; i += 256) { float v = r[i]*scale; sh[i] = v; mx = fmaxf(mx, v); }
    red[t] = mx; __syncthreads();
    for (int s = 128; s; s >>= 1) { if (t < s) red[t] = fmaxf(red[t], red[t+s]); __syncthreads(); }
    mx = red[0]; __syncthreads();
    float sum = 0.f;
    for (int i = t; i < M; i += 256) { float e = expf(sh[i] - mx); sh[i] = e; sum += e; }
    red[t] = sum; __syncthreads();
    for (int s = 128; s; s >>= 1) { if (t < s) red[t] += red[t+s]; __syncthreads(); }
    float inv = 1.0f/red[0];
    for (int i = t; i < M; i += 256) r[i] = sh[i]*inv;
}

__global__ void colmean_kernel(const float* __restrict__ S, float* __restrict__ score, int R, int M)
{
    int b = blockIdx.y;
    int m = blockIdx.x*256 + threadIdx.x;
    if (m >= M) return;
    const float* p = S + (size_t)b*R*M + m;
    float s = 0.f;
    for (int n = 0; n < R; n++) s += p[(size_t)n*M];
    score[(size_t)b*M + m] = s / (float)R;
}

__global__ void topm_kernel(const float* __restrict__ score, int* __restrict__ sel)
{
    __shared__ float v[NPTS];
    __shared__ int   id[NPTS];
    int b = blockIdx.x, t = threadIdx.x;
    for (int i = t; i < NPTS; i += 1024) { v[i] = score[(size_t)b*NPTS + i]; id[i] = i; }
    __syncthreads();
    for (int k = 2; k <= NPTS; k <<= 1) {
        for (int j = k >> 1; j > 0; j >>= 1) {
            for (int i = t; i < NPTS; i += 1024) {
                int p = i ^ j;
                if (p > i) {
                    bool up = ((i & k) == 0);
                    float vi = v[i], vp = v[p]; int ii = id[i], ip = id[p];
                    bool inOrder = (vi > vp) || (vi == vp && ii < ip);
                    if (up ? !inOrder : inOrder) { v[i]=vp; v[p]=vi; id[i]=ip; id[p]=ii; }
                }
            }
            __syncthreads();
        }
    }
    for (int i = t; i < MSEL; i += 1024) sel[(size_t)b*MSEL + i] = id[i];
}

__global__ void gather_kernel(const float* __restrict__ x, const int* __restrict__ sel,
                              float* __restrict__ out, int Np, int Ms)
{
    size_t i = (size_t)blockIdx.x*256 + threadIdx.x;
    if (i >= (size_t)BB*CF*Ms) return;
    int j = (int)(i % Ms); size_t tt = i / Ms;
    int c = (int)(tt % CF); int b = (int)(tt / CF);
    out[i] = x[((size_t)b*CF + c)*Np + sel[(size_t)b*Ms + j]];
}

__global__ void add_kernel(const float* __restrict__ a, const float* __restrict__ b,
                           float* __restrict__ o, size_t total)
{
    size_t i = (size_t)blockIdx.x*256 + threadIdx.x;
    if (i < total) o[i] = a[i] + b[i];
}

__global__ void maxmean_kernel(const float* __restrict__ xh, float* __restrict__ g, int Np)
{
    __shared__ float rm[256], rs[256];
    int bo = blockIdx.x;
    int b = bo >> 10, o = bo & 1023;
    const float* p = xh + ((size_t)b*1024 + o)*Np;
    int t = threadIdx.x;
    float mx = -3.4e38f, s = 0.f;
    for (int n = t; n < Np; n += 256) { float v = p[n]; mx = fmaxf(mx, v); s += v; }
    rm[t] = mx; rs[t] = s; __syncthreads();
    for (int st = 128; st; st >>= 1) {
        if (t < st) { rm[t] = fmaxf(rm[t], rm[t+st]); rs[t] += rs[t+st]; }
        __syncthreads();
    }
    if (!t) { g[(size_t)b*2112 + o] = rm[0]; g[(size_t)b*2112 + 1024 + o] = rs[0]/(float)Np; }
}

__global__ void cid_kernel(const float* __restrict__ cat, const float* __restrict__ Wc1,
                           float* __restrict__ g)
{
    int o = threadIdx.x;
    float y[BB];
    for (int b = 0; b < BB; b++) {
        float s = 0.f;
        for (int c = 0; c < 16; c++) s += Wc1[o*16+c]*cat[b*16+c];
        y[b] = s;
    }
    float mu = 0.f;
    for (int b = 0; b < BB; b++) mu += y[b];
    mu *= (1.0f/BB);
    float var = 0.f;
    for (int b = 0; b < BB; b++) { float dd = y[b]-mu; var += dd*dd; }
    var *= (1.0f/BB);
    float rs = rsqrtf(var + 1e-5f);
    for (int b = 0; b < BB; b++) {
        float v = (y[b]-mu)*rs;
        g[(size_t)b*2112 + 2048 + o] = v >= 0.f ? v : LRELU*v;
    }
}

__global__ void bias_kernel(const float* __restrict__ W, const float* __restrict__ g,
                            float* __restrict__ bias)
{
    int gw = blockIdx.x*8 + (threadIdx.x >> 5);
    if (gw >= BB*1024) return;
    int lane = threadIdx.x & 31;
    int b = gw >> 10, o = gw & 1023;
    const float* wr = W + (size_t)o*2240;
    const float* gb = g + (size_t)b*2112;
    float s = 0.f;
    for (int c = lane; c < 2112; c += 32) s += wr[c]*gb[c];
    #pragma unroll
    for (int off = 16; off; off >>= 1) s += __shfl_down_sync(0xffffffffu, s, off);
    if (!lane) bias[(size_t)b*1024 + o] = s;
}

__global__ void addbias_kernel(float* __restrict__ xc, const float* __restrict__ bias)
{
    size_t i = (size_t)blockIdx.x*256 + threadIdx.x;
    if (i >= (size_t)BB*1024*NPTS) return;
    size_t tt = i / NPTS;
    int o = (int)(tt % 1024); int b = (int)(tt / 1024);
    xc[i] += bias[(size_t)b*1024 + o];
}

// ---------------- host orchestration ----------------
struct Bufs {
    float *big,*h,*hfull,*bq,*bk,*bv,*ba,*by,*f1,*s1,*s2,*hd,*hu,*xtmp,*xh,*xc,*xc2;
    float *sq,*score,*gv,*bias,*mu,*rstd;
    int *idx,*sel;
};

static void getbufs(Bufs& P)
{
    cudaGetSymbolAddress((void**)&P.big, g_big);
    cudaGetSymbolAddress((void**)&P.h, g_h);
    cudaGetSymbolAddress((void**)&P.hfull, g_hfull);
    cudaGetSymbolAddress((void**)&P.bq, g_bq);
    cudaGetSymbolAddress((void**)&P.bk, g_bk);
    cudaGetSymbolAddress((void**)&P.bv, g_bv);
    cudaGetSymbolAddress((void**)&P.ba, g_ba);
    cudaGetSymbolAddress((void**)&P.by, g_by);
    cudaGetSymbolAddress((void**)&P.f1, g_f1);
    cudaGetSymbolAddress((void**)&P.s1, g_s1);
    cudaGetSymbolAddress((void**)&P.s2, g_s2);
    cudaGetSymbolAddress((void**)&P.hd, g_hd);
    cudaGetSymbolAddress((void**)&P.hu, g_hu);
    cudaGetSymbolAddress((void**)&P.xtmp, g_xtmp);
    cudaGetSymbolAddress((void**)&P.xh, g_xh);
    cudaGetSymbolAddress((void**)&P.xc, g_xc);
    cudaGetSymbolAddress((void**)&P.xc2, g_xc2);
    cudaGetSymbolAddress((void**)&P.sq, g_sqn);
    cudaGetSymbolAddress((void**)&P.score, g_score);
    cudaGetSymbolAddress((void**)&P.gv, g_gv);
    cudaGetSymbolAddress((void**)&P.bias, g_bias);
    cudaGetSymbolAddress((void**)&P.mu, g_mu);
    cudaGetSymbolAddress((void**)&P.rstd, g_rstd);
    cudaGetSymbolAddress((void**)&P.idx, g_idx);
    cudaGetSymbolAddress((void**)&P.sel, g_sel);
}

static inline size_t cdiv(size_t a, size_t b) { return (a + b - 1)/b; }

static void run_bn(float* x, const float* res, float* out, int Cch, int Np, long bstride, Bufs& P)
{
    bn_stats_kernel<<<Cch, 256>>>(x, P.mu, P.rstd, bstride, Np, 1.0/((double)BB*Np));
    size_t total = (size_t)BB*Cch*Np;
    bn_apply_kernel<<<(unsigned)cdiv(total,256), 256>>>(x, res, out, P.mu, P.rstd, total, Np, Cch, bstride);
}

static void run_knn(const float* xin, long xbs, int cin, int Np, Bufs& P)
{
    dim3 gs((Np+255)/256, BB);
    sqnorm_kernel<<<gs, 256>>>(xin, P.sq, cin, Np, xbs);
    gemmTN(xin, xbs, Np, xin, xbs, Np, cin, P.big);
    knn_topk_kernel<<<BB*Np, 256>>>(P.big, P.sq, P.idx, Np);
}

static void run_edge(const float* xin, long xbs, int cin, const float* W, int rowlen,
                     float* outslice, long out_bs, Bufs& P)
{
    run_knn(xin, xbs, cin, NPTS, P);
    // n-major W1@x and W2@x for coalesced neighbor gathers
    gemmWn(W,       CF, cin, rowlen, xin, xbs, NPTS, P.bq);
    gemmWn(W + cin, CF, cin, rowlen, xin, xbs, NPTS, P.bk);
    edge_pass1_kernel<<<BB*NPTS, 128>>>(P.bq, P.bk, P.idx, outslice, P.s1, P.s2, NPTS, out_bs);
    size_t total = (size_t)BB*CF*NPTS;
    bn_stats2_kernel<<<CF, 256>>>(P.s1, P.s2, P.mu, P.rstd, (long)CF*NPTS, NPTS,
                                  1.0/((double)BB*NPTS*KNB));
    bn_apply_kernel<<<(unsigned)cdiv(total,256), 256>>>(outslice, nullptr, outslice, P.mu, P.rstd,
                                                        total, NPTS, CF, out_bs);
}

static void run_n2p(const float* xin, long xbs, int cin, int Np,
                    const float* Wq, const float* Wk, const float* Wv, const float* Wo,
                    const float* Wf1, const float* Wf2, float* outp, Bufs& P)
{
    run_knn(xin, xbs, cin, Np, P);
    long fbs = (long)CF*Np;
    // n-major q/k/v for coalesced attention
    gemmWn(Wq, CF, cin, cin, xin, xbs, Np, P.bq);
    gemmWn(Wk, CF, cin, cin, xin, xbs, Np, P.bk);
    gemmWn(Wv, CF, cin, cin, xin, xbs, Np, P.bv);
    attn_kernel<<<BB*Np, 128>>>(P.bq, P.bk, P.bv, P.idx, P.ba, Np);
    gemmW(Wo, CF, CF, CF, P.ba, fbs, Np, P.by, fbs);
    run_bn(P.by, nullptr, P.by, CF, Np, fbs, P);
    long f1bs = 512L*Np;
    gemmW(Wf1, 512, CF, CF, P.by, fbs, Np, P.f1, f1bs);
    run_bn(P.f1, nullptr, P.f1, 512, Np, f1bs, P);
    gemmW(Wf2, CF, 512, 512, P.f1, f1bs, Np, P.bq, fbs);
    bn_stats_kernel<<<CF, 256>>>(P.bq, P.mu, P.rstd, fbs, Np, 1.0/((double)BB*Np));
    size_t total = (size_t)BB*CF*Np;
    bn_apply_kernel<<<(unsigned)cdiv(total,256), 256>>>(P.bq, P.by, outp, P.mu, P.rstd,
                                                        total, Np, CF, fbs);
}

extern "C" void kernel_launch(void* const* d_in, const int* in_sizes, int n_in,
                              void* d_out, int out_size)
{
    const float* x    = (const float*)d_in[0];
    const float* cat  = (const float*)d_in[1];
    const float* We0  = (const float*)d_in[2];
    const float* We1  = (const float*)d_in[3];
    const float *Wq[3], *Wk[3], *Wv[3], *Wo[3], *Wf1[3], *Wf2[3];
    for (int l = 0; l < 3; l++) {
        Wq[l]  = (const float*)d_in[4 + 6*l];
        Wk[l]  = (const float*)d_in[5 + 6*l];
        Wv[l]  = (const float*)d_in[6 + 6*l];
        Wo[l]  = (const float*)d_in[7 + 6*l];
        Wf1[l] = (const float*)d_in[8 + 6*l];
        Wf2[l] = (const float*)d_in[9 + 6*l];
    }
    const float* Wdq = (const float*)d_in[22];
    const float* Wdk = (const float*)d_in[23];
    const float* Wuq = (const float*)d_in[24];
    const float* Wuk = (const float*)d_in[25];
    const float* Wuv = (const float*)d_in[26];
    const float* Wc  = (const float*)d_in[27];
    const float* Wc1 = (const float*)d_in[28];
    const float* Wc2 = (const float*)d_in[29];
    const float* Wc3 = (const float*)d_in[30];
    const float* Wc4 = (const float*)d_in[31];

    Bufs P; getbufs(P);
    const long HBS = 256L*NPTS;
    const long FBS = (long)CF*NPTS;

    run_edge(x,   3L*NPTS, 3,   We0, 6,   P.h,             HBS, P);
    run_edge(P.h, HBS,     128, We1, 256, P.h + 128L*NPTS, HBS, P);

    run_n2p(P.h, HBS, 256, NPTS, Wq[0], Wk[0], Wv[0], Wo[0], Wf1[0], Wf2[0], P.hfull, P);

    // down_global
    gemmW(Wdq, CF, CF, CF, P.hfull, FBS, NPTS, P.bq, FBS);
    gemmW(Wdk, CF, CF, CF, P.hfull, FBS, NPTS, P.bk, FBS);
    gemmTN(P.bq, FBS, NPTS, P.bk, FBS, NPTS, CF, P.big);
    softmax_kernel<<<BB*NPTS, 256>>>(P.big, NPTS, ATTN_SCALE);
    {
        dim3 gs((NPTS+255)/256, BB);
        colmean_kernel<<<gs, 256>>>(P.big, P.score, NPTS, NPTS);
    }
    topm_kernel<<<BB, 1024>>>(P.score, P.sel);
    {
        size_t total = (size_t)BB*CF*MSEL;
        gather_kernel<<<(unsigned)cdiv(total,256), 256>>>(P.hfull, P.sel, P.hd, NPTS, MSEL);
    }

    run_n2p(P.hd, (long)CF*MSEL, CF, MSEL, Wq[1], Wk[1], Wv[1], Wo[1], Wf1[1], Wf2[1], P.hd, P);

    // up_cross
    gemmW(Wuq, CF, CF, CF, P.hfull, FBS, NPTS, P.bq, FBS);
    gemmW(Wuk, CF, CF, CF, P.hd, (long)CF*MSEL, MSEL, P.bk, (long)CF*MSEL);
    gemmW(Wuv, CF, CF, CF, P.hd, (long)CF*MSEL, MSEL, P.bv, (long)CF*MSEL);
    gemmTN(P.bq, FBS, NPTS, P.bk, (long)CF*MSEL, MSEL, CF, P.big);
    softmax_kernel<<<BB*NPTS, 256>>>(P.big, MSEL, ATTN_SCALE);
    gemm_launch(P.bv, P.big, P.hu, BB, CF, NPTS, MSEL,
                (long)CF*MSEL, MSEL, 1,
                (long)NPTS*MSEL, 1, MSEL,
                FBS, NPTS);
    {
        size_t total = (size_t)BB*CF*NPTS;
        add_kernel<<<(unsigned)cdiv(total,256), 256>>>(P.hfull, P.hu, P.hu, total);
    }

    run_n2p(P.hu, FBS, CF, NPTS, Wq[2], Wk[2], Wv[2], Wo[2], Wf1[2], Wf2[2], P.xtmp, P);

    gemmW(Wc, 1024, CF, CF, P.xtmp, FBS, NPTS, P.xh, 1024L*NPTS);
    run_bn(P.xh, nullptr, P.xh, 1024, NPTS, 1024L*NPTS, P);

    maxmean_kernel<<<BB*1024, 256>>>(P.xh, P.gv, NPTS);
    cid_kernel<<<1, 64>>>(cat, Wc1, P.gv);
    bias_kernel<<<1024, 256>>>(Wc2, P.gv, P.bias);

    gemmW(Wc2 + 2112, 1024, CF, 2240, P.xtmp, FBS, NPTS, P.xc, 1024L*NPTS);
    {
        size_t total = (size_t)BB*1024*NPTS;
        addbias_kernel<<<(unsigned)cdiv(total,256), 256>>>(P.xc, P.bias);
    }
    run_bn(P.xc, nullptr, P.xc, 1024, NPTS, 1024L*NPTS, P);

    gemmW(Wc3, 256, 1024, 1024, P.xc, 1024L*NPTS, NPTS, P.xc2, 256L*NPTS);
    run_bn(P.xc2, nullptr, P.xc2, 256, NPTS, 256L*NPTS, P);

    gemmW(Wc4, 50, 256, 256, P.xc2, 256L*NPTS, NPTS, (float*)d_out, 50L*NPTS);

    (void)in_sizes; (void)n_in; (void)out_size;
}

// round 11
// speedup vs baseline: 1.3197x; 1.0589x over previous
#include <cuda_runtime.h>
#include <math.h>

#define BB 8
#define NPTS 2048
#define KNB 32
#define MSEL 1024
#define CF 128
#define LRELU 0.2f
#define ATTN_SCALE 0.088388347648318447f

// ---------------- static device scratch ----------------
static __device__ float g_big[(size_t)BB*NPTS*NPTS];
static __device__ float g_h[(size_t)BB*256*NPTS];
static __device__ float g_hfull[(size_t)BB*CF*NPTS];
static __device__ float g_bq[(size_t)BB*CF*NPTS];
static __device__ float g_bk[(size_t)BB*CF*NPTS];
static __device__ float g_bv[(size_t)BB*CF*NPTS];
static __device__ float g_ba[(size_t)BB*CF*NPTS];
static __device__ float g_by[(size_t)BB*CF*NPTS];
static __device__ float g_f1[(size_t)BB*512*NPTS];
static __device__ float g_s1[(size_t)BB*CF*NPTS];
static __device__ float g_s2[(size_t)BB*CF*NPTS];
static __device__ float g_hd[(size_t)BB*CF*MSEL];
static __device__ float g_hu[(size_t)BB*CF*NPTS];
static __device__ float g_xtmp[(size_t)BB*CF*NPTS];
static __device__ float g_xh[(size_t)BB*1024*NPTS];
static __device__ float g_xc[(size_t)BB*1024*NPTS];
static __device__ float g_xc2[(size_t)BB*256*NPTS];
static __device__ float g_sqn[(size_t)BB*NPTS];
static __device__ float g_score[(size_t)BB*NPTS];
static __device__ float g_gv[(size_t)BB*2112];
static __device__ float g_bias[(size_t)BB*1024];
static __device__ float g_mu[1024];
static __device__ float g_rstd[1024];
static __device__ int   g_idx[(size_t)BB*NPTS*KNB];
static __device__ int   g_sel[(size_t)BB*MSEL];

// ---------------- generic strided batched GEMMs ----------------
// O[bz*o_b + i*o_i + j] = sum_k A[..] * B[..]; single accumulator, ascending k
// => bitwise identical across tile sizes / load vectorization.

// 128x128 tile, 8x8 microtile, double-buffered smem, vectorized loads.
__global__ void __launch_bounds__(256)
gemm_kernel128(const float* __restrict__ A, const float* __restrict__ Bm,
               float* __restrict__ O, int I, int J, int Kd,
               long a_b, long a_i, long a_k,
               long b_b, long b_k, long b_j,
               long o_b, long o_i)
{
    __shared__ float As[2][8][132];
    __shared__ float Bs[2][8][132];
    int bz = blockIdx.z;
    const float* Ab = A + (long)bz*a_b;
    const float* Bb = Bm + (long)bz*b_b;
    int i0 = blockIdx.y*128, j0 = blockIdx.x*128;
    int tid = threadIdx.x;
    int tx = tid & 15, ty = tid >> 4;
    int lk  = tid >> 5;         // 0..7   (k-row for vector row loads)
    int lv  = (tid & 31) * 4;   // 0..124 (vector offset within row)
    int li  = tid >> 1;         // 0..127 (row for transposed loads)
    int lkv = (tid & 1) * 4;    // 0 or 4 (k offset for transposed loads)

    // mode 0: inner (i/j) dim contiguous, full tile in range -> row float4 loads
    // mode 1: k contiguous, outer stride 16B-aligned -> float4 along k + smem transpose
    // mode 2: generic scalar (old code path)
    const int aMode = ((a_k != 1) && (a_i == 1) && ((a_k & 3) == 0) && (i0 + 128 <= I)) ? 0
                    : ((a_k == 1) && ((a_i & 3) == 0)) ? 1 : 2;
    const int bMode = ((b_j == 1) && ((b_k & 3) == 0) && (j0 + 128 <= J)) ? 0
                    : ((b_k == 1) && ((b_j & 3) == 0)) ? 1 : 2;

    float ra[4], rb[4];

    auto fetchA = [&](int k0) {
        if (aMode == 0) {
            if (k0 + lk < Kd) {
                const float4 v = *reinterpret_cast<const float4*>(&Ab[(long)(k0+lk)*a_k + (i0+lv)]);
                ra[0]=v.x; ra[1]=v.y; ra[2]=v.z; ra[3]=v.w;
            } else { ra[0]=ra[1]=ra[2]=ra[3]=0.f; }
        } else if (aMode == 1) {
            long base = (long)(i0+li)*a_i + k0 + lkv;
            bool iok = (i0+li) < I;
            if (iok && (k0+lkv+3) < Kd) {
                const float4 v = *reinterpret_cast<const float4*>(&Ab[base]);
                ra[0]=v.x; ra[1]=v.y; ra[2]=v.z; ra[3]=v.w;
            } else {
                #pragma unroll
                for (int q = 0; q < 4; q++)
                    ra[q] = (iok && (k0+lkv+q) < Kd) ? Ab[base+q] : 0.f;
            }
        } else {
            #pragma unroll
            for (int r = 0; r < 4; r++) {
                int e = tid*4 + r;
                int ii, kk;
                if (a_k == 1) { ii = e >> 3; kk = e & 7; }
                else          { kk = e >> 7; ii = e & 127; }
                ra[r] = (i0+ii < I && k0+kk < Kd)
                      ? Ab[(long)(i0+ii)*a_i + (long)(k0+kk)*a_k] : 0.f;
            }
        }
    };
    auto commitA = [&](int s) {
        if (aMode == 0) {
            *reinterpret_cast<float4*>(&As[s][lk][lv]) = make_float4(ra[0],ra[1],ra[2],ra[3]);
        } else if (aMode == 1) {
            #pragma unroll
            for (int q = 0; q < 4; q++) As[s][lkv+q][li] = ra[q];
        } else {
            #pragma unroll
            for (int r = 0; r < 4; r++) {
                int e = tid*4 + r;
                int ii, kk;
                if (a_k == 1) { ii = e >> 3; kk = e & 7; }
                else          { kk = e >> 7; ii = e & 127; }
                As[s][kk][ii] = ra[r];
            }
        }
    };
    auto fetchB = [&](int k0) {
        if (bMode == 0) {
            if (k0 + lk < Kd) {
                const float4 v = *reinterpret_cast<const float4*>(&Bb[(long)(k0+lk)*b_k + (j0+lv)]);
                rb[0]=v.x; rb[1]=v.y; rb[2]=v.z; rb[3]=v.w;
            } else { rb[0]=rb[1]=rb[2]=rb[3]=0.f; }
        } else if (bMode == 1) {
            long base = (long)(j0+li)*b_j + k0 + lkv;
            bool jok = (j0+li) < J;
            if (jok && (k0+lkv+3) < Kd) {
                const float4 v = *reinterpret_cast<const float4*>(&Bb[base]);
                rb[0]=v.x; rb[1]=v.y; rb[2]=v.z; rb[3]=v.w;
            } else {
                #pragma unroll
                for (int q = 0; q < 4; q++)
                    rb[q] = (jok && (k0+lkv+q) < Kd) ? Bb[base+q] : 0.f;
            }
        } else {
            #pragma unroll
            for (int r = 0; r < 4; r++) {
                int e = tid*4 + r;
                int jj, kk;
                if (b_j == 1) { jj = e & 127; kk = e >> 7; }
                else          { jj = e >> 3;  kk = e & 7; }
                rb[r] = (j0+jj < J && k0+kk < Kd)
                      ? Bb[(long)(k0+kk)*b_k + (long)(j0+jj)*b_j] : 0.f;
            }
        }
    };
    auto commitB = [&](int s) {
        if (bMode == 0) {
            *reinterpret_cast<float4*>(&Bs[s][lk][lv]) = make_float4(rb[0],rb[1],rb[2],rb[3]);
        } else if (bMode == 1) {
            #pragma unroll
            for (int q = 0; q < 4; q++) Bs[s][lkv+q][li] = rb[q];
        } else {
            #pragma unroll
            for (int r = 0; r < 4; r++) {
                int e = tid*4 + r;
                int jj, kk;
                if (b_j == 1) { jj = e & 127; kk = e >> 7; }
                else          { jj = e >> 3;  kk = e & 7; }
                Bs[s][kk][jj] = rb[r];
            }
        }
    };

    float acc[8][8] = {};
    fetchA(0); fetchB(0);
    commitA(0); commitB(0);
    __syncthreads();
    int s = 0;
    for (int k0 = 0; k0 < Kd; k0 += 8) {
        int kn = k0 + 8;
        bool more = (kn < Kd);
        if (more) { fetchA(kn); fetchB(kn); }     // LDG overlaps compute below
        #pragma unroll
        for (int kk = 0; kk < 8; kk++) {
            float4 a0 = *(const float4*)&As[s][kk][ty*8];
            float4 a1 = *(const float4*)&As[s][kk][ty*8+4];
            float4 b0 = *(const float4*)&Bs[s][kk][tx*8];
            float4 b1 = *(const float4*)&Bs[s][kk][tx*8+4];
            float av[8] = {a0.x,a0.y,a0.z,a0.w,a1.x,a1.y,a1.z,a1.w};
            float bw[8] = {b0.x,b0.y,b0.z,b0.w,b1.x,b1.y,b1.z,b1.w};
            #pragma unroll
            for (int u = 0; u < 8; u++)
                #pragma unroll
                for (int v = 0; v < 8; v++) acc[u][v] += av[u]*bw[v];
        }
        if (more) { commitA(s^1); commitB(s^1); }
        __syncthreads();
        s ^= 1;
    }
    #pragma unroll
    for (int u = 0; u < 8; u++) {
        int i = i0 + ty*8 + u;
        if (i >= I) continue;
        #pragma unroll
        for (int v = 0; v < 8; v++) {
            int j = j0 + tx*8 + v;
            if (j < J) O[(long)bz*o_b + (long)i*o_i + j] = acc[u][v];
        }
    }
}

// 64x64 tile, 4x4 microtile (for small grids)
__global__ void __launch_bounds__(256)
gemm_kernel64(const float* __restrict__ A, const float* __restrict__ Bm,
              float* __restrict__ O, int I, int J, int Kd,
              long a_b, long a_i, long a_k,
              long b_b, long b_k, long b_j,
              long o_b, long o_i)
{
    __shared__ float As[16*65];
    __shared__ float Bs[16*65];
    int bz = blockIdx.z;
    const float* Ab = A + (long)bz*a_b;
    const float* Bb = Bm + (long)bz*b_b;
    int i0 = blockIdx.y*64, j0 = blockIdx.x*64;
    int tid = threadIdx.x;
    int tx = tid & 15, ty = tid >> 4;
    float acc[4][4] = {};
    for (int k0 = 0; k0 < Kd; k0 += 16) {
        #pragma unroll
        for (int r = 0; r < 4; r++) {
            int e = tid + r*256;
            int kk, ii;
            if (a_k == 1) { ii = e >> 4; kk = e & 15; } else { kk = e >> 6; ii = e & 63; }
            float v = 0.f;
            if (i0+ii < I && k0+kk < Kd) v = Ab[(long)(i0+ii)*a_i + (long)(k0+kk)*a_k];
            As[kk*65+ii] = v;
        }
        #pragma unroll
        for (int r = 0; r < 4; r++) {
            int e = tid + r*256;
            int kk, jj;
            if (b_j == 1) { kk = e >> 6; jj = e & 63; } else { jj = e >> 4; kk = e & 15; }
            float v = 0.f;
            if (j0+jj < J && k0+kk < Kd) v = Bb[(long)(k0+kk)*b_k + (long)(j0+jj)*b_j];
            Bs[kk*65+jj] = v;
        }
        __syncthreads();
        #pragma unroll
        for (int kk = 0; kk < 16; kk++) {
            float av[4], bv[4];
            #pragma unroll
            for (int u = 0; u < 4; u++) av[u] = As[kk*65 + ty*4 + u];
            #pragma unroll
            for (int v = 0; v < 4; v++) bv[v] = Bs[kk*65 + tx*4 + v];
            #pragma unroll
            for (int u = 0; u < 4; u++)
                #pragma unroll
                for (int v = 0; v < 4; v++) acc[u][v] += av[u]*bv[v];
        }
        __syncthreads();
    }
    #pragma unroll
    for (int u = 0; u < 4; u++) {
        int i = i0 + ty*4 + u;
        if (i >= I) continue;
        #pragma unroll
        for (int v = 0; v < 4; v++) {
            int j = j0 + tx*4 + v;
            if (j < J) O[(long)bz*o_b + (long)i*o_i + j] = acc[u][v];
        }
    }
}

static void gemm_launch(const float* A, const float* B, float* O,
                        int Bn, int I, int J, int Kd,
                        long a_b, long a_i, long a_k,
                        long b_b, long b_k, long b_j,
                        long o_b, long o_i)
{
    long ctas128 = (long)((J+127)/128)*((I+127)/128)*Bn;
    if (ctas128 >= 256) {
        dim3 grid((J+127)/128, (I+127)/128, Bn);
        gemm_kernel128<<<grid, 256>>>(A,B,O,I,J,Kd,a_b,a_i,a_k,b_b,b_k,b_j,o_b,o_i);
    } else {
        dim3 grid((J+63)/64, (I+63)/64, Bn);
        gemm_kernel64<<<grid, 256>>>(A,B,O,I,J,Kd,a_b,a_i,a_k,b_b,b_k,b_j,o_b,o_i);
    }
}
// c-major output: O[b, o, n]
static void gemmW(const float* W, int Oc, int Kd, int rowlen,
                  const float* X, long xbs, int Np, float* O, long obs)
{
    gemm_launch(W, X, O, BB, Oc, Np, Kd, 0, rowlen, 1, xbs, Np, 1, obs, Np);
}
// n-major output: O[b, n, o]
static void gemmWn(const float* W, int Oc, int Kd, int rowlen,
                   const float* X, long xbs, int Np, float* O)
{
    gemm_launch(X, W, O, BB, Np, Oc, Kd, xbs, 1, Np, 0, 1, rowlen, (long)Oc*Np, Oc);
}
static void gemmTN(const float* X, long xbs, int Np,
                   const float* Y, long ybs, int Mp, int Cin, float* S)
{
    gemm_launch(X, Y, S, BB, Np, Mp, Cin, xbs, 1, Np, ybs, Mp, 1, (long)Np*Mp, Mp);
}

// ---------------- helper kernels ----------------
__global__ void sqnorm_kernel(const float* __restrict__ x, float* __restrict__ sq,
                              int Cin, int Np, long bstride)
{
    int b = blockIdx.y;
    int n = blockIdx.x*256 + threadIdx.x;
    if (n >= Np) return;
    const float* p = x + (long)b*bstride + n;
    float s = 0.f;
    for (int c = 0; c < Cin; c++) { float v = p[(long)c*Np]; s += v*v; }
    sq[(long)b*Np + n] = s;
}

__global__ void knn_topk_kernel(const float* __restrict__ inner, const float* __restrict__ sq,
                                int* __restrict__ idxout, int Np)
{
    __shared__ float sv[8][32];
    __shared__ int   si[8][32];
    int row = blockIdx.x;
    int b = row / Np, n = row % Np;
    int t = threadIdx.x, w = t >> 5, lane = t & 31;
    int chunk = Np >> 3;
    int per = chunk >> 5;
    const float* ir = inner + ((size_t)b*Np + n)*Np;
    const float* sqb = sq + (size_t)b*Np;
    float sn = sqb[n];
    int base = w*chunk;
    float dv[8];
    #pragma unroll
    for (int j = 0; j < 8; j++) {
        if (j < per) {
            int m = base + j*32 + lane;
            dv[j] = sn - 2.0f*ir[m] + sqb[m];
        } else dv[j] = 3.4e38f;
    }
    for (int k = 0; k < KNB; k++) {
        float bv = 3.4e38f; int bj = 0;
        #pragma unroll
        for (int j = 0; j < 8; j++) if (dv[j] < bv) { bv = dv[j]; bj = j; }
        int bi = base + bj*32 + lane;
        #pragma unroll
        for (int o = 16; o; o >>= 1) {
            float ov = __shfl_xor_sync(0xffffffffu, bv, o);
            int   oi = __shfl_xor_sync(0xffffffffu, bi, o);
            if (ov < bv || (ov == bv && oi < bi)) { bv = ov; bi = oi; }
        }
        if ((bi & 31) == lane) dv[(bi - base) >> 5] = 3.4e38f;
        if (lane == 0) { sv[w][k] = bv; si[w][k] = bi; }
    }
    __syncthreads();
    if (w == 0) {
        float cv[8]; int ci[8];
        #pragma unroll
        for (int j = 0; j < 8; j++) {
            int c = lane*8 + j;
            cv[j] = sv[c >> 5][c & 31];
            ci[j] = si[c >> 5][c & 31];
        }
        int* op = idxout + (size_t)row*KNB;
        for (int k = 0; k < KNB; k++) {
            float bv = 3.4e38f; int bi = 0x7fffffff; int bj = -1;
            #pragma unroll
            for (int j = 0; j < 8; j++) {
                if (cv[j] < bv || (cv[j] == bv && ci[j] < bi)) { bv = cv[j]; bi = ci[j]; bj = j; }
            }
            float rbv = bv; int rbi = bi;
            #pragma unroll
            for (int o = 16; o; o >>= 1) {
                float ov = __shfl_xor_sync(0xffffffffu, rbv, o);
                int   oi = __shfl_xor_sync(0xffffffffu, rbi, o);
                if (ov < rbv || (ov == rbv && oi < rbi)) { rbv = ov; rbi = oi; }
            }
            if (bj >= 0 && rbi == bi) cv[bj] = 3.4e38f;
            if (lane == 0) op[k] = rbi;
        }
    }
}

__global__ void edge_pass1_kernel(const float* __restrict__ An, const float* __restrict__ Bn_,
                                  const int* __restrict__ idx, float* __restrict__ pre,
                                  float* __restrict__ s1, float* __restrict__ s2,
                                  int Np, long pre_bs)
{
    int bn = blockIdx.x;
    int b = bn / Np, n = bn % Np;
    int t = threadIdx.x;
    size_t nb = (size_t)b*CF*Np;
    __shared__ int sidx[KNB];
    if (t < KNB) sidx[t] = idx[(size_t)bn*KNB + t];
    __syncthreads();
    float a  = An [nb + (size_t)n*CF + t];
    float bm = Bn_[nb + (size_t)n*CF + t];
    float diff = a - bm;
    const float* Br = Bn_ + nb;
    float s = 0.f, ss = 0.f, mx = -3.4e38f;
    #pragma unroll 4
    for (int k = 0; k < KNB; k++) {
        float v = diff + Br[(size_t)sidx[k]*CF + t];
        s += v; ss += v*v; mx = fmaxf(mx, v);
    }
    pre[(size_t)b*pre_bs + (size_t)t*Np + n] = mx;
    size_t ci = nb + (size_t)t*Np + n;
    s1[ci] = s; s2[ci] = ss;
}

__global__ void bn_stats_kernel(const float* __restrict__ x, float* __restrict__ mu,
                                float* __restrict__ rstd, long bstride, int Np, double invcount)
{
    int o = blockIdx.x, t = threadIdx.x;
    double s = 0.0, ss = 0.0;
    for (int b = 0; b < BB; b++) {
        const float* p = x + (long)b*bstride + (long)o*Np;
        for (int n = t; n < Np; n += 256) { double v = p[n]; s += v; ss += v*v; }
    }
    __shared__ double sh1[256], sh2[256];
    sh1[t] = s; sh2[t] = ss; __syncthreads();
    for (int st = 128; st; st >>= 1) {
        if (t < st) { sh1[t] += sh1[t+st]; sh2[t] += sh2[t+st]; }
        __syncthreads();
    }
    if (!t) {
        double m = sh1[0]*invcount;
        double var = sh2[0]*invcount - m*m;
        mu[o] = (float)m;
        rstd[o] = (float)(1.0/sqrt(var + 1e-5));
    }
}

__global__ void bn_stats2_kernel(const float* __restrict__ s1, const float* __restrict__ s2,
                                 float* __restrict__ mu, float* __restrict__ rstd,
                                 long bstride, int Np, double invcount)
{
    int o = blockIdx.x, t = threadIdx.x;
    double s = 0.0, ss = 0.0;
    for (int b = 0; b < BB; b++) {
        const float* p1 = s1 + (long)b*bstride + (long)o*Np;
        const float* p2 = s2 + (long)b*bstride + (long)o*Np;
        for (int n = t; n < Np; n += 256) { s += (double)p1[n]; ss += (double)p2[n]; }
    }
    __shared__ double sh1[256], sh2[256];
    sh1[t] = s; sh2[t] = ss; __syncthreads();
    for (int st = 128; st; st >>= 1) {
        if (t < st) { sh1[t] += sh1[t+st]; sh2[t] += sh2[t+st]; }
        __syncthreads();
    }
    if (!t) {
        double m = sh1[0]*invcount;
        double var = sh2[0]*invcount - m*m;
        mu[o] = (float)m;
        rstd[o] = (float)(1.0/sqrt(var + 1e-5));
    }
}

__global__ void bn_apply_kernel(const float* __restrict__ x, const float* __restrict__ res,
                                float* __restrict__ out, const float* __restrict__ mu,
                                const float* __restrict__ rstd, size_t total,
                                int Np, int Cch, long bstride)
{
    size_t i = (size_t)blockIdx.x*256 + threadIdx.x;
    if (i >= total) return;
    int n = (int)(i % Np); size_t tt = i / Np;
    int o = (int)(tt % Cch); int b = (int)(tt / Cch);
    size_t off = (size_t)b*bstride + (size_t)o*Np + n;
    float v = (x[off] - mu[o]) * rstd[o];
    v = v >= 0.f ? v : LRELU*v;
    out[off] = (res ? res[off] : 0.f) + v;
}

__global__ void attn_kernel(const float* __restrict__ qn, const float* __restrict__ Kn,
                            const float* __restrict__ Vn, const int* __restrict__ idx,
                            float* __restrict__ out, int Np)
{
    int bn = blockIdx.x;
    int b = bn / Np, n = bn % Np;
    int t = threadIdx.x, w = t >> 5, lane = t & 31;
    size_t nb = (size_t)b*CF*Np;
    __shared__ int   sidx[KNB];
    __shared__ float part[4][KNB];
    __shared__ float aw[KNB];
    if (t < KNB) sidx[t] = idx[(size_t)bn*KNB + t];
    __syncthreads();
    float qc = qn[nb + (size_t)n*CF + t];
    const float* Kb = Kn + nb;
    for (int k = 0; k < KNB; k++) {
        float v = qc * Kb[(size_t)sidx[k]*CF + t];
        #pragma unroll
        for (int o = 16; o; o >>= 1) v += __shfl_down_sync(0xffffffffu, v, o);
        if (lane == 0) part[w][k] = v;
    }
    __syncthreads();
    if (w == 0) {
        float l = (part[0][lane] + part[1][lane] + part[2][lane] + part[3][lane]) * ATTN_SCALE;
        float m = l;
        #pragma unroll
        for (int o = 16; o; o >>= 1) m = fmaxf(m, __shfl_xor_sync(0xffffffffu, m, o));
        float e = expf(l - m);
        float s = e;
        #pragma unroll
        for (int o = 16; o; o >>= 1) s += __shfl_xor_sync(0xffffffffu, s, o);
        aw[lane] = e / s;
    }
    __syncthreads();
    const float* Vb = Vn + nb;
    float acc = 0.f;
    for (int k = 0; k < KNB; k++) acc += aw[k]*Vb[(size_t)sidx[k]*CF + t];
    out[nb + (size_t)t*Np + n] = acc;
}

__global__ void softmax_kernel(float* __restrict__ S, int M, float scale)
{
    __shared__ float sh[NPTS];
    __shared__ float red[256];
    size_t row = blockIdx.x;
    float* r = S + row*(size_t)M;
    int t = threadIdx.x;
    float mx = -3.4e38f;
    for (int i = t; i < M; i += 256) { float v = r[i]*scale; sh[i] = v; mx = fmaxf(mx, v); }
    red[t] = mx; __syncthreads();
    for (int s = 128; s; s >>= 1) { if (t < s) red[t] = fmaxf(red[t], red[t+s]); __syncthreads(); }
    mx = red[0]; __syncthreads();
    float sum = 0.f;
    for (int i = t; i < M; i += 256) { float e = expf(sh[i] - mx); sh[i] = e; sum += e; }
    red[t] = sum; __syncthreads();
    for (int s = 128; s; s >>= 1) { if (t < s) red[t] += red[t+s]; __syncthreads(); }
    float inv = 1.0f/red[0];
    for (int i = t; i < M; i += 256) r[i] = sh[i]*inv;
}

__global__ void colmean_kernel(const float* __restrict__ S, float* __restrict__ score, int R, int M)
{
    int b = blockIdx.y;
    int m = blockIdx.x*256 + threadIdx.x;
    if (m >= M) return;
    const float* p = S + (size_t)b*R*M + m;
    float s = 0.f;
    for (int n = 0; n < R; n++) s += p[(size_t)n*M];
    score[(size_t)b*M + m] = s / (float)R;
}

__global__ void topm_kernel(const float* __restrict__ score, int* __restrict__ sel)
{
    __shared__ float v[NPTS];
    __shared__ int   id[NPTS];
    int b = blockIdx.x, t = threadIdx.x;
    for (int i = t; i < NPTS; i += 1024) { v[i] = score[(size_t)b*NPTS + i]; id[i] = i; }
    __syncthreads();
    for (int k = 2; k <= NPTS; k <<= 1) {
        for (int j = k >> 1; j > 0; j >>= 1) {
            for (int i = t; i < NPTS; i += 1024) {
                int p = i ^ j;
                if (p > i) {
                    bool up = ((i & k) == 0);
                    float vi = v[i], vp = v[p]; int ii = id[i], ip = id[p];
                    bool inOrder = (vi > vp) || (vi == vp && ii < ip);
                    if (up ? !inOrder : inOrder) { v[i]=vp; v[p]=vi; id[i]=ip; id[p]=ii; }
                }
            }
            __syncthreads();
        }
    }
    for (int i = t; i < MSEL; i += 1024) sel[(size_t)b*MSEL + i] = id[i];
}

__global__ void gather_kernel(const float* __restrict__ x, const int* __restrict__ sel,
                              float* __restrict__ out, int Np, int Ms)
{
    size_t i = (size_t)blockIdx.x*256 + threadIdx.x;
    if (i >= (size_t)BB*CF*Ms) return;
    int j = (int)(i % Ms); size_t tt = i / Ms;
    int c = (int)(tt % CF); int b = (int)(tt / CF);
    out[i] = x[((size_t)b*CF + c)*Np + sel[(size_t)b*Ms + j]];
}

__global__ void add_kernel(const float* __restrict__ a, const float* __restrict__ b,
                           float* __restrict__ o, size_t total)
{
    size_t i = (size_t)blockIdx.x*256 + threadIdx.x;
    if (i < total) o[i] = a[i] + b[i];
}

__global__ void maxmean_kernel(const float* __restrict__ xh, float* __restrict__ g, int Np)
{
    __shared__ float rm[256], rs[256];
    int bo = blockIdx.x;
    int b = bo >> 10, o = bo & 1023;
    const float* p = xh + ((size_t)b*1024 + o)*Np;
    int t = threadIdx.x;
    float mx = -3.4e38f, s = 0.f;
    for (int n = t; n < Np; n += 256) { float v = p[n]; mx = fmaxf(mx, v); s += v; }
    rm[t] = mx; rs[t] = s; __syncthreads();
    for (int st = 128; st; st >>= 1) {
        if (t < st) { rm[t] = fmaxf(rm[t], rm[t+st]); rs[t] += rs[t+st]; }
        __syncthreads();
    }
    if (!t) { g[(size_t)b*2112 + o] = rm[0]; g[(size_t)b*2112 + 1024 + o] = rs[0]/(float)Np; }
}

__global__ void cid_kernel(const float* __restrict__ cat, const float* __restrict__ Wc1,
                           float* __restrict__ g)
{
    int o = threadIdx.x;
    float y[BB];
    for (int b = 0; b < BB; b++) {
        float s = 0.f;
        for (int c = 0; c < 16; c++) s += Wc1[o*16+c]*cat[b*16+c];
        y[b] = s;
    }
    float mu = 0.f;
    for (int b = 0; b < BB; b++) mu += y[b];
    mu *= (1.0f/BB);
    float var = 0.f;
    for (int b = 0; b < BB; b++) { float dd = y[b]-mu; var += dd*dd; }
    var *= (1.0f/BB);
    float rs = rsqrtf(var + 1e-5f);
    for (int b = 0; b < BB; b++) {
        float v = (y[b]-mu)*rs;
        g[(size_t)b*2112 + 2048 + o] = v >= 0.f ? v : LRELU*v;
    }
}

__global__ void bias_kernel(const float* __restrict__ W, const float* __restrict__ g,
                            float* __restrict__ bias)
{
    int gw = blockIdx.x*8 + (threadIdx.x >> 5);
    if (gw >= BB*1024) return;
    int lane = threadIdx.x & 31;
    int b = gw >> 10, o = gw & 1023;
    const float* wr = W + (size_t)o*2240;
    const float* gb = g + (size_t)b*2112;
    float s = 0.f;
    for (int c = lane; c < 2112; c += 32) s += wr[c]*gb[c];
    #pragma unroll
    for (int off = 16; off; off >>= 1) s += __shfl_down_sync(0xffffffffu, s, off);
    if (!lane) bias[(size_t)b*1024 + o] = s;
}

__global__ void addbias_kernel(float* __restrict__ xc, const float* __restrict__ bias)
{
    size_t i = (size_t)blockIdx.x*256 + threadIdx.x;
    if (i >= (size_t)BB*1024*NPTS) return;
    size_t tt = i / NPTS;
    int o = (int)(tt % 1024); int b = (int)(tt / 1024);
    xc[i] += bias[(size_t)b*1024 + o];
}

// ---------------- host orchestration ----------------
struct Bufs {
    float *big,*h,*hfull,*bq,*bk,*bv,*ba,*by,*f1,*s1,*s2,*hd,*hu,*xtmp,*xh,*xc,*xc2;
    float *sq,*score,*gv,*bias,*mu,*rstd;
    int *idx,*sel;
};

static void getbufs(Bufs& P)
{
    cudaGetSymbolAddress((void**)&P.big, g_big);
    cudaGetSymbolAddress((void**)&P.h, g_h);
    cudaGetSymbolAddress((void**)&P.hfull, g_hfull);
    cudaGetSymbolAddress((void**)&P.bq, g_bq);
    cudaGetSymbolAddress((void**)&P.bk, g_bk);
    cudaGetSymbolAddress((void**)&P.bv, g_bv);
    cudaGetSymbolAddress((void**)&P.ba, g_ba);
    cudaGetSymbolAddress((void**)&P.by, g_by);
    cudaGetSymbolAddress((void**)&P.f1, g_f1);
    cudaGetSymbolAddress((void**)&P.s1, g_s1);
    cudaGetSymbolAddress((void**)&P.s2, g_s2);
    cudaGetSymbolAddress((void**)&P.hd, g_hd);
    cudaGetSymbolAddress((void**)&P.hu, g_hu);
    cudaGetSymbolAddress((void**)&P.xtmp, g_xtmp);
    cudaGetSymbolAddress((void**)&P.xh, g_xh);
    cudaGetSymbolAddress((void**)&P.xc, g_xc);
    cudaGetSymbolAddress((void**)&P.xc2, g_xc2);
    cudaGetSymbolAddress((void**)&P.sq, g_sqn);
    cudaGetSymbolAddress((void**)&P.score, g_score);
    cudaGetSymbolAddress((void**)&P.gv, g_gv);
    cudaGetSymbolAddress((void**)&P.bias, g_bias);
    cudaGetSymbolAddress((void**)&P.mu, g_mu);
    cudaGetSymbolAddress((void**)&P.rstd, g_rstd);
    cudaGetSymbolAddress((void**)&P.idx, g_idx);
    cudaGetSymbolAddress((void**)&P.sel, g_sel);
}

static inline size_t cdiv(size_t a, size_t b) { return (a + b - 1)/b; }

static void run_bn(float* x, const float* res, float* out, int Cch, int Np, long bstride, Bufs& P)
{
    bn_stats_kernel<<<Cch, 256>>>(x, P.mu, P.rstd, bstride, Np, 1.0/((double)BB*Np));
    size_t total = (size_t)BB*Cch*Np;
    bn_apply_kernel<<<(unsigned)cdiv(total,256), 256>>>(x, res, out, P.mu, P.rstd, total, Np, Cch, bstride);
}

static void run_knn(const float* xin, long xbs, int cin, int Np, Bufs& P)
{
    dim3 gs((Np+255)/256, BB);
    sqnorm_kernel<<<gs, 256>>>(xin, P.sq, cin, Np, xbs);
    gemmTN(xin, xbs, Np, xin, xbs, Np, cin, P.big);
    knn_topk_kernel<<<BB*Np, 256>>>(P.big, P.sq, P.idx, Np);
}

static void run_edge(const float* xin, long xbs, int cin, const float* W, int rowlen,
                     float* outslice, long out_bs, Bufs& P)
{
    run_knn(xin, xbs, cin, NPTS, P);
    gemmWn(W,       CF, cin, rowlen, xin, xbs, NPTS, P.bq);
    gemmWn(W + cin, CF, cin, rowlen, xin, xbs, NPTS, P.bk);
    edge_pass1_kernel<<<BB*NPTS, 128>>>(P.bq, P.bk, P.idx, outslice, P.s1, P.s2, NPTS, out_bs);
    size_t total = (size_t)BB*CF*NPTS;
    bn_stats2_kernel<<<CF, 256>>>(P.s1, P.s2, P.mu, P.rstd, (long)CF*NPTS, NPTS,
                                  1.0/((double)BB*NPTS*KNB));
    bn_apply_kernel<<<(unsigned)cdiv(total,256), 256>>>(outslice, nullptr, outslice, P.mu, P.rstd,
                                                        total, NPTS, CF, out_bs);
}

static void run_n2p(const float* xin, long xbs, int cin, int Np,
                    const float* Wq, const float* Wk, const float* Wv, const float* Wo,
                    const float* Wf1, const float* Wf2, float* outp, Bufs& P)
{
    run_knn(xin, xbs, cin, Np, P);
    long fbs = (long)CF*Np;
    gemmWn(Wq, CF, cin, cin, xin, xbs, Np, P.bq);
    gemmWn(Wk, CF, cin, cin, xin, xbs, Np, P.bk);
    gemmWn(Wv, CF, cin, cin, xin, xbs, Np, P.bv);
    attn_kernel<<<BB*Np, 128>>>(P.bq, P.bk, P.bv, P.idx, P.ba, Np);
    gemmW(Wo, CF, CF, CF, P.ba, fbs, Np, P.by, fbs);
    run_bn(P.by, nullptr, P.by, CF, Np, fbs, P);
    long f1bs = 512L*Np;
    gemmW(Wf1, 512, CF, CF, P.by, fbs, Np, P.f1, f1bs);
    run_bn(P.f1, nullptr, P.f1, 512, Np, f1bs, P);
    gemmW(Wf2, CF, 512, 512, P.f1, f1bs, Np, P.bq, fbs);
    bn_stats_kernel<<<CF, 256>>>(P.bq, P.mu, P.rstd, fbs, Np, 1.0/((double)BB*Np));
    size_t total = (size_t)BB*CF*Np;
    bn_apply_kernel<<<(unsigned)cdiv(total,256), 256>>>(P.bq, P.by, outp, P.mu, P.rstd,
                                                        total, Np, CF, fbs);
}

extern "C" void kernel_launch(void* const* d_in, const int* in_sizes, int n_in,
                              void* d_out, int out_size)
{
    const float* x    = (const float*)d_in[0];
    const float* cat  = (const float*)d_in[1];
    const float* We0  = (const float*)d_in[2];
    const float* We1  = (const float*)d_in[3];
    const float *Wq[3], *Wk[3], *Wv[3], *Wo[3], *Wf1[3], *Wf2[3];
    for (int l = 0; l < 3; l++) {
        Wq[l]  = (const float*)d_in[4 + 6*l];
        Wk[l]  = (const float*)d_in[5 + 6*l];
        Wv[l]  = (const float*)d_in[6 + 6*l];
        Wo[l]  = (const float*)d_in[7 + 6*l];
        Wf1[l] = (const float*)d_in[8 + 6*l];
        Wf2[l] = (const float*)d_in[9 + 6*l];
    }
    const float* Wdq = (const float*)d_in[22];
    const float* Wdk = (const float*)d_in[23];
    const float* Wuq = (const float*)d_in[24];
    const float* Wuk = (const float*)d_in[25];
    const float* Wuv = (const float*)d_in[26];
    const float* Wc  = (const float*)d_in[27];
    const float* Wc1 = (const float*)d_in[28];
    const float* Wc2 = (const float*)d_in[29];
    const float* Wc3 = (const float*)d_in[30];
    const float* Wc4 = (const float*)d_in[31];

    Bufs P; getbufs(P);
    const long HBS = 256L*NPTS;
    const long FBS = (long)CF*NPTS;

    run_edge(x,   3L*NPTS, 3,   We0, 6,   P.h,             HBS, P);
    run_edge(P.h, HBS,     128, We1, 256, P.h + 128L*NPTS, HBS, P);

    run_n2p(P.h, HBS, 256, NPTS, Wq[0], Wk[0], Wv[0], Wo[0], Wf1[0], Wf2[0], P.hfull, P);

    // down_global
    gemmW(Wdq, CF, CF, CF, P.hfull, FBS, NPTS, P.bq, FBS);
    gemmW(Wdk, CF, CF, CF, P.hfull, FBS, NPTS, P.bk, FBS);
    gemmTN(P.bq, FBS, NPTS, P.bk, FBS, NPTS, CF, P.big);
    softmax_kernel<<<BB*NPTS, 256>>>(P.big, NPTS, ATTN_SCALE);
    {
        dim3 gs((NPTS+255)/256, BB);
        colmean_kernel<<<gs, 256>>>(P.big, P.score, NPTS, NPTS);
    }
    topm_kernel<<<BB, 1024>>>(P.score, P.sel);
    {
        size_t total = (size_t)BB*CF*MSEL;
        gather_kernel<<<(unsigned)cdiv(total,256), 256>>>(P.hfull, P.sel, P.hd, NPTS, MSEL);
    }

    run_n2p(P.hd, (long)CF*MSEL, CF, MSEL, Wq[1], Wk[1], Wv[1], Wo[1], Wf1[1], Wf2[1], P.hd, P);

    // up_cross
    gemmW(Wuq, CF, CF, CF, P.hfull, FBS, NPTS, P.bq, FBS);
    gemmW(Wuk, CF, CF, CF, P.hd, (long)CF*MSEL, MSEL, P.bk, (long)CF*MSEL);
    gemmW(Wuv, CF, CF, CF, P.hd, (long)CF*MSEL, MSEL, P.bv, (long)CF*MSEL);
    gemmTN(P.bq, FBS, NPTS, P.bk, (long)CF*MSEL, MSEL, CF, P.big);
    softmax_kernel<<<BB*NPTS, 256>>>(P.big, MSEL, ATTN_SCALE);
    gemm_launch(P.bv, P.big, P.hu, BB, CF, NPTS, MSEL,
                (long)CF*MSEL, MSEL, 1,
                (long)NPTS*MSEL, 1, MSEL,
                FBS, NPTS);
    {
        size_t total = (size_t)BB*CF*NPTS;
        add_kernel<<<(unsigned)cdiv(total,256), 256>>>(P.hfull, P.hu, P.hu, total);
    }

    run_n2p(P.hu, FBS, CF, NPTS, Wq[2], Wk[2], Wv[2], Wo[2], Wf1[2], Wf2[2], P.xtmp, P);

    gemmW(Wc, 1024, CF, CF, P.xtmp, FBS, NPTS, P.xh, 1024L*NPTS);
    run_bn(P.xh, nullptr, P.xh, 1024, NPTS, 1024L*NPTS, P);

    maxmean_kernel<<<BB*1024, 256>>>(P.xh, P.gv, NPTS);
    cid_kernel<<<1, 64>>>(cat, Wc1, P.gv);
    bias_kernel<<<1024, 256>>>(Wc2, P.gv, P.bias);

    gemmW(Wc2 + 2112, 1024, CF, 2240, P.xtmp, FBS, NPTS, P.xc, 1024L*NPTS);
    {
        size_t total = (size_t)BB*1024*NPTS;
        addbias_kernel<<<(unsigned)cdiv(total,256), 256>>>(P.xc, P.bias);
    }
    run_bn(P.xc, nullptr, P.xc, 1024, NPTS, 1024L*NPTS, P);

    gemmW(Wc3, 256, 1024, 1024, P.xc, 1024L*NPTS, NPTS, P.xc2, 256L*NPTS);
    run_bn(P.xc2, nullptr, P.xc2, 256, NPTS, 256L*NPTS, P);

    gemmW(Wc4, 50, 256, 256, P.xc2, 256L*NPTS, NPTS, (float*)d_out, 50L*NPTS);

    (void)in_sizes; (void)n_in; (void)out_size;
}

// round 12
// speedup vs baseline: 1.4491x; 1.0980x over previous
#include <cuda_runtime.h>
#include <math.h>

#define BB 8
#define NPTS 2048
#define KNB 32
#define MSEL 1024
#define CF 128
#define LRELU 0.2f
#define ATTN_SCALE 0.088388347648318447f

// ---------------- static device scratch ----------------
static __device__ float g_big[(size_t)BB*NPTS*NPTS];
static __device__ float g_h[(size_t)BB*256*NPTS];
static __device__ float g_hfull[(size_t)BB*CF*NPTS];
static __device__ float g_bq[(size_t)BB*CF*NPTS];
static __device__ float g_bk[(size_t)BB*CF*NPTS];
static __device__ float g_bv[(size_t)BB*CF*NPTS];
static __device__ float g_ba[(size_t)BB*CF*NPTS];
static __device__ float g_by[(size_t)BB*CF*NPTS];
static __device__ float g_f1[(size_t)BB*512*NPTS];
static __device__ float g_s1[(size_t)BB*CF*NPTS];
static __device__ float g_s2[(size_t)BB*CF*NPTS];
static __device__ float g_hd[(size_t)BB*CF*MSEL];
static __device__ float g_hu[(size_t)BB*CF*NPTS];
static __device__ float g_xtmp[(size_t)BB*CF*NPTS];
static __device__ float g_xh[(size_t)BB*1024*NPTS];
static __device__ float g_xc[(size_t)BB*1024*NPTS];
static __device__ float g_xc2[(size_t)BB*256*NPTS];
static __device__ float g_sqn[(size_t)BB*NPTS];
static __device__ float g_score[(size_t)BB*NPTS];
static __device__ float g_gv[(size_t)BB*2112];
static __device__ float g_bias[(size_t)BB*1024];
static __device__ float g_mu[1024];
static __device__ float g_rstd[1024];
static __device__ int   g_idx[(size_t)BB*NPTS*KNB];
static __device__ int   g_sel[(size_t)BB*MSEL];

// ---------------- SYRK: O = X^T X (symmetric, bitwise), upper triangle + mirror ----
// X layout: [c][n], c-major rows of length Np (element (n,c) at c*Np + n).
__global__ void __launch_bounds__(256, 2)
syrk_kernel(const float* __restrict__ X, float* __restrict__ O,
            int Np, int Kd, long xbs)
{
    __shared__ float As[2][8][132];
    __shared__ float Bs[2][8][132];
    int bz = blockIdx.z;
    const float* Xb = X + (long)bz*xbs;
    float* Ob = O + (size_t)bz*Np*Np;
    int nt = Np >> 7;
    int t = blockIdx.x, bi = 0, rem = nt;
    while (t >= rem) { t -= rem; bi++; rem--; }
    int bj = bi + t;
    int i0 = bi << 7, j0 = bj << 7;

    int tid = threadIdx.x;
    int tx = tid & 15, ty = tid >> 4;
    int lk = tid >> 5, lv = (tid & 31) * 4;

    float ra[4], rb[4];
    auto fetch = [&](int k0) {
        if (k0 + lk < Kd) {
            float4 a = *reinterpret_cast<const float4*>(&Xb[(long)(k0+lk)*Np + (i0+lv)]);
            ra[0]=a.x; ra[1]=a.y; ra[2]=a.z; ra[3]=a.w;
            float4 b = *reinterpret_cast<const float4*>(&Xb[(long)(k0+lk)*Np + (j0+lv)]);
            rb[0]=b.x; rb[1]=b.y; rb[2]=b.z; rb[3]=b.w;
        } else {
            ra[0]=ra[1]=ra[2]=ra[3]=0.f;
            rb[0]=rb[1]=rb[2]=rb[3]=0.f;
        }
    };
    auto commit = [&](int s) {
        *reinterpret_cast<float4*>(&As[s][lk][lv]) = make_float4(ra[0],ra[1],ra[2],ra[3]);
        *reinterpret_cast<float4*>(&Bs[s][lk][lv]) = make_float4(rb[0],rb[1],rb[2],rb[3]);
    };

    float acc[8][8] = {};
    fetch(0); commit(0);
    __syncthreads();
    int s = 0;
    for (int k0 = 0; k0 < Kd; k0 += 8) {
        int kn = k0 + 8;
        bool more = (kn < Kd);
        if (more) fetch(kn);
        #pragma unroll
        for (int kk = 0; kk < 8; kk++) {
            float4 a0 = *(const float4*)&As[s][kk][ty*8];
            float4 a1 = *(const float4*)&As[s][kk][ty*8+4];
            float4 b0 = *(const float4*)&Bs[s][kk][tx*8];
            float4 b1 = *(const float4*)&Bs[s][kk][tx*8+4];
            float av[8] = {a0.x,a0.y,a0.z,a0.w,a1.x,a1.y,a1.z,a1.w};
            float bw[8] = {b0.x,b0.y,b0.z,b0.w,b1.x,b1.y,b1.z,b1.w};
            #pragma unroll
            for (int u = 0; u < 8; u++)
                #pragma unroll
                for (int v = 0; v < 8; v++) acc[u][v] += av[u]*bw[v];
        }
        if (more) commit(s^1);
        __syncthreads();
        s ^= 1;
    }
    // normal write: O[i, j]
    #pragma unroll
    for (int u = 0; u < 8; u++) {
        int i = i0 + ty*8 + u;
        *reinterpret_cast<float4*>(&Ob[(size_t)i*Np + j0 + tx*8]) =
            make_float4(acc[u][0], acc[u][1], acc[u][2], acc[u][3]);
        *reinterpret_cast<float4*>(&Ob[(size_t)i*Np + j0 + tx*8 + 4]) =
            make_float4(acc[u][4], acc[u][5], acc[u][6], acc[u][7]);
    }
    // mirror write: O[j, i] (bitwise-equal values by commutativity)
    if (bi != bj) {
        float* Ms = &As[0][0][0];   // reuse as [16][132]
        for (int vv = 0; vv < 8; vv++) {
            __syncthreads();
            #pragma unroll
            for (int u = 0; u < 8; u++) Ms[tx*132 + ty*8 + u] = acc[u][vv];
            __syncthreads();
            int jl = tid >> 4;          // 0..15
            int ic = (tid & 15) * 8;    // 0..120
            int jg = j0 + jl*8 + vv;
            float4 w0 = *reinterpret_cast<float4*>(&Ms[jl*132 + ic]);
            float4 w1 = *reinterpret_cast<float4*>(&Ms[jl*132 + ic + 4]);
            *reinterpret_cast<float4*>(&Ob[(size_t)jg*Np + i0 + ic]) = w0;
            *reinterpret_cast<float4*>(&Ob[(size_t)jg*Np + i0 + ic + 4]) = w1;
        }
    }
}

// ---------------- generic strided batched GEMMs ----------------
// O[bz*o_b + i*o_i + j] = sum_k A[..] * B[..]; single accumulator, ascending k.

// 128x128 tile, 8x8 microtile, double-buffered smem, vectorized loads.
__global__ void __launch_bounds__(256, 2)
gemm_kernel128(const float* __restrict__ A, const float* __restrict__ Bm,
               float* __restrict__ O, int I, int J, int Kd,
               long a_b, long a_i, long a_k,
               long b_b, long b_k, long b_j,
               long o_b, long o_i)
{
    __shared__ float As[2][8][132];
    __shared__ float Bs[2][8][132];
    int bz = blockIdx.z;
    const float* Ab = A + (long)bz*a_b;
    const float* Bb = Bm + (long)bz*b_b;
    int i0 = blockIdx.y*128, j0 = blockIdx.x*128;
    int tid = threadIdx.x;
    int tx = tid & 15, ty = tid >> 4;
    int lk  = tid >> 5;
    int lv  = (tid & 31) * 4;
    int li  = tid >> 1;
    int lkv = (tid & 1) * 4;

    const int aMode = ((a_k != 1) && (a_i == 1) && ((a_k & 3) == 0) && (i0 + 128 <= I)) ? 0
                    : ((a_k == 1) && ((a_i & 3) == 0)) ? 1 : 2;
    const int bMode = ((b_j == 1) && ((b_k & 3) == 0) && (j0 + 128 <= J)) ? 0
                    : ((b_k == 1) && ((b_j & 3) == 0)) ? 1 : 2;

    float ra[4], rb[4];

    auto fetchA = [&](int k0) {
        if (aMode == 0) {
            if (k0 + lk < Kd) {
                const float4 v = *reinterpret_cast<const float4*>(&Ab[(long)(k0+lk)*a_k + (i0+lv)]);
                ra[0]=v.x; ra[1]=v.y; ra[2]=v.z; ra[3]=v.w;
            } else { ra[0]=ra[1]=ra[2]=ra[3]=0.f; }
        } else if (aMode == 1) {
            long base = (long)(i0+li)*a_i + k0 + lkv;
            bool iok = (i0+li) < I;
            if (iok && (k0+lkv+3) < Kd) {
                const float4 v = *reinterpret_cast<const float4*>(&Ab[base]);
                ra[0]=v.x; ra[1]=v.y; ra[2]=v.z; ra[3]=v.w;
            } else {
                #pragma unroll
                for (int q = 0; q < 4; q++)
                    ra[q] = (iok && (k0+lkv+q) < Kd) ? Ab[base+q] : 0.f;
            }
        } else {
            #pragma unroll
            for (int r = 0; r < 4; r++) {
                int e = tid*4 + r;
                int ii, kk;
                if (a_k == 1) { ii = e >> 3; kk = e & 7; }
                else          { kk = e >> 7; ii = e & 127; }
                ra[r] = (i0+ii < I && k0+kk < Kd)
                      ? Ab[(long)(i0+ii)*a_i + (long)(k0+kk)*a_k] : 0.f;
            }
        }
    };
    auto commitA = [&](int s) {
        if (aMode == 0) {
            *reinterpret_cast<float4*>(&As[s][lk][lv]) = make_float4(ra[0],ra[1],ra[2],ra[3]);
        } else if (aMode == 1) {
            #pragma unroll
            for (int q = 0; q < 4; q++) As[s][lkv+q][li] = ra[q];
        } else {
            #pragma unroll
            for (int r = 0; r < 4; r++) {
                int e = tid*4 + r;
                int ii, kk;
                if (a_k == 1) { ii = e >> 3; kk = e & 7; }
                else          { kk = e >> 7; ii = e & 127; }
                As[s][kk][ii] = ra[r];
            }
        }
    };
    auto fetchB = [&](int k0) {
        if (bMode == 0) {
            if (k0 + lk < Kd) {
                const float4 v = *reinterpret_cast<const float4*>(&Bb[(long)(k0+lk)*b_k + (j0+lv)]);
                rb[0]=v.x; rb[1]=v.y; rb[2]=v.z; rb[3]=v.w;
            } else { rb[0]=rb[1]=rb[2]=rb[3]=0.f; }
        } else if (bMode == 1) {
            long base = (long)(j0+li)*b_j + k0 + lkv;
            bool jok = (j0+li) < J;
            if (jok && (k0+lkv+3) < Kd) {
                const float4 v = *reinterpret_cast<const float4*>(&Bb[base]);
                rb[0]=v.x; rb[1]=v.y; rb[2]=v.z; rb[3]=v.w;
            } else {
                #pragma unroll
                for (int q = 0; q < 4; q++)
                    rb[q] = (jok && (k0+lkv+q) < Kd) ? Bb[base+q] : 0.f;
            }
        } else {
            #pragma unroll
            for (int r = 0; r < 4; r++) {
                int e = tid*4 + r;
                int jj, kk;
                if (b_j == 1) { jj = e & 127; kk = e >> 7; }
                else          { jj = e >> 3;  kk = e & 7; }
                rb[r] = (j0+jj < J && k0+kk < Kd)
                      ? Bb[(long)(k0+kk)*b_k + (long)(j0+jj)*b_j] : 0.f;
            }
        }
    };
    auto commitB = [&](int s) {
        if (bMode == 0) {
            *reinterpret_cast<float4*>(&Bs[s][lk][lv]) = make_float4(rb[0],rb[1],rb[2],rb[3]);
        } else if (bMode == 1) {
            #pragma unroll
            for (int q = 0; q < 4; q++) Bs[s][lkv+q][li] = rb[q];
        } else {
            #pragma unroll
            for (int r = 0; r < 4; r++) {
                int e = tid*4 + r;
                int jj, kk;
                if (b_j == 1) { jj = e & 127; kk = e >> 7; }
                else          { jj = e >> 3;  kk = e & 7; }
                Bs[s][kk][jj] = rb[r];
            }
        }
    };

    float acc[8][8] = {};
    fetchA(0); fetchB(0);
    commitA(0); commitB(0);
    __syncthreads();
    int s = 0;
    for (int k0 = 0; k0 < Kd; k0 += 8) {
        int kn = k0 + 8;
        bool more = (kn < Kd);
        if (more) { fetchA(kn); fetchB(kn); }
        #pragma unroll
        for (int kk = 0; kk < 8; kk++) {
            float4 a0 = *(const float4*)&As[s][kk][ty*8];
            float4 a1 = *(const float4*)&As[s][kk][ty*8+4];
            float4 b0 = *(const float4*)&Bs[s][kk][tx*8];
            float4 b1 = *(const float4*)&Bs[s][kk][tx*8+4];
            float av[8] = {a0.x,a0.y,a0.z,a0.w,a1.x,a1.y,a1.z,a1.w};
            float bw[8] = {b0.x,b0.y,b0.z,b0.w,b1.x,b1.y,b1.z,b1.w};
            #pragma unroll
            for (int u = 0; u < 8; u++)
                #pragma unroll
                for (int v = 0; v < 8; v++) acc[u][v] += av[u]*bw[v];
        }
        if (more) { commitA(s^1); commitB(s^1); }
        __syncthreads();
        s ^= 1;
    }
    #pragma unroll
    for (int u = 0; u < 8; u++) {
        int i = i0 + ty*8 + u;
        if (i >= I) continue;
        #pragma unroll
        for (int v = 0; v < 8; v++) {
            int j = j0 + tx*8 + v;
            if (j < J) O[(long)bz*o_b + (long)i*o_i + j] = acc[u][v];
        }
    }
}

// 64x64 tile, 4x4 microtile (small grids)
__global__ void __launch_bounds__(256)
gemm_kernel64(const float* __restrict__ A, const float* __restrict__ Bm,
              float* __restrict__ O, int I, int J, int Kd,
              long a_b, long a_i, long a_k,
              long b_b, long b_k, long b_j,
              long o_b, long o_i)
{
    __shared__ float As[16*65];
    __shared__ float Bs[16*65];
    int bz = blockIdx.z;
    const float* Ab = A + (long)bz*a_b;
    const float* Bb = Bm + (long)bz*b_b;
    int i0 = blockIdx.y*64, j0 = blockIdx.x*64;
    int tid = threadIdx.x;
    int tx = tid & 15, ty = tid >> 4;
    float acc[4][4] = {};
    for (int k0 = 0; k0 < Kd; k0 += 16) {
        #pragma unroll
        for (int r = 0; r < 4; r++) {
            int e = tid + r*256;
            int kk, ii;
            if (a_k == 1) { ii = e >> 4; kk = e & 15; } else { kk = e >> 6; ii = e & 63; }
            float v = 0.f;
            if (i0+ii < I && k0+kk < Kd) v = Ab[(long)(i0+ii)*a_i + (long)(k0+kk)*a_k];
            As[kk*65+ii] = v;
        }
        #pragma unroll
        for (int r = 0; r < 4; r++) {
            int e = tid + r*256;
            int kk, jj;
            if (b_j == 1) { kk = e >> 6; jj = e & 63; } else { jj = e >> 4; kk = e & 15; }
            float v = 0.f;
            if (j0+jj < J && k0+kk < Kd) v = Bb[(long)(k0+kk)*b_k + (long)(j0+jj)*b_j];
            Bs[kk*65+jj] = v;
        }
        __syncthreads();
        #pragma unroll
        for (int kk = 0; kk < 16; kk++) {
            float av[4], bv[4];
            #pragma unroll
            for (int u = 0; u < 4; u++) av[u] = As[kk*65 + ty*4 + u];
            #pragma unroll
            for (int v = 0; v < 4; v++) bv[v] = Bs[kk*65 + tx*4 + v];
            #pragma unroll
            for (int u = 0; u < 4; u++)
                #pragma unroll
                for (int v = 0; v < 4; v++) acc[u][v] += av[u]*bv[v];
        }
        __syncthreads();
    }
    #pragma unroll
    for (int u = 0; u < 4; u++) {
        int i = i0 + ty*4 + u;
        if (i >= I) continue;
        #pragma unroll
        for (int v = 0; v < 4; v++) {
            int j = j0 + tx*4 + v;
            if (j < J) O[(long)bz*o_b + (long)i*o_i + j] = acc[u][v];
        }
    }
}

static void gemm_launch(const float* A, const float* B, float* O,
                        int Bn, int I, int J, int Kd,
                        long a_b, long a_i, long a_k,
                        long b_b, long b_k, long b_j,
                        long o_b, long o_i)
{
    long ctas128 = (long)((J+127)/128)*((I+127)/128)*Bn;
    if (ctas128 >= 112) {
        dim3 grid((J+127)/128, (I+127)/128, Bn);
        gemm_kernel128<<<grid, 256>>>(A,B,O,I,J,Kd,a_b,a_i,a_k,b_b,b_k,b_j,o_b,o_i);
    } else {
        dim3 grid((J+63)/64, (I+63)/64, Bn);
        gemm_kernel64<<<grid, 256>>>(A,B,O,I,J,Kd,a_b,a_i,a_k,b_b,b_k,b_j,o_b,o_i);
    }
}
// c-major output: O[b, o, n]
static void gemmW(const float* W, int Oc, int Kd, int rowlen,
                  const float* X, long xbs, int Np, float* O, long obs)
{
    gemm_launch(W, X, O, BB, Oc, Np, Kd, 0, rowlen, 1, xbs, Np, 1, obs, Np);
}
// n-major output: O[b, n, o]
static void gemmWn(const float* W, int Oc, int Kd, int rowlen,
                   const float* X, long xbs, int Np, float* O)
{
    gemm_launch(X, W, O, BB, Np, Oc, Kd, xbs, 1, Np, 0, 1, rowlen, (long)Oc*Np, Oc);
}
static void gemmTN(const float* X, long xbs, int Np,
                   const float* Y, long ybs, int Mp, int Cin, float* S)
{
    gemm_launch(X, Y, S, BB, Np, Mp, Cin, xbs, 1, Np, ybs, Mp, 1, (long)Np*Mp, Mp);
}

// ---------------- helper kernels ----------------
__global__ void sqnorm_kernel(const float* __restrict__ x, float* __restrict__ sq,
                              int Cin, int Np, long bstride)
{
    int b = blockIdx.y;
    int n = blockIdx.x*256 + threadIdx.x;
    if (n >= Np) return;
    const float* p = x + (long)b*bstride + n;
    float s = 0.f;
    for (int c = 0; c < Cin; c++) { float v = p[(long)c*Np]; s += v*v; }
    sq[(long)b*Np + n] = s;
}

__global__ void knn_topk_kernel(const float* __restrict__ inner, const float* __restrict__ sq,
                                int* __restrict__ idxout, int Np)
{
    __shared__ float sv[8][32];
    __shared__ int   si[8][32];
    int row = blockIdx.x;
    int b = row / Np, n = row % Np;
    int t = threadIdx.x, w = t >> 5, lane = t & 31;
    int chunk = Np >> 3;
    int per = chunk >> 5;
    const float* ir = inner + ((size_t)b*Np + n)*Np;
    const float* sqb = sq + (size_t)b*Np;
    float sn = sqb[n];
    int base = w*chunk;
    float dv[8];
    #pragma unroll
    for (int j = 0; j < 8; j++) {
        if (j < per) {
            int m = base + j*32 + lane;
            dv[j] = sn - 2.0f*ir[m] + sqb[m];
        } else dv[j] = 3.4e38f;
    }
    for (int k = 0; k < KNB; k++) {
        float bv = 3.4e38f; int bj = 0;
        #pragma unroll
        for (int j = 0; j < 8; j++) if (dv[j] < bv) { bv = dv[j]; bj = j; }
        int bi = base + bj*32 + lane;
        #pragma unroll
        for (int o = 16; o; o >>= 1) {
            float ov = __shfl_xor_sync(0xffffffffu, bv, o);
            int   oi = __shfl_xor_sync(0xffffffffu, bi, o);
            if (ov < bv || (ov == bv && oi < bi)) { bv = ov; bi = oi; }
        }
        if ((bi & 31) == lane) dv[(bi - base) >> 5] = 3.4e38f;
        if (lane == 0) { sv[w][k] = bv; si[w][k] = bi; }
    }
    __syncthreads();
    if (w == 0) {
        float cv[8]; int ci[8];
        #pragma unroll
        for (int j = 0; j < 8; j++) {
            int c = lane*8 + j;
            cv[j] = sv[c >> 5][c & 31];
            ci[j] = si[c >> 5][c & 31];
        }
        int* op = idxout + (size_t)row*KNB;
        for (int k = 0; k < KNB; k++) {
            float bv = 3.4e38f; int bi = 0x7fffffff; int bj = -1;
            #pragma unroll
            for (int j = 0; j < 8; j++) {
                if (cv[j] < bv || (cv[j] == bv && ci[j] < bi)) { bv = cv[j]; bi = ci[j]; bj = j; }
            }
            float rbv = bv; int rbi = bi;
            #pragma unroll
            for (int o = 16; o; o >>= 1) {
                float ov = __shfl_xor_sync(0xffffffffu, rbv, o);
                int   oi = __shfl_xor_sync(0xffffffffu, rbi, o);
                if (ov < rbv || (ov == rbv && oi < rbi)) { rbv = ov; rbi = oi; }
            }
            if (bj >= 0 && rbi == bi) cv[bj] = 3.4e38f;
            if (lane == 0) op[k] = rbi;
        }
    }
}

__global__ void edge_pass1_kernel(const float* __restrict__ An, const float* __restrict__ Bn_,
                                  const int* __restrict__ idx, float* __restrict__ pre,
                                  float* __restrict__ s1, float* __restrict__ s2,
                                  int Np, long pre_bs)
{
    int bn = blockIdx.x;
    int b = bn / Np, n = bn % Np;
    int t = threadIdx.x;
    size_t nb = (size_t)b*CF*Np;
    __shared__ int sidx[KNB];
    if (t < KNB) sidx[t] = idx[(size_t)bn*KNB + t];
    __syncthreads();
    float a  = An [nb + (size_t)n*CF + t];
    float bm = Bn_[nb + (size_t)n*CF + t];
    float diff = a - bm;
    const float* Br = Bn_ + nb;
    float s = 0.f, ss = 0.f, mx = -3.4e38f;
    #pragma unroll 4
    for (int k = 0; k < KNB; k++) {
        float v = diff + Br[(size_t)sidx[k]*CF + t];
        s += v; ss += v*v; mx = fmaxf(mx, v);
    }
    pre[(size_t)b*pre_bs + (size_t)t*Np + n] = mx;
    size_t ci = nb + (size_t)t*Np + n;
    s1[ci] = s; s2[ci] = ss;
}

__global__ void bn_stats_kernel(const float* __restrict__ x, float* __restrict__ mu,
                                float* __restrict__ rstd, long bstride, int Np, double invcount)
{
    int o = blockIdx.x, t = threadIdx.x;
    double s = 0.0, ss = 0.0;
    for (int b = 0; b < BB; b++) {
        const float* p = x + (long)b*bstride + (long)o*Np;
        for (int n = t; n < Np; n += 256) { double v = p[n]; s += v; ss += v*v; }
    }
    __shared__ double sh1[256], sh2[256];
    sh1[t] = s; sh2[t] = ss; __syncthreads();
    for (int st = 128; st; st >>= 1) {
        if (t < st) { sh1[t] += sh1[t+st]; sh2[t] += sh2[t+st]; }
        __syncthreads();
    }
    if (!t) {
        double m = sh1[0]*invcount;
        double var = sh2[0]*invcount - m*m;
        mu[o] = (float)m;
        rstd[o] = (float)(1.0/sqrt(var + 1e-5));
    }
}

__global__ void bn_stats2_kernel(const float* __restrict__ s1, const float* __restrict__ s2,
                                 float* __restrict__ mu, float* __restrict__ rstd,
                                 long bstride, int Np, double invcount)
{
    int o = blockIdx.x, t = threadIdx.x;
    double s = 0.0, ss = 0.0;
    for (int b = 0; b < BB; b++) {
        const float* p1 = s1 + (long)b*bstride + (long)o*Np;
        const float* p2 = s2 + (long)b*bstride + (long)o*Np;
        for (int n = t; n < Np; n += 256) { s += (double)p1[n]; ss += (double)p2[n]; }
    }
    __shared__ double sh1[256], sh2[256];
    sh1[t] = s; sh2[t] = ss; __syncthreads();
    for (int st = 128; st; st >>= 1) {
        if (t < st) { sh1[t] += sh1[t+st]; sh2[t] += sh2[t+st]; }
        __syncthreads();
    }
    if (!t) {
        double m = sh1[0]*invcount;
        double var = sh2[0]*invcount - m*m;
        mu[o] = (float)m;
        rstd[o] = (float)(1.0/sqrt(var + 1e-5));
    }
}

__global__ void bn_apply_kernel(const float* __restrict__ x, const float* __restrict__ res,
                                float* __restrict__ out, const float* __restrict__ mu,
                                const float* __restrict__ rstd, size_t total,
                                int Np, int Cch, long bstride)
{
    size_t i = (size_t)blockIdx.x*256 + threadIdx.x;
    if (i >= total) return;
    int n = (int)(i % Np); size_t tt = i / Np;
    int o = (int)(tt % Cch); int b = (int)(tt / Cch);
    size_t off = (size_t)b*bstride + (size_t)o*Np + n;
    float v = (x[off] - mu[o]) * rstd[o];
    v = v >= 0.f ? v : LRELU*v;
    out[off] = (res ? res[off] : 0.f) + v;
}

// fused qkv buffer [b, n, 384]: q at +0, k at +128, v at +256
__global__ void attn_kernel(const float* __restrict__ qkv, const int* __restrict__ idx,
                            float* __restrict__ out, int Np)
{
    int bn = blockIdx.x;
    int b = bn / Np, n = bn % Np;
    int t = threadIdx.x, w = t >> 5, lane = t & 31;
    size_t nb3 = (size_t)b*Np*384;
    size_t nb  = (size_t)b*CF*Np;
    __shared__ int   sidx[KNB];
    __shared__ float part[4][KNB];
    __shared__ float aw[KNB];
    if (t < KNB) sidx[t] = idx[(size_t)bn*KNB + t];
    __syncthreads();
    float qc = qkv[nb3 + (size_t)n*384 + t];
    const float* Kb = qkv + nb3 + 128;
    for (int k = 0; k < KNB; k++) {
        float v = qc * Kb[(size_t)sidx[k]*384 + t];
        #pragma unroll
        for (int o = 16; o; o >>= 1) v += __shfl_down_sync(0xffffffffu, v, o);
        if (lane == 0) part[w][k] = v;
    }
    __syncthreads();
    if (w == 0) {
        float l = (part[0][lane] + part[1][lane] + part[2][lane] + part[3][lane]) * ATTN_SCALE;
        float m = l;
        #pragma unroll
        for (int o = 16; o; o >>= 1) m = fmaxf(m, __shfl_xor_sync(0xffffffffu, m, o));
        float e = expf(l - m);
        float s = e;
        #pragma unroll
        for (int o = 16; o; o >>= 1) s += __shfl_xor_sync(0xffffffffu, s, o);
        aw[lane] = e / s;
    }
    __syncthreads();
    const float* Vb = qkv + nb3 + 256;
    float acc = 0.f;
    for (int k = 0; k < KNB; k++) acc += aw[k]*Vb[(size_t)sidx[k]*384 + t];
    out[nb + (size_t)t*Np + n] = acc;
}

__global__ void softmax_kernel(float* __restrict__ S, int M, float scale)
{
    __shared__ float sh[NPTS];
    __shared__ float red[256];
    size_t row = blockIdx.x;
    float* r = S + row*(size_t)M;
    int t = threadIdx.x;
    float mx = -3.4e38f;
    for (int i = t; i < M; i += 256) { float v = r[i]*scale; sh[i] = v; mx = fmaxf(mx, v); }
    red[t] = mx; __syncthreads();
    for (int s = 128; s; s >>= 1) { if (t < s) red[t] = fmaxf(red[t], red[t+s]); __syncthreads(); }
    mx = red[0]; __syncthreads();
    float sum = 0.f;
    for (int i = t; i < M; i += 256) { float e = expf(sh[i] - mx); sh[i] = e; sum += e; }
    red[t] = sum; __syncthreads();
    for (int s = 128; s; s >>= 1) { if (t < s) red[t] += red[t+s]; __syncthreads(); }
    float inv = 1.0f/red[0];
    for (int i = t; i < M; i += 256) r[i] = sh[i]*inv;
}

__global__ void colmean_kernel(const float* __restrict__ S, float* __restrict__ score, int R, int M)
{
    int b = blockIdx.y;
    int m = blockIdx.x*256 + threadIdx.x;
    if (m >= M) return;
    const float* p = S + (size_t)b*R*M + m;
    float s = 0.f;
    for (int n = 0; n < R; n++) s += p[(size_t)n*M];
    score[(size_t)b*M + m] = s / (float)R;
}

__global__ void topm_kernel(const float* __restrict__ score, int* __restrict__ sel)
{
    __shared__ float v[NPTS];
    __shared__ int   id[NPTS];
    int b = blockIdx.x, t = threadIdx.x;
    for (int i = t; i < NPTS; i += 1024) { v[i] = score[(size_t)b*NPTS + i]; id[i] = i; }
    __syncthreads();
    for (int k = 2; k <= NPTS; k <<= 1) {
        for (int j = k >> 1; j > 0; j >>= 1) {
            for (int i = t; i < NPTS; i += 1024) {
                int p = i ^ j;
                if (p > i) {
                    bool up = ((i & k) == 0);
                    float vi = v[i], vp = v[p]; int ii = id[i], ip = id[p];
                    bool inOrder = (vi > vp) || (vi == vp && ii < ip);
                    if (up ? !inOrder : inOrder) { v[i]=vp; v[p]=vi; id[i]=ip; id[p]=ii; }
                }
            }
            __syncthreads();
        }
    }
    for (int i = t; i < MSEL; i += 1024) sel[(size_t)b*MSEL + i] = id[i];
}

__global__ void gather_kernel(const float* __restrict__ x, const int* __restrict__ sel,
                              float* __restrict__ out, int Np, int Ms)
{
    size_t i = (size_t)blockIdx.x*256 + threadIdx.x;
    if (i >= (size_t)BB*CF*Ms) return;
    int j = (int)(i % Ms); size_t tt = i / Ms;
    int c = (int)(tt % CF); int b = (int)(tt / CF);
    out[i] = x[((size_t)b*CF + c)*Np + sel[(size_t)b*Ms + j]];
}

__global__ void add_kernel(const float* __restrict__ a, const float* __restrict__ b,
                           float* __restrict__ o, size_t total)
{
    size_t i = (size_t)blockIdx.x*256 + threadIdx.x;
    if (i < total) o[i] = a[i] + b[i];
}

__global__ void maxmean_kernel(const float* __restrict__ xh, float* __restrict__ g, int Np)
{
    __shared__ float rm[256], rs[256];
    int bo = blockIdx.x;
    int b = bo >> 10, o = bo & 1023;
    const float* p = xh + ((size_t)b*1024 + o)*Np;
    int t = threadIdx.x;
    float mx = -3.4e38f, s = 0.f;
    for (int n = t; n < Np; n += 256) { float v = p[n]; mx = fmaxf(mx, v); s += v; }
    rm[t] = mx; rs[t] = s; __syncthreads();
    for (int st = 128; st; st >>= 1) {
        if (t < st) { rm[t] = fmaxf(rm[t], rm[t+st]); rs[t] += rs[t+st]; }
        __syncthreads();
    }
    if (!t) { g[(size_t)b*2112 + o] = rm[0]; g[(size_t)b*2112 + 1024 + o] = rs[0]/(float)Np; }
}

__global__ void cid_kernel(const float* __restrict__ cat, const float* __restrict__ Wc1,
                           float* __restrict__ g)
{
    int o = threadIdx.x;
    float y[BB];
    for (int b = 0; b < BB; b++) {
        float s = 0.f;
        for (int c = 0; c < 16; c++) s += Wc1[o*16+c]*cat[b*16+c];
        y[b] = s;
    }
    float mu = 0.f;
    for (int b = 0; b < BB; b++) mu += y[b];
    mu *= (1.0f/BB);
    float var = 0.f;
    for (int b = 0; b < BB; b++) { float dd = y[b]-mu; var += dd*dd; }
    var *= (1.0f/BB);
    float rs = rsqrtf(var + 1e-5f);
    for (int b = 0; b < BB; b++) {
        float v = (y[b]-mu)*rs;
        g[(size_t)b*2112 + 2048 + o] = v >= 0.f ? v : LRELU*v;
    }
}

__global__ void bias_kernel(const float* __restrict__ W, const float* __restrict__ g,
                            float* __restrict__ bias)
{
    int gw = blockIdx.x*8 + (threadIdx.x >> 5);
    if (gw >= BB*1024) return;
    int lane = threadIdx.x & 31;
    int b = gw >> 10, o = gw & 1023;
    const float* wr = W + (size_t)o*2240;
    const float* gb = g + (size_t)b*2112;
    float s = 0.f;
    for (int c = lane; c < 2112; c += 32) s += wr[c]*gb[c];
    #pragma unroll
    for (int off = 16; off; off >>= 1) s += __shfl_down_sync(0xffffffffu, s, off);
    if (!lane) bias[(size_t)b*1024 + o] = s;
}

__global__ void addbias_kernel(float* __restrict__ xc, const float* __restrict__ bias)
{
    size_t i = (size_t)blockIdx.x*256 + threadIdx.x;
    if (i >= (size_t)BB*1024*NPTS) return;
    size_t tt = i / NPTS;
    int o = (int)(tt % 1024); int b = (int)(tt / 1024);
    xc[i] += bias[(size_t)b*1024 + o];
}

// ---------------- host orchestration ----------------
struct Bufs {
    float *big,*h,*hfull,*bq,*bk,*bv,*ba,*by,*f1,*s1,*s2,*hd,*hu,*xtmp,*xh,*xc,*xc2;
    float *sq,*score,*gv,*bias,*mu,*rstd;
    int *idx,*sel;
};

static void getbufs(Bufs& P)
{
    cudaGetSymbolAddress((void**)&P.big, g_big);
    cudaGetSymbolAddress((void**)&P.h, g_h);
    cudaGetSymbolAddress((void**)&P.hfull, g_hfull);
    cudaGetSymbolAddress((void**)&P.bq, g_bq);
    cudaGetSymbolAddress((void**)&P.bk, g_bk);
    cudaGetSymbolAddress((void**)&P.bv, g_bv);
    cudaGetSymbolAddress((void**)&P.ba, g_ba);
    cudaGetSymbolAddress((void**)&P.by, g_by);
    cudaGetSymbolAddress((void**)&P.f1, g_f1);
    cudaGetSymbolAddress((void**)&P.s1, g_s1);
    cudaGetSymbolAddress((void**)&P.s2, g_s2);
    cudaGetSymbolAddress((void**)&P.hd, g_hd);
    cudaGetSymbolAddress((void**)&P.hu, g_hu);
    cudaGetSymbolAddress((void**)&P.xtmp, g_xtmp);
    cudaGetSymbolAddress((void**)&P.xh, g_xh);
    cudaGetSymbolAddress((void**)&P.xc, g_xc);
    cudaGetSymbolAddress((void**)&P.xc2, g_xc2);
    cudaGetSymbolAddress((void**)&P.sq, g_sqn);
    cudaGetSymbolAddress((void**)&P.score, g_score);
    cudaGetSymbolAddress((void**)&P.gv, g_gv);
    cudaGetSymbolAddress((void**)&P.bias, g_bias);
    cudaGetSymbolAddress((void**)&P.mu, g_mu);
    cudaGetSymbolAddress((void**)&P.rstd, g_rstd);
    cudaGetSymbolAddress((void**)&P.idx, g_idx);
    cudaGetSymbolAddress((void**)&P.sel, g_sel);
}

static inline size_t cdiv(size_t a, size_t b) { return (a + b - 1)/b; }

static void run_bn(float* x, const float* res, float* out, int Cch, int Np, long bstride, Bufs& P)
{
    bn_stats_kernel<<<Cch, 256>>>(x, P.mu, P.rstd, bstride, Np, 1.0/((double)BB*Np));
    size_t total = (size_t)BB*Cch*Np;
    bn_apply_kernel<<<(unsigned)cdiv(total,256), 256>>>(x, res, out, P.mu, P.rstd, total, Np, Cch, bstride);
}

static void run_knn(const float* xin, long xbs, int cin, int Np, Bufs& P)
{
    dim3 gs((Np+255)/256, BB);
    sqnorm_kernel<<<gs, 256>>>(xin, P.sq, cin, Np, xbs);
    int nt = Np >> 7;
    dim3 grid(nt*(nt+1)/2, 1, BB);
    syrk_kernel<<<grid, 256>>>(xin, P.big, Np, cin, xbs);
    knn_topk_kernel<<<BB*Np, 256>>>(P.big, P.sq, P.idx, Np);
}

static void run_edge(const float* xin, long xbs, int cin, const float* W, int rowlen,
                     float* outslice, long out_bs, Bufs& P)
{
    run_knn(xin, xbs, cin, NPTS, P);
    gemmWn(W,       CF, cin, rowlen, xin, xbs, NPTS, P.bq);
    gemmWn(W + cin, CF, cin, rowlen, xin, xbs, NPTS, P.bk);
    edge_pass1_kernel<<<BB*NPTS, 128>>>(P.bq, P.bk, P.idx, outslice, P.s1, P.s2, NPTS, out_bs);
    size_t total = (size_t)BB*CF*NPTS;
    bn_stats2_kernel<<<CF, 256>>>(P.s1, P.s2, P.mu, P.rstd, (long)CF*NPTS, NPTS,
                                  1.0/((double)BB*NPTS*KNB));
    bn_apply_kernel<<<(unsigned)cdiv(total,256), 256>>>(outslice, nullptr, outslice, P.mu, P.rstd,
                                                        total, NPTS, CF, out_bs);
}

static void run_n2p(const float* xin, long xbs, int cin, int Np,
                    const float* Wq, const float* Wk, const float* Wv, const float* Wo,
                    const float* Wf1, const float* Wf2, float* outp, Bufs& P)
{
    run_knn(xin, xbs, cin, Np, P);
    long fbs = (long)CF*Np;
    // merge Wq/Wk/Wv into one [384 x cin] weight (scratch in s1), one GEMM -> f1 [b,n,384]
    size_t wsz = (size_t)CF*cin*sizeof(float);
    cudaMemcpyAsync(P.s1,            Wq, wsz, cudaMemcpyDeviceToDevice);
    cudaMemcpyAsync(P.s1 + CF*cin,   Wk, wsz, cudaMemcpyDeviceToDevice);
    cudaMemcpyAsync(P.s1 + 2*CF*cin, Wv, wsz, cudaMemcpyDeviceToDevice);
    gemmWn(P.s1, 3*CF, cin, cin, xin, xbs, Np, P.f1);
    attn_kernel<<<BB*Np, 128>>>(P.f1, P.idx, P.ba, Np);
    gemmW(Wo, CF, CF, CF, P.ba, fbs, Np, P.by, fbs);
    run_bn(P.by, nullptr, P.by, CF, Np, fbs, P);
    long f1bs = 512L*Np;
    gemmW(Wf1, 512, CF, CF, P.by, fbs, Np, P.f1, f1bs);
    run_bn(P.f1, nullptr, P.f1, 512, Np, f1bs, P);
    gemmW(Wf2, CF, 512, 512, P.f1, f1bs, Np, P.bq, fbs);
    bn_stats_kernel<<<CF, 256>>>(P.bq, P.mu, P.rstd, fbs, Np, 1.0/((double)BB*Np));
    size_t total = (size_t)BB*CF*Np;
    bn_apply_kernel<<<(unsigned)cdiv(total,256), 256>>>(P.bq, P.by, outp, P.mu, P.rstd,
                                                        total, Np, CF, fbs);
}

extern "C" void kernel_launch(void* const* d_in, const int* in_sizes, int n_in,
                              void* d_out, int out_size)
{
    const float* x    = (const float*)d_in[0];
    const float* cat  = (const float*)d_in[1];
    const float* We0  = (const float*)d_in[2];
    const float* We1  = (const float*)d_in[3];
    const float *Wq[3], *Wk[3], *Wv[3], *Wo[3], *Wf1[3], *Wf2[3];
    for (int l = 0; l < 3; l++) {
        Wq[l]  = (const float*)d_in[4 + 6*l];
        Wk[l]  = (const float*)d_in[5 + 6*l];
        Wv[l]  = (const float*)d_in[6 + 6*l];
        Wo[l]  = (const float*)d_in[7 + 6*l];
        Wf1[l] = (const float*)d_in[8 + 6*l];
        Wf2[l] = (const float*)d_in[9 + 6*l];
    }
    const float* Wdq = (const float*)d_in[22];
    const float* Wdk = (const float*)d_in[23];
    const float* Wuq = (const float*)d_in[24];
    const float* Wuk = (const float*)d_in[25];
    const float* Wuv = (const float*)d_in[26];
    const float* Wc  = (const float*)d_in[27];
    const float* Wc1 = (const float*)d_in[28];
    const float* Wc2 = (const float*)d_in[29];
    const float* Wc3 = (const float*)d_in[30];
    const float* Wc4 = (const float*)d_in[31];

    Bufs P; getbufs(P);
    const long HBS = 256L*NPTS;
    const long FBS = (long)CF*NPTS;

    run_edge(x,   3L*NPTS, 3,   We0, 6,   P.h,             HBS, P);
    run_edge(P.h, HBS,     128, We1, 256, P.h + 128L*NPTS, HBS, P);

    run_n2p(P.h, HBS, 256, NPTS, Wq[0], Wk[0], Wv[0], Wo[0], Wf1[0], Wf2[0], P.hfull, P);

    // down_global
    gemmW(Wdq, CF, CF, CF, P.hfull, FBS, NPTS, P.bq, FBS);
    gemmW(Wdk, CF, CF, CF, P.hfull, FBS, NPTS, P.bk, FBS);
    gemmTN(P.bq, FBS, NPTS, P.bk, FBS, NPTS, CF, P.big);
    softmax_kernel<<<BB*NPTS, 256>>>(P.big, NPTS, ATTN_SCALE);
    {
        dim3 gs((NPTS+255)/256, BB);
        colmean_kernel<<<gs, 256>>>(P.big, P.score, NPTS, NPTS);
    }
    topm_kernel<<<BB, 1024>>>(P.score, P.sel);
    {
        size_t total = (size_t)BB*CF*MSEL;
        gather_kernel<<<(unsigned)cdiv(total,256), 256>>>(P.hfull, P.sel, P.hd, NPTS, MSEL);
    }

    run_n2p(P.hd, (long)CF*MSEL, CF, MSEL, Wq[1], Wk[1], Wv[1], Wo[1], Wf1[1], Wf2[1], P.hd, P);

    // up_cross
    gemmW(Wuq, CF, CF, CF, P.hfull, FBS, NPTS, P.bq, FBS);
    gemmW(Wuk, CF, CF, CF, P.hd, (long)CF*MSEL, MSEL, P.bk, (long)CF*MSEL);
    gemmW(Wuv, CF, CF, CF, P.hd, (long)CF*MSEL, MSEL, P.bv, (long)CF*MSEL);
    gemmTN(P.bq, FBS, NPTS, P.bk, (long)CF*MSEL, MSEL, CF, P.big);
    softmax_kernel<<<BB*NPTS, 256>>>(P.big, MSEL, ATTN_SCALE);
    gemm_launch(P.bv, P.big, P.hu, BB, CF, NPTS, MSEL,
                (long)CF*MSEL, MSEL, 1,
                (long)NPTS*MSEL, 1, MSEL,
                FBS, NPTS);
    {
        size_t total = (size_t)BB*CF*NPTS;
        add_kernel<<<(unsigned)cdiv(total,256), 256>>>(P.hfull, P.hu, P.hu, total);
    }

    run_n2p(P.hu, FBS, CF, NPTS, Wq[2], Wk[2], Wv[2], Wo[2], Wf1[2], Wf2[2], P.xtmp, P);

    gemmW(Wc, 1024, CF, CF, P.xtmp, FBS, NPTS, P.xh, 1024L*NPTS);
    run_bn(P.xh, nullptr, P.xh, 1024, NPTS, 1024L*NPTS, P);

    maxmean_kernel<<<BB*1024, 256>>>(P.xh, P.gv, NPTS);
    cid_kernel<<<1, 64>>>(cat, Wc1, P.gv);
    bias_kernel<<<1024, 256>>>(Wc2, P.gv, P.bias);

    gemmW(Wc2 + 2112, 1024, CF, 2240, P.xtmp, FBS, NPTS, P.xc, 1024L*NPTS);
    {
        size_t total = (size_t)BB*1024*NPTS;
        addbias_kernel<<<(unsigned)cdiv(total,256), 256>>>(P.xc, P.bias);
    }
    run_bn(P.xc, nullptr, P.xc, 1024, NPTS, 1024L*NPTS, P);

    gemmW(Wc3, 256, 1024, 1024, P.xc, 1024L*NPTS, NPTS, P.xc2, 256L*NPTS);
    run_bn(P.xc2, nullptr, P.xc2, 256, NPTS, 256L*NPTS, P);

    gemmW(Wc4, 50, 256, 256, P.xc2, 256L*NPTS, NPTS, (float*)d_out, 50L*NPTS);

    (void)in_sizes; (void)n_in; (void)out_size;
}

// round 14
// speedup vs baseline: 1.4592x; 1.0070x over previous
#include <cuda_runtime.h>
#include <math.h>

#define BB 8
#define NPTS 2048
#define KNB 32
#define MSEL 1024
#define CF 128
#define LRELU 0.2f
#define ATTN_SCALE 0.088388347648318447f

// ---------------- static device scratch ----------------
static __device__ float g_big[(size_t)BB*NPTS*NPTS];
static __device__ float g_h[(size_t)BB*256*NPTS];
static __device__ float g_hfull[(size_t)BB*CF*NPTS];
static __device__ float g_bq[(size_t)BB*CF*NPTS];
static __device__ float g_bk[(size_t)BB*CF*NPTS];
static __device__ float g_bv[(size_t)BB*CF*NPTS];
static __device__ float g_ba[(size_t)BB*CF*NPTS];
static __device__ float g_by[(size_t)BB*CF*NPTS];
static __device__ float g_f1[(size_t)BB*512*NPTS];
static __device__ float g_s1[(size_t)BB*CF*NPTS];
static __device__ float g_s2[(size_t)BB*CF*NPTS];
static __device__ float g_hd[(size_t)BB*CF*MSEL];
static __device__ float g_hu[(size_t)BB*CF*NPTS];
static __device__ float g_xtmp[(size_t)BB*CF*NPTS];
static __device__ float g_xh[(size_t)BB*1024*NPTS];
static __device__ float g_xc[(size_t)BB*1024*NPTS];
static __device__ float g_xc2[(size_t)BB*256*NPTS];
static __device__ float g_sqn[(size_t)BB*NPTS];
static __device__ float g_score[(size_t)BB*NPTS];
static __device__ float g_gv[(size_t)BB*2112];
static __device__ float g_bias[(size_t)BB*1024];
static __device__ float g_mu[1024];
static __device__ float g_rstd[1024];
static __device__ int   g_idx[(size_t)BB*NPTS*KNB];
static __device__ int   g_sel[(size_t)BB*MSEL];

// ---------------- SYRK: O = X^T X (symmetric, bitwise), upper triangle + mirror ----
__global__ void __launch_bounds__(256, 2)
syrk_kernel(const float* __restrict__ X, float* __restrict__ O,
            int Np, int Kd, long xbs)
{
    __shared__ float As[2][8][132];
    __shared__ float Bs[2][8][132];
    int bz = blockIdx.z;
    const float* Xb = X + (long)bz*xbs;
    float* Ob = O + (size_t)bz*Np*Np;
    int nt = Np >> 7;
    int t = blockIdx.x, bi = 0, rem = nt;
    while (t >= rem) { t -= rem; bi++; rem--; }
    int bj = bi + t;
    int i0 = bi << 7, j0 = bj << 7;

    int tid = threadIdx.x;
    int tx = tid & 15, ty = tid >> 4;
    int lk = tid >> 5, lv = (tid & 31) * 4;

    float ra[4], rb[4];
    auto fetch = [&](int k0) {
        if (k0 + lk < Kd) {
            float4 a = *reinterpret_cast<const float4*>(&Xb[(long)(k0+lk)*Np + (i0+lv)]);
            ra[0]=a.x; ra[1]=a.y; ra[2]=a.z; ra[3]=a.w;
            float4 b = *reinterpret_cast<const float4*>(&Xb[(long)(k0+lk)*Np + (j0+lv)]);
            rb[0]=b.x; rb[1]=b.y; rb[2]=b.z; rb[3]=b.w;
        } else {
            ra[0]=ra[1]=ra[2]=ra[3]=0.f;
            rb[0]=rb[1]=rb[2]=rb[3]=0.f;
        }
    };
    auto commit = [&](int s) {
        *reinterpret_cast<float4*>(&As[s][lk][lv]) = make_float4(ra[0],ra[1],ra[2],ra[3]);
        *reinterpret_cast<float4*>(&Bs[s][lk][lv]) = make_float4(rb[0],rb[1],rb[2],rb[3]);
    };

    float acc[8][8] = {};
    fetch(0); commit(0);
    __syncthreads();
    int s = 0;
    for (int k0 = 0; k0 < Kd; k0 += 8) {
        int kn = k0 + 8;
        bool more = (kn < Kd);
        if (more) fetch(kn);
        #pragma unroll
        for (int kk = 0; kk < 8; kk++) {
            float4 a0 = *(const float4*)&As[s][kk][ty*8];
            float4 a1 = *(const float4*)&As[s][kk][ty*8+4];
            float4 b0 = *(const float4*)&Bs[s][kk][tx*8];
            float4 b1 = *(const float4*)&Bs[s][kk][tx*8+4];
            float av[8] = {a0.x,a0.y,a0.z,a0.w,a1.x,a1.y,a1.z,a1.w};
            float bw[8] = {b0.x,b0.y,b0.z,b0.w,b1.x,b1.y,b1.z,b1.w};
            #pragma unroll
            for (int u = 0; u < 8; u++)
                #pragma unroll
                for (int v = 0; v < 8; v++) acc[u][v] += av[u]*bw[v];
        }
        if (more) commit(s^1);
        __syncthreads();
        s ^= 1;
    }
    #pragma unroll
    for (int u = 0; u < 8; u++) {
        int i = i0 + ty*8 + u;
        *reinterpret_cast<float4*>(&Ob[(size_t)i*Np + j0 + tx*8]) =
            make_float4(acc[u][0], acc[u][1], acc[u][2], acc[u][3]);
        *reinterpret_cast<float4*>(&Ob[(size_t)i*Np + j0 + tx*8 + 4]) =
            make_float4(acc[u][4], acc[u][5], acc[u][6], acc[u][7]);
    }
    if (bi != bj) {
        float* Ms = &As[0][0][0];
        for (int vv = 0; vv < 8; vv++) {
            __syncthreads();
            #pragma unroll
            for (int u = 0; u < 8; u++) Ms[tx*132 + ty*8 + u] = acc[u][vv];
            __syncthreads();
            int jl = tid >> 4;
            int ic = (tid & 15) * 8;
            int jg = j0 + jl*8 + vv;
            float4 w0 = *reinterpret_cast<float4*>(&Ms[jl*132 + ic]);
            float4 w1 = *reinterpret_cast<float4*>(&Ms[jl*132 + ic + 4]);
            *reinterpret_cast<float4*>(&Ob[(size_t)jg*Np + i0 + ic]) = w0;
            *reinterpret_cast<float4*>(&Ob[(size_t)jg*Np + i0 + ic + 4]) = w1;
        }
    }
}

// ---------------- templated 128x128 GEMM (modes compile-time) ----------------
// AM/BM: 0 = inner-contiguous full-tile row loads; 1 = k-contiguous + smem transpose.
template<int AM, int BM>
__global__ void __launch_bounds__(256, 2)
gemm128_t(const float* __restrict__ A, const float* __restrict__ Bm,
          float* __restrict__ O, int I, int J, int Kd,
          long a_b, long a_i, long a_k,
          long b_b, long b_k, long b_j,
          long o_b, long o_i)
{
    __shared__ float As[2][8][132];
    __shared__ float Bs[2][8][132];
    int bz = blockIdx.z;
    const float* Ab = A + (long)bz*a_b;
    const float* Bb = Bm + (long)bz*b_b;
    int i0 = blockIdx.y*128, j0 = blockIdx.x*128;
    int tid = threadIdx.x;
    int tx = tid & 15, ty = tid >> 4;
    int lk  = tid >> 5;
    int lv  = (tid & 31) * 4;
    int li  = tid >> 1;
    int lkv = (tid & 1) * 4;

    float ra[4], rb[4];

    auto fetchA = [&](int k0) {
        if constexpr (AM == 0) {
            if (k0 + lk < Kd) {
                const float4 v = *reinterpret_cast<const float4*>(&Ab[(long)(k0+lk)*a_k + (i0+lv)]);
                ra[0]=v.x; ra[1]=v.y; ra[2]=v.z; ra[3]=v.w;
            } else { ra[0]=ra[1]=ra[2]=ra[3]=0.f; }
        } else {
            long base = (long)(i0+li)*a_i + k0 + lkv;
            bool iok = (i0+li) < I;
            if (iok && (k0+lkv+3) < Kd) {
                const float4 v = *reinterpret_cast<const float4*>(&Ab[base]);
                ra[0]=v.x; ra[1]=v.y; ra[2]=v.z; ra[3]=v.w;
            } else {
                #pragma unroll
                for (int q = 0; q < 4; q++)
                    ra[q] = (iok && (k0+lkv+q) < Kd) ? Ab[base+q] : 0.f;
            }
        }
    };
    auto commitA = [&](int s) {
        if constexpr (AM == 0) {
            *reinterpret_cast<float4*>(&As[s][lk][lv]) = make_float4(ra[0],ra[1],ra[2],ra[3]);
        } else {
            #pragma unroll
            for (int q = 0; q < 4; q++) As[s][lkv+q][li] = ra[q];
        }
    };
    auto fetchB = [&](int k0) {
        if constexpr (BM == 0) {
            if (k0 + lk < Kd) {
                const float4 v = *reinterpret_cast<const float4*>(&Bb[(long)(k0+lk)*b_k + (j0+lv)]);
                rb[0]=v.x; rb[1]=v.y; rb[2]=v.z; rb[3]=v.w;
            } else { rb[0]=rb[1]=rb[2]=rb[3]=0.f; }
        } else {
            long base = (long)(j0+li)*b_j + k0 + lkv;
            bool jok = (j0+li) < J;
            if (jok && (k0+lkv+3) < Kd) {
                const float4 v = *reinterpret_cast<const float4*>(&Bb[base]);
                rb[0]=v.x; rb[1]=v.y; rb[2]=v.z; rb[3]=v.w;
            } else {
                #pragma unroll
                for (int q = 0; q < 4; q++)
                    rb[q] = (jok && (k0+lkv+q) < Kd) ? Bb[base+q] : 0.f;
            }
        }
    };
    auto commitB = [&](int s) {
        if constexpr (BM == 0) {
            *reinterpret_cast<float4*>(&Bs[s][lk][lv]) = make_float4(rb[0],rb[1],rb[2],rb[3]);
        } else {
            #pragma unroll
            for (int q = 0; q < 4; q++) Bs[s][lkv+q][li] = rb[q];
        }
    };

    float acc[8][8] = {};
    fetchA(0); fetchB(0);
    commitA(0); commitB(0);
    __syncthreads();
    int s = 0;
    for (int k0 = 0; k0 < Kd; k0 += 8) {
        int kn = k0 + 8;
        bool more = (kn < Kd);
        if (more) { fetchA(kn); fetchB(kn); }
        #pragma unroll
        for (int kk = 0; kk < 8; kk++) {
            float4 a0 = *(const float4*)&As[s][kk][ty*8];
            float4 a1 = *(const float4*)&As[s][kk][ty*8+4];
            float4 b0 = *(const float4*)&Bs[s][kk][tx*8];
            float4 b1 = *(const float4*)&Bs[s][kk][tx*8+4];
            float av[8] = {a0.x,a0.y,a0.z,a0.w,a1.x,a1.y,a1.z,a1.w};
            float bw[8] = {b0.x,b0.y,b0.z,b0.w,b1.x,b1.y,b1.z,b1.w};
            #pragma unroll
            for (int u = 0; u < 8; u++)
                #pragma unroll
                for (int v = 0; v < 8; v++) acc[u][v] += av[u]*bw[v];
        }
        if (more) { commitA(s^1); commitB(s^1); }
        __syncthreads();
        s ^= 1;
    }
    #pragma unroll
    for (int u = 0; u < 8; u++) {
        int i = i0 + ty*8 + u;
        if (i >= I) continue;
        #pragma unroll
        for (int v = 0; v < 8; v++) {
            int j = j0 + tx*8 + v;
            if (j < J) O[(long)bz*o_b + (long)i*o_i + j] = acc[u][v];
        }
    }
}

// 64x64 tile, 4x4 microtile (small grids, odd strides)
__global__ void __launch_bounds__(256)
gemm_kernel64(const float* __restrict__ A, const float* __restrict__ Bm,
              float* __restrict__ O, int I, int J, int Kd,
              long a_b, long a_i, long a_k,
              long b_b, long b_k, long b_j,
              long o_b, long o_i)
{
    __shared__ float As[16*65];
    __shared__ float Bs[16*65];
    int bz = blockIdx.z;
    const float* Ab = A + (long)bz*a_b;
    const float* Bb = Bm + (long)bz*b_b;
    int i0 = blockIdx.y*64, j0 = blockIdx.x*64;
    int tid = threadIdx.x;
    int tx = tid & 15, ty = tid >> 4;
    float acc[4][4] = {};
    for (int k0 = 0; k0 < Kd; k0 += 16) {
        #pragma unroll
        for (int r = 0; r < 4; r++) {
            int e = tid + r*256;
            int kk, ii;
            if (a_k == 1) { ii = e >> 4; kk = e & 15; } else { kk = e >> 6; ii = e & 63; }
            float v = 0.f;
            if (i0+ii < I && k0+kk < Kd) v = Ab[(long)(i0+ii)*a_i + (long)(k0+kk)*a_k];
            As[kk*65+ii] = v;
        }
        #pragma unroll
        for (int r = 0; r < 4; r++) {
            int e = tid + r*256;
            int kk, jj;
            if (b_j == 1) { kk = e >> 6; jj = e & 63; } else { jj = e >> 4; kk = e & 15; }
            float v = 0.f;
            if (j0+jj < J && k0+kk < Kd) v = Bb[(long)(k0+kk)*b_k + (long)(j0+jj)*b_j];
            Bs[kk*65+jj] = v;
        }
        __syncthreads();
        #pragma unroll
        for (int kk = 0; kk < 16; kk++) {
            float av[4], bv[4];
            #pragma unroll
            for (int u = 0; u < 4; u++) av[u] = As[kk*65 + ty*4 + u];
            #pragma unroll
            for (int v = 0; v < 4; v++) bv[v] = Bs[kk*65 + tx*4 + v];
            #pragma unroll
            for (int u = 0; u < 4; u++)
                #pragma unroll
                for (int v = 0; v < 4; v++) acc[u][v] += av[u]*bv[v];
        }
        __syncthreads();
    }
    #pragma unroll
    for (int u = 0; u < 4; u++) {
        int i = i0 + ty*4 + u;
        if (i >= I) continue;
        #pragma unroll
        for (int v = 0; v < 4; v++) {
            int j = j0 + tx*4 + v;
            if (j < J) O[(long)bz*o_b + (long)i*o_i + j] = acc[u][v];
        }
    }
}

static void gemm_launch(const float* A, const float* B, float* O,
                        int Bn, int I, int J, int Kd,
                        long a_b, long a_i, long a_k,
                        long b_b, long b_k, long b_j,
                        long o_b, long o_i)
{
    long ctas128 = (long)((J+127)/128)*((I+127)/128)*Bn;
    int am = ((a_k != 1) && (a_i == 1) && ((a_k & 3) == 0) && (I % 128 == 0)) ? 0
           : ((a_k == 1) && ((a_i & 3) == 0)) ? 1 : 2;
    int bm = ((b_j == 1) && ((b_k & 3) == 0) && (J % 128 == 0)) ? 0
           : ((b_k == 1) && ((b_j & 3) == 0)) ? 1 : 2;
    if (ctas128 >= 224 && am < 2 && bm < 2) {
        dim3 grid((J+127)/128, (I+127)/128, Bn);
        switch (am*2 + bm) {
            case 0: gemm128_t<0,0><<<grid, 256>>>(A,B,O,I,J,Kd,a_b,a_i,a_k,b_b,b_k,b_j,o_b,o_i); break;
            case 1: gemm128_t<0,1><<<grid, 256>>>(A,B,O,I,J,Kd,a_b,a_i,a_k,b_b,b_k,b_j,o_b,o_i); break;
            case 2: gemm128_t<1,0><<<grid, 256>>>(A,B,O,I,J,Kd,a_b,a_i,a_k,b_b,b_k,b_j,o_b,o_i); break;
            default: gemm128_t<1,1><<<grid, 256>>>(A,B,O,I,J,Kd,a_b,a_i,a_k,b_b,b_k,b_j,o_b,o_i); break;
        }
    } else {
        dim3 grid((J+63)/64, (I+63)/64, Bn);
        gemm_kernel64<<<grid, 256>>>(A,B,O,I,J,Kd,a_b,a_i,a_k,b_b,b_k,b_j,o_b,o_i);
    }
}
// c-major output: O[b, o, n]
static void gemmW(const float* W, int Oc, int Kd, int rowlen,
                  const float* X, long xbs, int Np, float* O, long obs)
{
    gemm_launch(W, X, O, BB, Oc, Np, Kd, 0, rowlen, 1, xbs, Np, 1, obs, Np);
}
// n-major output: O[b, n, o]
static void gemmWn(const float* W, int Oc, int Kd, int rowlen,
                   const float* X, long xbs, int Np, float* O)
{
    gemm_launch(X, W, O, BB, Np, Oc, Kd, xbs, 1, Np, 0, 1, rowlen, (long)Oc*Np, Oc);
}
static void gemmTN(const float* X, long xbs, int Np,
                   const float* Y, long ybs, int Mp, int Cin, float* S)
{
    gemm_launch(X, Y, S, BB, Np, Mp, Cin, xbs, 1, Np, ybs, Mp, 1, (long)Np*Mp, Mp);
}

// ---------------- helper kernels ----------------
__global__ void sqnorm_kernel(const float* __restrict__ x, float* __restrict__ sq,
                              int Cin, int Np, long bstride)
{
    int b = blockIdx.y;
    int n = blockIdx.x*256 + threadIdx.x;
    if (n >= Np) return;
    const float* p = x + (long)b*bstride + n;
    float s = 0.f;
    for (int c = 0; c < Cin; c++) { float v = p[(long)c*Np]; s += v*v; }
    sq[(long)b*Np + n] = s;
}

__global__ void knn_topk_kernel(const float* __restrict__ inner, const float* __restrict__ sq,
                                int* __restrict__ idxout, int Np)
{
    __shared__ float sv[8][32];
    __shared__ int   si[8][32];
    int row = blockIdx.x;
    int b = row / Np, n = row % Np;
    int t = threadIdx.x, w = t >> 5, lane = t & 31;
    int chunk = Np >> 3;
    int per = chunk >> 5;
    const float* ir = inner + ((size_t)b*Np + n)*Np;
    const float* sqb = sq + (size_t)b*Np;
    float sn = sqb[n];
    int base = w*chunk;
    float dv[8];
    #pragma unroll
    for (int j = 0; j < 8; j++) {
        if (j < per) {
            int m = base + j*32 + lane;
            dv[j] = sn - 2.0f*ir[m] + sqb[m];
        } else dv[j] = 3.4e38f;
    }
    for (int k = 0; k < KNB; k++) {
        float bv = 3.4e38f; int bj = 0;
        #pragma unroll
        for (int j = 0; j < 8; j++) if (dv[j] < bv) { bv = dv[j]; bj = j; }
        int bi = base + bj*32 + lane;
        #pragma unroll
        for (int o = 16; o; o >>= 1) {
            float ov = __shfl_xor_sync(0xffffffffu, bv, o);
            int   oi = __shfl_xor_sync(0xffffffffu, bi, o);
            if (ov < bv || (ov == bv && oi < bi)) { bv = ov; bi = oi; }
        }
        if ((bi & 31) == lane) dv[(bi - base) >> 5] = 3.4e38f;
        if (lane == 0) { sv[w][k] = bv; si[w][k] = bi; }
    }
    __syncthreads();
    if (w == 0) {
        float cv[8]; int ci[8];
        #pragma unroll
        for (int j = 0; j < 8; j++) {
            int c = lane*8 + j;
            cv[j] = sv[c >> 5][c & 31];
            ci[j] = si[c >> 5][c & 31];
        }
        int* op = idxout + (size_t)row*KNB;
        for (int k = 0; k < KNB; k++) {
            float bv = 3.4e38f; int bi = 0x7fffffff; int bj = -1;
            #pragma unroll
            for (int j = 0; j < 8; j++) {
                if (cv[j] < bv || (cv[j] == bv && ci[j] < bi)) { bv = cv[j]; bi = ci[j]; bj = j; }
            }
            float rbv = bv; int rbi = bi;
            #pragma unroll
            for (int o = 16; o; o >>= 1) {
                float ov = __shfl_xor_sync(0xffffffffu, rbv, o);
                int   oi = __shfl_xor_sync(0xffffffffu, rbi, o);
                if (ov < rbv || (ov == rbv && oi < rbi)) { rbv = ov; rbi = oi; }
            }
            if (bj >= 0 && rbi == bi) cv[bj] = 3.4e38f;
            if (lane == 0) op[k] = rbi;
        }
    }
}

__global__ void edge_pass1_kernel(const float* __restrict__ An, const float* __restrict__ Bn_,
                                  const int* __restrict__ idx, float* __restrict__ pre,
                                  float* __restrict__ s1, float* __restrict__ s2,
                                  int Np, long pre_bs)
{
    int bn = blockIdx.x;
    int b = bn / Np, n = bn % Np;
    int t = threadIdx.x;
    size_t nb = (size_t)b*CF*Np;
    __shared__ int sidx[KNB];
    if (t < KNB) sidx[t] = idx[(size_t)bn*KNB + t];
    __syncthreads();
    float a  = An [nb + (size_t)n*CF + t];
    float bm = Bn_[nb + (size_t)n*CF + t];
    float diff = a - bm;
    const float* Br = Bn_ + nb;
    float s = 0.f, ss = 0.f, mx = -3.4e38f;
    #pragma unroll 4
    for (int k = 0; k < KNB; k++) {
        float v = diff + Br[(size_t)sidx[k]*CF + t];
        s += v; ss += v*v; mx = fmaxf(mx, v);
    }
    pre[(size_t)b*pre_bs + (size_t)t*Np + n] = mx;
    size_t ci = nb + (size_t)t*Np + n;
    s1[ci] = s; s2[ci] = ss;
}

__global__ void bn_stats_kernel(const float* __restrict__ x, float* __restrict__ mu,
                                float* __restrict__ rstd, long bstride, int Np, double invcount)
{
    int o = blockIdx.x, t = threadIdx.x;
    double s = 0.0, ss = 0.0;
    for (int b = 0; b < BB; b++) {
        const float* p = x + (long)b*bstride + (long)o*Np;
        for (int n = t; n < Np; n += 256) { double v = p[n]; s += v; ss += v*v; }
    }
    __shared__ double sh1[256], sh2[256];
    sh1[t] = s; sh2[t] = ss; __syncthreads();
    for (int st = 128; st; st >>= 1) {
        if (t < st) { sh1[t] += sh1[t+st]; sh2[t] += sh2[t+st]; }
        __syncthreads();
    }
    if (!t) {
        double m = sh1[0]*invcount;
        double var = sh2[0]*invcount - m*m;
        mu[o] = (float)m;
        rstd[o] = (float)(1.0/sqrt(var + 1e-5));
    }
}

__global__ void bn_stats2_kernel(const float* __restrict__ s1, const float* __restrict__ s2,
                                 float* __restrict__ mu, float* __restrict__ rstd,
                                 long bstride, int Np, double invcount)
{
    int o = blockIdx.x, t = threadIdx.x;
    double s = 0.0, ss = 0.0;
    for (int b = 0; b < BB; b++) {
        const float* p1 = s1 + (long)b*bstride + (long)o*Np;
        const float* p2 = s2 + (long)b*bstride + (long)o*Np;
        for (int n = t; n < Np; n += 256) { s += (double)p1[n]; ss += (double)p2[n]; }
    }
    __shared__ double sh1[256], sh2[256];
    sh1[t] = s; sh2[t] = ss; __syncthreads();
    for (int st = 128; st; st >>= 1) {
        if (t < st) { sh1[t] += sh1[t+st]; sh2[t] += sh2[t+st]; }
        __syncthreads();
    }
    if (!t) {
        double m = sh1[0]*invcount;
        double var = sh2[0]*invcount - m*m;
        mu[o] = (float)m;
        rstd[o] = (float)(1.0/sqrt(var + 1e-5));
    }
}

__global__ void bn_apply_kernel(const float* __restrict__ x, const float* __restrict__ res,
                                float* __restrict__ out, const float* __restrict__ mu,
                                const float* __restrict__ rstd, size_t total,
                                int Np, int Cch, long bstride)
{
    size_t i = (size_t)blockIdx.x*256 + threadIdx.x;
    if (i >= total) return;
    int n = (int)(i % Np); size_t tt = i / Np;
    int o = (int)(tt % Cch); int b = (int)(tt / Cch);
    size_t off = (size_t)b*bstride + (size_t)o*Np + n;
    float v = (x[off] - mu[o]) * rstd[o];
    v = v >= 0.f ? v : LRELU*v;
    out[off] = (res ? res[off] : 0.f) + v;
}

// fused qkv buffer [b, n, 384]: q at +0, k at +128, v at +256
__global__ void attn_kernel(const float* __restrict__ qkv, const int* __restrict__ idx,
                            float* __restrict__ out, int Np)
{
    int bn = blockIdx.x;
    int b = bn / Np, n = bn % Np;
    int t = threadIdx.x, w = t >> 5, lane = t & 31;
    size_t nb3 = (size_t)b*Np*384;
    size_t nb  = (size_t)b*CF*Np;
    __shared__ int   sidx[KNB];
    __shared__ float part[4][KNB];
    __shared__ float aw[KNB];
    if (t < KNB) sidx[t] = idx[(size_t)bn*KNB + t];
    __syncthreads();
    float qc = qkv[nb3 + (size_t)n*384 + t];
    const float* Kb = qkv + nb3 + 128;
    for (int k = 0; k < KNB; k++) {
        float v = qc * Kb[(size_t)sidx[k]*384 + t];
        #pragma unroll
        for (int o = 16; o; o >>= 1) v += __shfl_down_sync(0xffffffffu, v, o);
        if (lane == 0) part[w][k] = v;
    }
    __syncthreads();
    if (w == 0) {
        float l = (part[0][lane] + part[1][lane] + part[2][lane] + part[3][lane]) * ATTN_SCALE;
        float m = l;
        #pragma unroll
        for (int o = 16; o; o >>= 1) m = fmaxf(m, __shfl_xor_sync(0xffffffffu, m, o));
        float e = expf(l - m);
        float s = e;
        #pragma unroll
        for (int o = 16; o; o >>= 1) s += __shfl_xor_sync(0xffffffffu, s, o);
        aw[lane] = e / s;
    }
    __syncthreads();
    const float* Vb = qkv + nb3 + 256;
    float acc = 0.f;
    for (int k = 0; k < KNB; k++) acc += aw[k]*Vb[(size_t)sidx[k]*384 + t];
    out[nb + (size_t)t*Np + n] = acc;
}

__global__ void softmax_kernel(float* __restrict__ S, int M, float scale)
{
    __shared__ float sh[NPTS];
    __shared__ float red[256];
    size_t row = blockIdx.x;
    float* r = S + row*(size_t)M;
    int t = threadIdx.x;
    float mx = -3.4e38f;
    for (int i = t; i < M; i += 256) { float v = r[i]*scale; sh[i] = v; mx = fmaxf(mx, v); }
    red[t] = mx; __syncthreads();
    for (int s = 128; s; s >>= 1) { if (t < s) red[t] = fmaxf(red[t], red[t+s]); __syncthreads(); }
    mx = red[0]; __syncthreads();
    float sum = 0.f;
    for (int i = t; i < M; i += 256) { float e = expf(sh[i] - mx); sh[i] = e; sum += e; }
    red[t] = sum; __syncthreads();
    for (int s = 128; s; s >>= 1) { if (t < s) red[t] += red[t+s]; __syncthreads(); }
    float inv = 1.0f/red[0];
    for (int i = t; i < M; i += 256) r[i] = sh[i]*inv;
}

__global__ void colmean_kernel(const float* __restrict__ S, float* __restrict__ score, int R, int M)
{
    int b = blockIdx.y;
    int m = blockIdx.x*256 + threadIdx.x;
    if (m >= M) return;
    const float* p = S + (size_t)b*R*M + m;
    float s = 0.f;
    for (int n = 0; n < R; n++) s += p[(size_t)n*M];
    score[(size_t)b*M + m] = s / (float)R;
}

__global__ void topm_kernel(const float* __restrict__ score, int* __restrict__ sel)
{
    __shared__ float v[NPTS];
    __shared__ int   id[NPTS];
    int b = blockIdx.x, t = threadIdx.x;
    for (int i = t; i < NPTS; i += 1024) { v[i] = score[(size_t)b*NPTS + i]; id[i] = i; }
    __syncthreads();
    for (int k = 2; k <= NPTS; k <<= 1) {
        for (int j = k >> 1; j > 0; j >>= 1) {
            for (int i = t; i < NPTS; i += 1024) {
                int p = i ^ j;
                if (p > i) {
                    bool up = ((i & k) == 0);
                    float vi = v[i], vp = v[p]; int ii = id[i], ip = id[p];
                    bool inOrder = (vi > vp) || (vi == vp && ii < ip);
                    if (up ? !inOrder : inOrder) { v[i]=vp; v[p]=vi; id[i]=ip; id[p]=ii; }
                }
            }
            __syncthreads();
        }
    }
    for (int i = t; i < MSEL; i += 1024) sel[(size_t)b*MSEL + i] = id[i];
}

__global__ void gather_kernel(const float* __restrict__ x, const int* __restrict__ sel,
                              float* __restrict__ out, int Np, int Ms)
{
    size_t i = (size_t)blockIdx.x*256 + threadIdx.x;
    if (i >= (size_t)BB*CF*Ms) return;
    int j = (int)(i % Ms); size_t tt = i / Ms;
    int c = (int)(tt % CF); int b = (int)(tt / CF);
    out[i] = x[((size_t)b*CF + c)*Np + sel[(size_t)b*Ms + j]];
}

__global__ void add_kernel(const float* __restrict__ a, const float* __restrict__ b,
                           float* __restrict__ o, size_t total)
{
    size_t i = (size_t)blockIdx.x*256 + threadIdx.x;
    if (i < total) o[i] = a[i] + b[i];
}

__global__ void maxmean_kernel(const float* __restrict__ xh, float* __restrict__ g, int Np)
{
    __shared__ float rm[256], rs[256];
    int bo = blockIdx.x;
    int b = bo >> 10, o = bo & 1023;
    const float* p = xh + ((size_t)b*1024 + o)*Np;
    int t = threadIdx.x;
    float mx = -3.4e38f, s = 0.f;
    for (int n = t; n < Np; n += 256) { float v = p[n]; mx = fmaxf(mx, v); s += v; }
    rm[t] = mx; rs[t] = s; __syncthreads();
    for (int st = 128; st; st >>= 1) {
        if (t < st) { rm[t] = fmaxf(rm[t], rm[t+st]); rs[t] += rs[t+st]; }
        __syncthreads();
    }
    if (!t) { g[(size_t)b*2112 + o] = rm[0]; g[(size_t)b*2112 + 1024 + o] = rs[0]/(float)Np; }
}

__global__ void cid_kernel(const float* __restrict__ cat, const float* __restrict__ Wc1,
                           float* __restrict__ g)
{
    int o = threadIdx.x;
    float y[BB];
    for (int b = 0; b < BB; b++) {
        float s = 0.f;
        for (int c = 0; c < 16; c++) s += Wc1[o*16+c]*cat[b*16+c];
        y[b] = s;
    }
    float mu = 0.f;
    for (int b = 0; b < BB; b++) mu += y[b];
    mu *= (1.0f/BB);
    float var = 0.f;
    for (int b = 0; b < BB; b++) { float dd = y[b]-mu; var += dd*dd; }
    var *= (1.0f/BB);
    float rs = rsqrtf(var + 1e-5f);
    for (int b = 0; b < BB; b++) {
        float v = (y[b]-mu)*rs;
        g[(size_t)b*2112 + 2048 + o] = v >= 0.f ? v : LRELU*v;
    }
}

__global__ void bias_kernel(const float* __restrict__ W, const float* __restrict__ g,
                            float* __restrict__ bias)
{
    int gw = blockIdx.x*8 + (threadIdx.x >> 5);
    if (gw >= BB*1024) return;
    int lane = threadIdx.x & 31;
    int b = gw >> 10, o = gw & 1023;
    const float* wr = W + (size_t)o*2240;
    const float* gb = g + (size_t)b*2112;
    float s = 0.f;
    for (int c = lane; c < 2112; c += 32) s += wr[c]*gb[c];
    #pragma unroll
    for (int off = 16; off; off >>= 1) s += __shfl_down_sync(0xffffffffu, s, off);
    if (!lane) bias[(size_t)b*1024 + o] = s;
}

__global__ void addbias_kernel(float* __restrict__ xc, const float* __restrict__ bias)
{
    size_t i = (size_t)blockIdx.x*256 + threadIdx.x;
    if (i >= (size_t)BB*1024*NPTS) return;
    size_t tt = i / NPTS;
    int o = (int)(tt % 1024); int b = (int)(tt / 1024);
    xc[i] += bias[(size_t)b*1024 + o];
}

// ---------------- host orchestration ----------------
struct Bufs {
    float *big,*h,*hfull,*bq,*bk,*bv,*ba,*by,*f1,*s1,*s2,*hd,*hu,*xtmp,*xh,*xc,*xc2;
    float *sq,*score,*gv,*bias,*mu,*rstd;
    int *idx,*sel;
};

static void getbufs(Bufs& P)
{
    cudaGetSymbolAddress((void**)&P.big, g_big);
    cudaGetSymbolAddress((void**)&P.h, g_h);
    cudaGetSymbolAddress((void**)&P.hfull, g_hfull);
    cudaGetSymbolAddress((void**)&P.bq, g_bq);
    cudaGetSymbolAddress((void**)&P.bk, g_bk);
    cudaGetSymbolAddress((void**)&P.bv, g_bv);
    cudaGetSymbolAddress((void**)&P.ba, g_ba);
    cudaGetSymbolAddress((void**)&P.by, g_by);
    cudaGetSymbolAddress((void**)&P.f1, g_f1);
    cudaGetSymbolAddress((void**)&P.s1, g_s1);
    cudaGetSymbolAddress((void**)&P.s2, g_s2);
    cudaGetSymbolAddress((void**)&P.hd, g_hd);
    cudaGetSymbolAddress((void**)&P.hu, g_hu);
    cudaGetSymbolAddress((void**)&P.xtmp, g_xtmp);
    cudaGetSymbolAddress((void**)&P.xh, g_xh);
    cudaGetSymbolAddress((void**)&P.xc, g_xc);
    cudaGetSymbolAddress((void**)&P.xc2, g_xc2);
    cudaGetSymbolAddress((void**)&P.sq, g_sqn);
    cudaGetSymbolAddress((void**)&P.score, g_score);
    cudaGetSymbolAddress((void**)&P.gv, g_gv);
    cudaGetSymbolAddress((void**)&P.bias, g_bias);
    cudaGetSymbolAddress((void**)&P.mu, g_mu);
    cudaGetSymbolAddress((void**)&P.rstd, g_rstd);
    cudaGetSymbolAddress((void**)&P.idx, g_idx);
    cudaGetSymbolAddress((void**)&P.sel, g_sel);
}

static inline size_t cdiv(size_t a, size_t b) { return (a + b - 1)/b; }

static void run_bn(float* x, const float* res, float* out, int Cch, int Np, long bstride, Bufs& P)
{
    bn_stats_kernel<<<Cch, 256>>>(x, P.mu, P.rstd, bstride, Np, 1.0/((double)BB*Np));
    size_t total = (size_t)BB*Cch*Np;
    bn_apply_kernel<<<(unsigned)cdiv(total,256), 256>>>(x, res, out, P.mu, P.rstd, total, Np, Cch, bstride);
}

static void run_knn(const float* xin, long xbs, int cin, int Np, Bufs& P)
{
    dim3 gs((Np+255)/256, BB);
    sqnorm_kernel<<<gs, 256>>>(xin, P.sq, cin, Np, xbs);
    int nt = Np >> 7;
    dim3 grid(nt*(nt+1)/2, 1, BB);
    syrk_kernel<<<grid, 256>>>(xin, P.big, Np, cin, xbs);
    knn_topk_kernel<<<BB*Np, 256>>>(P.big, P.sq, P.idx, Np);
}

static void run_edge(const float* xin, long xbs, int cin, const float* W, int rowlen,
                     float* outslice, long out_bs, Bufs& P)
{
    run_knn(xin, xbs, cin, NPTS, P);
    gemmWn(W,       CF, cin, rowlen, xin, xbs, NPTS, P.bq);
    gemmWn(W + cin, CF, cin, rowlen, xin, xbs, NPTS, P.bk);
    edge_pass1_kernel<<<BB*NPTS, 128>>>(P.bq, P.bk, P.idx, outslice, P.s1, P.s2, NPTS, out_bs);
    size_t total = (size_t)BB*CF*NPTS;
    bn_stats2_kernel<<<CF, 256>>>(P.s1, P.s2, P.mu, P.rstd, (long)CF*NPTS, NPTS,
                                  1.0/((double)BB*NPTS*KNB));
    bn_apply_kernel<<<(unsigned)cdiv(total,256), 256>>>(outslice, nullptr, outslice, P.mu, P.rstd,
                                                        total, NPTS, CF, out_bs);
}

static void run_n2p(const float* xin, long xbs, int cin, int Np,
                    const float* Wq, const float* Wk, const float* Wv, const float* Wo,
                    const float* Wf1, const float* Wf2, float* outp, Bufs& P)
{
    run_knn(xin, xbs, cin, Np, P);
    long fbs = (long)CF*Np;
    size_t wsz = (size_t)CF*cin*sizeof(float);
    cudaMemcpyAsync(P.s1,            Wq, wsz, cudaMemcpyDeviceToDevice);
    cudaMemcpyAsync(P.s1 + CF*cin,   Wk, wsz, cudaMemcpyDeviceToDevice);
    cudaMemcpyAsync(P.s1 + 2*CF*cin, Wv, wsz, cudaMemcpyDeviceToDevice);
    gemmWn(P.s1, 3*CF, cin, cin, xin, xbs, Np, P.f1);
    attn_kernel<<<BB*Np, 128>>>(P.f1, P.idx, P.ba, Np);
    gemmW(Wo, CF, CF, CF, P.ba, fbs, Np, P.by, fbs);
    run_bn(P.by, nullptr, P.by, CF, Np, fbs, P);
    long f1bs = 512L*Np;
    gemmW(Wf1, 512, CF, CF, P.by, fbs, Np, P.f1, f1bs);
    run_bn(P.f1, nullptr, P.f1, 512, Np, f1bs, P);
    gemmW(Wf2, CF, 512, 512, P.f1, f1bs, Np, P.bq, fbs);
    bn_stats_kernel<<<CF, 256>>>(P.bq, P.mu, P.rstd, fbs, Np, 1.0/((double)BB*Np));
    size_t total = (size_t)BB*CF*Np;
    bn_apply_kernel<<<(unsigned)cdiv(total,256), 256>>>(P.bq, P.by, outp, P.mu, P.rstd,
                                                        total, Np, CF, fbs);
}

extern "C" void kernel_launch(void* const* d_in, const int* in_sizes, int n_in,
                              void* d_out, int out_size)
{
    const float* x    = (const float*)d_in[0];
    const float* cat  = (const float*)d_in[1];
    const float* We0  = (const float*)d_in[2];
    const float* We1  = (const float*)d_in[3];
    const float *Wq[3], *Wk[3], *Wv[3], *Wo[3], *Wf1[3], *Wf2[3];
    for (int l = 0; l < 3; l++) {
        Wq[l]  = (const float*)d_in[4 + 6*l];
        Wk[l]  = (const float*)d_in[5 + 6*l];
        Wv[l]  = (const float*)d_in[6 + 6*l];
        Wo[l]  = (const float*)d_in[7 + 6*l];
        Wf1[l] = (const float*)d_in[8 + 6*l];
        Wf2[l] = (const float*)d_in[9 + 6*l];
    }
    const float* Wdq = (const float*)d_in[22];
    const float* Wdk = (const float*)d_in[23];
    const float* Wuq = (const float*)d_in[24];
    const float* Wuk = (const float*)d_in[25];
    const float* Wuv = (const float*)d_in[26];
    const float* Wc  = (const float*)d_in[27];
    const float* Wc1 = (const float*)d_in[28];
    const float* Wc2 = (const float*)d_in[29];
    const float* Wc3 = (const float*)d_in[30];
    const float* Wc4 = (const float*)d_in[31];

    Bufs P; getbufs(P);
    const long HBS = 256L*NPTS;
    const long FBS = (long)CF*NPTS;

    run_edge(x,   3L*NPTS, 3,   We0, 6,   P.h,             HBS, P);
    run_edge(P.h, HBS,     128, We1, 256, P.h + 128L*NPTS, HBS, P);

    run_n2p(P.h, HBS, 256, NPTS, Wq[0], Wk[0], Wv[0], Wo[0], Wf1[0], Wf2[0], P.hfull, P);

    // down_global
    gemmW(Wdq, CF, CF, CF, P.hfull, FBS, NPTS, P.bq, FBS);
    gemmW(Wdk, CF, CF, CF, P.hfull, FBS, NPTS, P.bk, FBS);
    gemmTN(P.bq, FBS, NPTS, P.bk, FBS, NPTS, CF, P.big);
    softmax_kernel<<<BB*NPTS, 256>>>(P.big, NPTS, ATTN_SCALE);
    {
        dim3 gs((NPTS+255)/256, BB);
        colmean_kernel<<<gs, 256>>>(P.big, P.score, NPTS, NPTS);
    }
    topm_kernel<<<BB, 1024>>>(P.score, P.sel);
    {
        size_t total = (size_t)BB*CF*MSEL;
        gather_kernel<<<(unsigned)cdiv(total,256), 256>>>(P.hfull, P.sel, P.hd, NPTS, MSEL);
    }

    run_n2p(P.hd, (long)CF*MSEL, CF, MSEL, Wq[1], Wk[1], Wv[1], Wo[1], Wf1[1], Wf2[1], P.hd, P);

    // up_cross
    gemmW(Wuq, CF, CF, CF, P.hfull, FBS, NPTS, P.bq, FBS);
    gemmW(Wuk, CF, CF, CF, P.hd, (long)CF*MSEL, MSEL, P.bk, (long)CF*MSEL);
    gemmW(Wuv, CF, CF, CF, P.hd, (long)CF*MSEL, MSEL, P.bv, (long)CF*MSEL);
    gemmTN(P.bq, FBS, NPTS, P.bk, (long)CF*MSEL, MSEL, CF, P.big);
    softmax_kernel<<<BB*NPTS, 256>>>(P.big, MSEL, ATTN_SCALE);
    gemm_launch(P.bv, P.big, P.hu, BB, CF, NPTS, MSEL,
                (long)CF*MSEL, MSEL, 1,
                (long)NPTS*MSEL, 1, MSEL,
                FBS, NPTS);
    {
        size_t total = (size_t)BB*CF*NPTS;
        add_kernel<<<(unsigned)cdiv(total,256), 256>>>(P.hfull, P.hu, P.hu, total);
    }

    run_n2p(P.hu, FBS, CF, NPTS, Wq[2], Wk[2], Wv[2], Wo[2], Wf1[2], Wf2[2], P.xtmp, P);

    gemmW(Wc, 1024, CF, CF, P.xtmp, FBS, NPTS, P.xh, 1024L*NPTS);
    run_bn(P.xh, nullptr, P.xh, 1024, NPTS, 1024L*NPTS, P);

    maxmean_kernel<<<BB*1024, 256>>>(P.xh, P.gv, NPTS);
    cid_kernel<<<1, 64>>>(cat, Wc1, P.gv);
    bias_kernel<<<1024, 256>>>(Wc2, P.gv, P.bias);

    gemmW(Wc2 + 2112, 1024, CF, 2240, P.xtmp, FBS, NPTS, P.xc, 1024L*NPTS);
    {
        size_t total = (size_t)BB*1024*NPTS;
        addbias_kernel<<<(unsigned)cdiv(total,256), 256>>>(P.xc, P.bias);
    }
    run_bn(P.xc, nullptr, P.xc, 1024, NPTS, 1024L*NPTS, P);

    gemmW(Wc3, 256, 1024, 1024, P.xc, 1024L*NPTS, NPTS, P.xc2, 256L*NPTS);
    run_bn(P.xc2, nullptr, P.xc2, 256, NPTS, 256L*NPTS, P);

    gemmW(Wc4, 50, 256, 256, P.xc2, 256L*NPTS, NPTS, (float*)d_out, 50L*NPTS);

    (void)in_sizes; (void)n_in; (void)out_size;
}

// round 16
// speedup vs baseline: 1.4941x; 1.0239x over previous
#include <cuda_runtime.h>
#include <math.h>

#define BB 8
#define NPTS 2048
#define KNB 32
#define MSEL 1024
#define CF 128
#define LRELU 0.2f
#define ATTN_SCALE 0.088388347648318447f

// ---------------- static device scratch ----------------
static __device__ float g_big[(size_t)BB*NPTS*NPTS];
static __device__ float g_h[(size_t)BB*256*NPTS];
static __device__ float g_hfull[(size_t)BB*CF*NPTS];
static __device__ float g_bq[(size_t)BB*CF*NPTS];
static __device__ float g_bk[(size_t)BB*CF*NPTS];
static __device__ float g_bv[(size_t)BB*CF*NPTS];
static __device__ float g_ba[(size_t)BB*CF*NPTS];
static __device__ float g_by[(size_t)BB*CF*NPTS];
static __device__ float g_f1[(size_t)BB*512*NPTS];
static __device__ float g_s1[(size_t)BB*CF*NPTS];
static __device__ float g_s2[(size_t)BB*CF*NPTS];
static __device__ float g_hd[(size_t)BB*CF*MSEL];
static __device__ float g_hu[(size_t)BB*CF*NPTS];
static __device__ float g_xtmp[(size_t)BB*CF*NPTS];
static __device__ float g_xh[(size_t)BB*1024*NPTS];
static __device__ float g_xc[(size_t)BB*1024*NPTS];
static __device__ float g_xc2[(size_t)BB*256*NPTS];
static __device__ float g_sqn[(size_t)BB*NPTS];
static __device__ float g_score[(size_t)BB*NPTS];
static __device__ float g_gv[(size_t)BB*2112];
static __device__ float g_bias[(size_t)BB*1024];
static __device__ float g_mu[1024];
static __device__ float g_rstd[1024];
static __device__ int   g_idx[(size_t)BB*NPTS*KNB];
static __device__ int   g_sel[(size_t)BB*MSEL];

// ---------------- SYRK: O = X^T X (symmetric, bitwise), upper triangle + mirror ----
__global__ void __launch_bounds__(256, 2)
syrk_kernel(const float* __restrict__ X, float* __restrict__ O,
            int Np, int Kd, long xbs)
{
    __shared__ float As[2][8][132];
    __shared__ float Bs[2][8][132];
    int bz = blockIdx.z;
    const float* Xb = X + (long)bz*xbs;
    float* Ob = O + (size_t)bz*Np*Np;
    int nt = Np >> 7;
    int t = blockIdx.x, bi = 0, rem = nt;
    while (t >= rem) { t -= rem; bi++; rem--; }
    int bj = bi + t;
    int i0 = bi << 7, j0 = bj << 7;

    int tid = threadIdx.x;
    int tx = tid & 15, ty = tid >> 4;
    int lk = tid >> 5, lv = (tid & 31) * 4;

    float ra[4], rb[4];
    auto fetch = [&](int k0) {
        if (k0 + lk < Kd) {
            float4 a = *reinterpret_cast<const float4*>(&Xb[(long)(k0+lk)*Np + (i0+lv)]);
            ra[0]=a.x; ra[1]=a.y; ra[2]=a.z; ra[3]=a.w;
            float4 b = *reinterpret_cast<const float4*>(&Xb[(long)(k0+lk)*Np + (j0+lv)]);
            rb[0]=b.x; rb[1]=b.y; rb[2]=b.z; rb[3]=b.w;
        } else {
            ra[0]=ra[1]=ra[2]=ra[3]=0.f;
            rb[0]=rb[1]=rb[2]=rb[3]=0.f;
        }
    };
    auto commit = [&](int s) {
        *reinterpret_cast<float4*>(&As[s][lk][lv]) = make_float4(ra[0],ra[1],ra[2],ra[3]);
        *reinterpret_cast<float4*>(&Bs[s][lk][lv]) = make_float4(rb[0],rb[1],rb[2],rb[3]);
    };

    float acc[8][8] = {};
    fetch(0); commit(0);
    __syncthreads();
    int s = 0;
    for (int k0 = 0; k0 < Kd; k0 += 8) {
        int kn = k0 + 8;
        bool more = (kn < Kd);
        if (more) fetch(kn);
        #pragma unroll
        for (int kk = 0; kk < 8; kk++) {
            float4 a0 = *(const float4*)&As[s][kk][ty*8];
            float4 a1 = *(const float4*)&As[s][kk][ty*8+4];
            float4 b0 = *(const float4*)&Bs[s][kk][tx*8];
            float4 b1 = *(const float4*)&Bs[s][kk][tx*8+4];
            float av[8] = {a0.x,a0.y,a0.z,a0.w,a1.x,a1.y,a1.z,a1.w};
            float bw[8] = {b0.x,b0.y,b0.z,b0.w,b1.x,b1.y,b1.z,b1.w};
            #pragma unroll
            for (int u = 0; u < 8; u++)
                #pragma unroll
                for (int v = 0; v < 8; v++) acc[u][v] += av[u]*bw[v];
        }
        if (more) commit(s^1);
        __syncthreads();
        s ^= 1;
    }
    #pragma unroll
    for (int u = 0; u < 8; u++) {
        int i = i0 + ty*8 + u;
        *reinterpret_cast<float4*>(&Ob[(size_t)i*Np + j0 + tx*8]) =
            make_float4(acc[u][0], acc[u][1], acc[u][2], acc[u][3]);
        *reinterpret_cast<float4*>(&Ob[(size_t)i*Np + j0 + tx*8 + 4]) =
            make_float4(acc[u][4], acc[u][5], acc[u][6], acc[u][7]);
    }
    if (bi != bj) {
        float* Ms = &As[0][0][0];
        for (int vv = 0; vv < 8; vv++) {
            __syncthreads();
            #pragma unroll
            for (int u = 0; u < 8; u++) Ms[tx*132 + ty*8 + u] = acc[u][vv];
            __syncthreads();
            int jl = tid >> 4;
            int ic = (tid & 15) * 8;
            int jg = j0 + jl*8 + vv;
            float4 w0 = *reinterpret_cast<float4*>(&Ms[jl*132 + ic]);
            float4 w1 = *reinterpret_cast<float4*>(&Ms[jl*132 + ic + 4]);
            *reinterpret_cast<float4*>(&Ob[(size_t)jg*Np + i0 + ic]) = w0;
            *reinterpret_cast<float4*>(&Ob[(size_t)jg*Np + i0 + ic + 4]) = w1;
        }
    }
}

// ---------------- templated 128x128 GEMM (modes compile-time) ----------------
template<int AM, int BM>
__global__ void __launch_bounds__(256, 2)
gemm128_t(const float* __restrict__ A, const float* __restrict__ Bm,
          float* __restrict__ O, int I, int J, int Kd,
          long a_b, long a_i, long a_k,
          long b_b, long b_k, long b_j,
          long o_b, long o_i)
{
    __shared__ float As[2][8][132];
    __shared__ float Bs[2][8][132];
    int bz = blockIdx.z;
    const float* Ab = A + (long)bz*a_b;
    const float* Bb = Bm + (long)bz*b_b;
    int i0 = blockIdx.y*128, j0 = blockIdx.x*128;
    int tid = threadIdx.x;
    int tx = tid & 15, ty = tid >> 4;
    int lk  = tid >> 5;
    int lv  = (tid & 31) * 4;
    int li  = tid >> 1;
    int lkv = (tid & 1) * 4;

    float ra[4], rb[4];

    auto fetchA = [&](int k0) {
        if constexpr (AM == 0) {
            if (k0 + lk < Kd) {
                const float4 v = *reinterpret_cast<const float4*>(&Ab[(long)(k0+lk)*a_k + (i0+lv)]);
                ra[0]=v.x; ra[1]=v.y; ra[2]=v.z; ra[3]=v.w;
            } else { ra[0]=ra[1]=ra[2]=ra[3]=0.f; }
        } else {
            long base = (long)(i0+li)*a_i + k0 + lkv;
            bool iok = (i0+li) < I;
            if (iok && (k0+lkv+3) < Kd) {
                const float4 v = *reinterpret_cast<const float4*>(&Ab[base]);
                ra[0]=v.x; ra[1]=v.y; ra[2]=v.z; ra[3]=v.w;
            } else {
                #pragma unroll
                for (int q = 0; q < 4; q++)
                    ra[q] = (iok && (k0+lkv+q) < Kd) ? Ab[base+q] : 0.f;
            }
        }
    };
    auto commitA = [&](int s) {
        if constexpr (AM == 0) {
            *reinterpret_cast<float4*>(&As[s][lk][lv]) = make_float4(ra[0],ra[1],ra[2],ra[3]);
        } else {
            #pragma unroll
            for (int q = 0; q < 4; q++) As[s][lkv+q][li] = ra[q];
        }
    };
    auto fetchB = [&](int k0) {
        if constexpr (BM == 0) {
            if (k0 + lk < Kd) {
                const float4 v = *reinterpret_cast<const float4*>(&Bb[(long)(k0+lk)*b_k + (j0+lv)]);
                rb[0]=v.x; rb[1]=v.y; rb[2]=v.z; rb[3]=v.w;
            } else { rb[0]=rb[1]=rb[2]=rb[3]=0.f; }
        } else {
            long base = (long)(j0+li)*b_j + k0 + lkv;
            bool jok = (j0+li) < J;
            if (jok && (k0+lkv+3) < Kd) {
                const float4 v = *reinterpret_cast<const float4*>(&Bb[base]);
                rb[0]=v.x; rb[1]=v.y; rb[2]=v.z; rb[3]=v.w;
            } else {
                #pragma unroll
                for (int q = 0; q < 4; q++)
                    rb[q] = (jok && (k0+lkv+q) < Kd) ? Bb[base+q] : 0.f;
            }
        }
    };
    auto commitB = [&](int s) {
        if constexpr (BM == 0) {
            *reinterpret_cast<float4*>(&Bs[s][lk][lv]) = make_float4(rb[0],rb[1],rb[2],rb[3]);
        } else {
            #pragma unroll
            for (int q = 0; q < 4; q++) Bs[s][lkv+q][li] = rb[q];
        }
    };

    float acc[8][8] = {};
    fetchA(0); fetchB(0);
    commitA(0); commitB(0);
    __syncthreads();
    int s = 0;
    for (int k0 = 0; k0 < Kd; k0 += 8) {
        int kn = k0 + 8;
        bool more = (kn < Kd);
        if (more) { fetchA(kn); fetchB(kn); }
        #pragma unroll
        for (int kk = 0; kk < 8; kk++) {
            float4 a0 = *(const float4*)&As[s][kk][ty*8];
            float4 a1 = *(const float4*)&As[s][kk][ty*8+4];
            float4 b0 = *(const float4*)&Bs[s][kk][tx*8];
            float4 b1 = *(const float4*)&Bs[s][kk][tx*8+4];
            float av[8] = {a0.x,a0.y,a0.z,a0.w,a1.x,a1.y,a1.z,a1.w};
            float bw[8] = {b0.x,b0.y,b0.z,b0.w,b1.x,b1.y,b1.z,b1.w};
            #pragma unroll
            for (int u = 0; u < 8; u++)
                #pragma unroll
                for (int v = 0; v < 8; v++) acc[u][v] += av[u]*bw[v];
        }
        if (more) { commitA(s^1); commitB(s^1); }
        __syncthreads();
        s ^= 1;
    }
    #pragma unroll
    for (int u = 0; u < 8; u++) {
        int i = i0 + ty*8 + u;
        if (i >= I) continue;
        #pragma unroll
        for (int v = 0; v < 8; v++) {
            int j = j0 + tx*8 + v;
            if (j < J) O[(long)bz*o_b + (long)i*o_i + j] = acc[u][v];
        }
    }
}

// 64x64 tile, 4x4 microtile (small grids, odd strides)
__global__ void __launch_bounds__(256)
gemm_kernel64(const float* __restrict__ A, const float* __restrict__ Bm,
              float* __restrict__ O, int I, int J, int Kd,
              long a_b, long a_i, long a_k,
              long b_b, long b_k, long b_j,
              long o_b, long o_i)
{
    __shared__ float As[16*65];
    __shared__ float Bs[16*65];
    int bz = blockIdx.z;
    const float* Ab = A + (long)bz*a_b;
    const float* Bb = Bm + (long)bz*b_b;
    int i0 = blockIdx.y*64, j0 = blockIdx.x*64;
    int tid = threadIdx.x;
    int tx = tid & 15, ty = tid >> 4;
    float acc[4][4] = {};
    for (int k0 = 0; k0 < Kd; k0 += 16) {
        #pragma unroll
        for (int r = 0; r < 4; r++) {
            int e = tid + r*256;
            int kk, ii;
            if (a_k == 1) { ii = e >> 4; kk = e & 15; } else { kk = e >> 6; ii = e & 63; }
            float v = 0.f;
            if (i0+ii < I && k0+kk < Kd) v = Ab[(long)(i0+ii)*a_i + (long)(k0+kk)*a_k];
            As[kk*65+ii] = v;
        }
        #pragma unroll
        for (int r = 0; r < 4; r++) {
            int e = tid + r*256;
            int kk, jj;
            if (b_j == 1) { kk = e >> 6; jj = e & 63; } else { jj = e >> 4; kk = e & 15; }
            float v = 0.f;
            if (j0+jj < J && k0+kk < Kd) v = Bb[(long)(k0+kk)*b_k + (long)(j0+jj)*b_j];
            Bs[kk*65+jj] = v;
        }
        __syncthreads();
        #pragma unroll
        for (int kk = 0; kk < 16; kk++) {
            float av[4], bv[4];
            #pragma unroll
            for (int u = 0; u < 4; u++) av[u] = As[kk*65 + ty*4 + u];
            #pragma unroll
            for (int v = 0; v < 4; v++) bv[v] = Bs[kk*65 + tx*4 + v];
            #pragma unroll
            for (int u = 0; u < 4; u++)
                #pragma unroll
                for (int v = 0; v < 4; v++) acc[u][v] += av[u]*bv[v];
        }
        __syncthreads();
    }
    #pragma unroll
    for (int u = 0; u < 4; u++) {
        int i = i0 + ty*4 + u;
        if (i >= I) continue;
        #pragma unroll
        for (int v = 0; v < 4; v++) {
            int j = j0 + tx*4 + v;
            if (j < J) O[(long)bz*o_b + (long)i*o_i + j] = acc[u][v];
        }
    }
}

static void gemm_launch(const float* A, const float* B, float* O,
                        int Bn, int I, int J, int Kd,
                        long a_b, long a_i, long a_k,
                        long b_b, long b_k, long b_j,
                        long o_b, long o_i)
{
    long ctas128 = (long)((J+127)/128)*((I+127)/128)*Bn;
    int am = ((a_k != 1) && (a_i == 1) && ((a_k & 3) == 0) && (I % 128 == 0)) ? 0
           : ((a_k == 1) && ((a_i & 3) == 0)) ? 1 : 2;
    int bm = ((b_j == 1) && ((b_k & 3) == 0) && (J % 128 == 0)) ? 0
           : ((b_k == 1) && ((b_j & 3) == 0)) ? 1 : 2;
    if (ctas128 >= 96 && am < 2 && bm < 2) {
        dim3 grid((J+127)/128, (I+127)/128, Bn);
        switch (am*2 + bm) {
            case 0: gemm128_t<0,0><<<grid, 256>>>(A,B,O,I,J,Kd,a_b,a_i,a_k,b_b,b_k,b_j,o_b,o_i); break;
            case 1: gemm128_t<0,1><<<grid, 256>>>(A,B,O,I,J,Kd,a_b,a_i,a_k,b_b,b_k,b_j,o_b,o_i); break;
            case 2: gemm128_t<1,0><<<grid, 256>>>(A,B,O,I,J,Kd,a_b,a_i,a_k,b_b,b_k,b_j,o_b,o_i); break;
            default: gemm128_t<1,1><<<grid, 256>>>(A,B,O,I,J,Kd,a_b,a_i,a_k,b_b,b_k,b_j,o_b,o_i); break;
        }
    } else {
        dim3 grid((J+63)/64, (I+63)/64, Bn);
        gemm_kernel64<<<grid, 256>>>(A,B,O,I,J,Kd,a_b,a_i,a_k,b_b,b_k,b_j,o_b,o_i);
    }
}
// c-major output: O[b, o, n]
static void gemmW(const float* W, int Oc, int Kd, int rowlen,
                  const float* X, long xbs, int Np, float* O, long obs)
{
    gemm_launch(W, X, O, BB, Oc, Np, Kd, 0, rowlen, 1, xbs, Np, 1, obs, Np);
}
// n-major output: O[b, n, o]
static void gemmWn(const float* W, int Oc, int Kd, int rowlen,
                   const float* X, long xbs, int Np, float* O)
{
    gemm_launch(X, W, O, BB, Np, Oc, Kd, xbs, 1, Np, 0, 1, rowlen, (long)Oc*Np, Oc);
}
// X given n-major [b, n, c]; W [Oc x Kd]; c-major output
static void gemmW_nmajorX(const float* W, int Oc, int Kd,
                          const float* Xn, int Np, float* O, long obs)
{
    gemm_launch(W, Xn, O, BB, Oc, Np, Kd, 0, Kd, 1,
                (long)Kd*Np, 1, Kd, obs, Np);
}
static void gemmTN(const float* X, long xbs, int Np,
                   const float* Y, long ybs, int Mp, int Cin, float* S)
{
    gemm_launch(X, Y, S, BB, Np, Mp, Cin, xbs, 1, Np, ybs, Mp, 1, (long)Np*Mp, Mp);
}

// ---------------- helper kernels ----------------
__global__ void sqnorm_kernel(const float* __restrict__ x, float* __restrict__ sq,
                              int Cin, int Np, long bstride)
{
    int b = blockIdx.y;
    int n = blockIdx.x*256 + threadIdx.x;
    if (n >= Np) return;
    const float* p = x + (long)b*bstride + n;
    float s = 0.f;
    for (int c = 0; c < Cin; c++) { float v = p[(long)c*Np]; s += v*v; }
    sq[(long)b*Np + n] = s;
}

__global__ void knn_topk_kernel(const float* __restrict__ inner, const float* __restrict__ sq,
                                int* __restrict__ idxout, int Np)
{
    __shared__ float sv[8][32];
    __shared__ int   si[8][32];
    int row = blockIdx.x;
    int b = row / Np, n = row % Np;
    int t = threadIdx.x, w = t >> 5, lane = t & 31;
    int chunk = Np >> 3;
    int per = chunk >> 5;
    const float* ir = inner + ((size_t)b*Np + n)*Np;
    const float* sqb = sq + (size_t)b*Np;
    float sn = sqb[n];
    int base = w*chunk;
    float dv[8];
    #pragma unroll
    for (int j = 0; j < 8; j++) {
        if (j < per) {
            int m = base + j*32 + lane;
            dv[j] = sn - 2.0f*ir[m] + sqb[m];
        } else dv[j] = 3.4e38f;
    }
    for (int k = 0; k < KNB; k++) {
        float bv = 3.4e38f; int bj = 0;
        #pragma unroll
        for (int j = 0; j < 8; j++) if (dv[j] < bv) { bv = dv[j]; bj = j; }
        int bi = base + bj*32 + lane;
        #pragma unroll
        for (int o = 16; o; o >>= 1) {
            float ov = __shfl_xor_sync(0xffffffffu, bv, o);
            int   oi = __shfl_xor_sync(0xffffffffu, bi, o);
            if (ov < bv || (ov == bv && oi < bi)) { bv = ov; bi = oi; }
        }
        if ((bi & 31) == lane) dv[(bi - base) >> 5] = 3.4e38f;
        if (lane == 0) { sv[w][k] = bv; si[w][k] = bi; }
    }
    __syncthreads();
    if (w == 0) {
        float cv[8]; int ci[8];
        #pragma unroll
        for (int j = 0; j < 8; j++) {
            int c = lane*8 + j;
            cv[j] = sv[c >> 5][c & 31];
            ci[j] = si[c >> 5][c & 31];
        }
        int* op = idxout + (size_t)row*KNB;
        for (int k = 0; k < KNB; k++) {
            float bv = 3.4e38f; int bi = 0x7fffffff; int bj = -1;
            #pragma unroll
            for (int j = 0; j < 8; j++) {
                if (cv[j] < bv || (cv[j] == bv && ci[j] < bi)) { bv = cv[j]; bi = ci[j]; bj = j; }
            }
            float rbv = bv; int rbi = bi;
            #pragma unroll
            for (int o = 16; o; o >>= 1) {
                float ov = __shfl_xor_sync(0xffffffffu, rbv, o);
                int   oi = __shfl_xor_sync(0xffffffffu, rbi, o);
                if (ov < rbv || (ov == rbv && oi < rbi)) { rbv = ov; rbi = oi; }
            }
            if (bj >= 0 && rbi == bi) cv[bj] = 3.4e38f;
            if (lane == 0) op[k] = rbi;
        }
    }
}

__global__ void edge_pass1_kernel(const float* __restrict__ An, const float* __restrict__ Bn_,
                                  const int* __restrict__ idx, float* __restrict__ pre,
                                  float* __restrict__ s1, float* __restrict__ s2,
                                  int Np, long pre_bs)
{
    int bn = blockIdx.x;
    int b = bn / Np, n = bn % Np;
    int t = threadIdx.x;
    size_t nb = (size_t)b*CF*Np;
    __shared__ int sidx[KNB];
    if (t < KNB) sidx[t] = idx[(size_t)bn*KNB + t];
    __syncthreads();
    float a  = An [nb + (size_t)n*CF + t];
    float bm = Bn_[nb + (size_t)n*CF + t];
    float diff = a - bm;
    const float* Br = Bn_ + nb;
    float s = 0.f, ss = 0.f, mx = -3.4e38f;
    #pragma unroll 4
    for (int k = 0; k < KNB; k++) {
        float v = diff + Br[(size_t)sidx[k]*CF + t];
        s += v; ss += v*v; mx = fmaxf(mx, v);
    }
    pre[(size_t)b*pre_bs + (size_t)t*Np + n] = mx;
    size_t ci = nb + (size_t)t*Np + n;
    s1[ci] = s; s2[ci] = ss;
}

__global__ void bn_stats_kernel(const float* __restrict__ x, float* __restrict__ mu,
                                float* __restrict__ rstd, long bstride, int Np, double invcount)
{
    int o = blockIdx.x, t = threadIdx.x;
    double s = 0.0, ss = 0.0;
    for (int b = 0; b < BB; b++) {
        const float* p = x + (long)b*bstride + (long)o*Np;
        for (int n = t; n < Np; n += 256) { double v = p[n]; s += v; ss += v*v; }
    }
    __shared__ double sh1[256], sh2[256];
    sh1[t] = s; sh2[t] = ss; __syncthreads();
    for (int st = 128; st; st >>= 1) {
        if (t < st) { sh1[t] += sh1[t+st]; sh2[t] += sh2[t+st]; }
        __syncthreads();
    }
    if (!t) {
        double m = sh1[0]*invcount;
        double var = sh2[0]*invcount - m*m;
        mu[o] = (float)m;
        rstd[o] = (float)(1.0/sqrt(var + 1e-5));
    }
}

__global__ void bn_stats2_kernel(const float* __restrict__ s1, const float* __restrict__ s2,
                                 float* __restrict__ mu, float* __restrict__ rstd,
                                 long bstride, int Np, double invcount)
{
    int o = blockIdx.x, t = threadIdx.x;
    double s = 0.0, ss = 0.0;
    for (int b = 0; b < BB; b++) {
        const float* p1 = s1 + (long)b*bstride + (long)o*Np;
        const float* p2 = s2 + (long)b*bstride + (long)o*Np;
        for (int n = t; n < Np; n += 256) { s += (double)p1[n]; ss += (double)p2[n]; }
    }
    __shared__ double sh1[256], sh2[256];
    sh1[t] = s; sh2[t] = ss; __syncthreads();
    for (int st = 128; st; st >>= 1) {
        if (t < st) { sh1[t] += sh1[t+st]; sh2[t] += sh2[t+st]; }
        __syncthreads();
    }
    if (!t) {
        double m = sh1[0]*invcount;
        double var = sh2[0]*invcount - m*m;
        mu[o] = (float)m;
        rstd[o] = (float)(1.0/sqrt(var + 1e-5));
    }
}

__global__ void bn_apply_kernel(const float* __restrict__ x, const float* __restrict__ res,
                                float* __restrict__ out, const float* __restrict__ mu,
                                const float* __restrict__ rstd, size_t total,
                                int Np, int Cch, long bstride)
{
    size_t i = (size_t)blockIdx.x*256 + threadIdx.x;
    if (i >= total) return;
    int n = (int)(i % Np); size_t tt = i / Np;
    int o = (int)(tt % Cch); int b = (int)(tt / Cch);
    size_t off = (size_t)b*bstride + (size_t)o*Np + n;
    float v = (x[off] - mu[o]) * rstd[o];
    v = v >= 0.f ? v : LRELU*v;
    out[off] = (res ? res[off] : 0.f) + v;
}

// fused qkv buffer [b, n, 384]; output n-major [b, n, 128] (coalesced stores)
__global__ void attn_kernel(const float* __restrict__ qkv, const int* __restrict__ idx,
                            float* __restrict__ out, int Np)
{
    int bn = blockIdx.x;
    int b = bn / Np, n = bn % Np;
    int t = threadIdx.x, w = t >> 5, lane = t & 31;
    size_t nb3 = (size_t)b*Np*384;
    size_t nb  = (size_t)b*CF*Np;
    __shared__ int   sidx[KNB];
    __shared__ float part[4][KNB];
    __shared__ float aw[KNB];
    if (t < KNB) sidx[t] = idx[(size_t)bn*KNB + t];
    __syncthreads();
    float qc = qkv[nb3 + (size_t)n*384 + t];
    const float* Kb = qkv + nb3 + 128;
    for (int k = 0; k < KNB; k++) {
        float v = qc * Kb[(size_t)sidx[k]*384 + t];
        #pragma unroll
        for (int o = 16; o; o >>= 1) v += __shfl_down_sync(0xffffffffu, v, o);
        if (lane == 0) part[w][k] = v;
    }
    __syncthreads();
    if (w == 0) {
        float l = (part[0][lane] + part[1][lane] + part[2][lane] + part[3][lane]) * ATTN_SCALE;
        float m = l;
        #pragma unroll
        for (int o = 16; o; o >>= 1) m = fmaxf(m, __shfl_xor_sync(0xffffffffu, m, o));
        float e = expf(l - m);
        float s = e;
        #pragma unroll
        for (int o = 16; o; o >>= 1) s += __shfl_xor_sync(0xffffffffu, s, o);
        aw[lane] = e / s;
    }
    __syncthreads();
    const float* Vb = qkv + nb3 + 256;
    float acc = 0.f;
    for (int k = 0; k < KNB; k++) acc += aw[k]*Vb[(size_t)sidx[k]*384 + t];
    out[nb + (size_t)n*CF + t] = acc;   // n-major, coalesced
}

__global__ void softmax_kernel(float* __restrict__ S, int M, float scale)
{
    __shared__ float sh[NPTS];
    __shared__ float red[256];
    size_t row = blockIdx.x;
    float* r = S + row*(size_t)M;
    int t = threadIdx.x;
    float mx = -3.4e38f;
    for (int i = t; i < M; i += 256) { float v = r[i]*scale; sh[i] = v; mx = fmaxf(mx, v); }
    red[t] = mx; __syncthreads();
    for (int s = 128; s; s >>= 1) { if (t < s) red[t] = fmaxf(red[t], red[t+s]); __syncthreads(); }
    mx = red[0]; __syncthreads();
    float sum = 0.f;
    for (int i = t; i < M; i += 256) { float e = expf(sh[i] - mx); sh[i] = e; sum += e; }
    red[t] = sum; __syncthreads();
    for (int s = 128; s; s >>= 1) { if (t < s) red[t] += red[t+s]; __syncthreads(); }
    float inv = 1.0f/red[0];
    for (int i = t; i < M; i += 256) r[i] = sh[i]*inv;
}

__global__ void colmean_kernel(const float* __restrict__ S, float* __restrict__ score, int R, int M)
{
    int b = blockIdx.y;
    int m = blockIdx.x*256 + threadIdx.x;
    if (m >= M) return;
    const float* p = S + (size_t)b*R*M + m;
    float s = 0.f;
    for (int n = 0; n < R; n++) s += p[(size_t)n*M];
    score[(size_t)b*M + m] = s / (float)R;
}

__global__ void topm_kernel(const float* __restrict__ score, int* __restrict__ sel)
{
    __shared__ float v[NPTS];
    __shared__ int   id[NPTS];
    int b = blockIdx.x, t = threadIdx.x;
    for (int i = t; i < NPTS; i += 1024) { v[i] = score[(size_t)b*NPTS + i]; id[i] = i; }
    __syncthreads();
    for (int k = 2; k <= NPTS; k <<= 1) {
        for (int j = k >> 1; j > 0; j >>= 1) {
            for (int i = t; i < NPTS; i += 1024) {
                int p = i ^ j;
                if (p > i) {
                    bool up = ((i & k) == 0);
                    float vi = v[i], vp = v[p]; int ii = id[i], ip = id[p];
                    bool inOrder = (vi > vp) || (vi == vp && ii < ip);
                    if (up ? !inOrder : inOrder) { v[i]=vp; v[p]=vi; id[i]=ip; id[p]=ii; }
                }
            }
            __syncthreads();
        }
    }
    for (int i = t; i < MSEL; i += 1024) sel[(size_t)b*MSEL + i] = id[i];
}

__global__ void gather_kernel(const float* __restrict__ x, const int* __restrict__ sel,
                              float* __restrict__ out, int Np, int Ms)
{
    size_t i = (size_t)blockIdx.x*256 + threadIdx.x;
    if (i >= (size_t)BB*CF*Ms) return;
    int j = (int)(i % Ms); size_t tt = i / Ms;
    int c = (int)(tt % CF); int b = (int)(tt / CF);
    out[i] = x[((size_t)b*CF + c)*Np + sel[(size_t)b*Ms + j]];
}

__global__ void add_kernel(const float* __restrict__ a, const float* __restrict__ b,
                           float* __restrict__ o, size_t total)
{
    size_t i = (size_t)blockIdx.x*256 + threadIdx.x;
    if (i < total) o[i] = a[i] + b[i];
}

__global__ void maxmean_kernel(const float* __restrict__ xh, float* __restrict__ g, int Np)
{
    __shared__ float rm[256], rs[256];
    int bo = blockIdx.x;
    int b = bo >> 10, o = bo & 1023;
    const float* p = xh + ((size_t)b*1024 + o)*Np;
    int t = threadIdx.x;
    float mx = -3.4e38f, s = 0.f;
    for (int n = t; n < Np; n += 256) { float v = p[n]; mx = fmaxf(mx, v); s += v; }
    rm[t] = mx; rs[t] = s; __syncthreads();
    for (int st = 128; st; st >>= 1) {
        if (t < st) { rm[t] = fmaxf(rm[t], rm[t+st]); rs[t] += rs[t+st]; }
        __syncthreads();
    }
    if (!t) { g[(size_t)b*2112 + o] = rm[0]; g[(size_t)b*2112 + 1024 + o] = rs[0]/(float)Np; }
}

__global__ void cid_kernel(const float* __restrict__ cat, const float* __restrict__ Wc1,
                           float* __restrict__ g)
{
    int o = threadIdx.x;
    float y[BB];
    for (int b = 0; b < BB; b++) {
        float s = 0.f;
        for (int c = 0; c < 16; c++) s += Wc1[o*16+c]*cat[b*16+c];
        y[b] = s;
    }
    float mu = 0.f;
    for (int b = 0; b < BB; b++) mu += y[b];
    mu *= (1.0f/BB);
    float var = 0.f;
    for (int b = 0; b < BB; b++) { float dd = y[b]-mu; var += dd*dd; }
    var *= (1.0f/BB);
    float rs = rsqrtf(var + 1e-5f);
    for (int b = 0; b < BB; b++) {
        float v = (y[b]-mu)*rs;
        g[(size_t)b*2112 + 2048 + o] = v >= 0.f ? v : LRELU*v;
    }
}

__global__ void bias_kernel(const float* __restrict__ W, const float* __restrict__ g,
                            float* __restrict__ bias)
{
    int gw = blockIdx.x*8 + (threadIdx.x >> 5);
    if (gw >= BB*1024) return;
    int lane = threadIdx.x & 31;
    int b = gw >> 10, o = gw & 1023;
    const float* wr = W + (size_t)o*2240;
    const float* gb = g + (size_t)b*2112;
    float s = 0.f;
    for (int c = lane; c < 2112; c += 32) s += wr[c]*gb[c];
    #pragma unroll
    for (int off = 16; off; off >>= 1) s += __shfl_down_sync(0xffffffffu, s, off);
    if (!lane) bias[(size_t)b*1024 + o] = s;
}

__global__ void addbias_kernel(float* __restrict__ xc, const float* __restrict__ bias)
{
    size_t i = (size_t)blockIdx.x*256 + threadIdx.x;
    if (i >= (size_t)BB*1024*NPTS) return;
    size_t tt = i / NPTS;
    int o = (int)(tt % 1024); int b = (int)(tt / 1024);
    xc[i] += bias[(size_t)b*1024 + o];
}

// ---------------- host orchestration ----------------
struct Bufs {
    float *big,*h,*hfull,*bq,*bk,*bv,*ba,*by,*f1,*s1,*s2,*hd,*hu,*xtmp,*xh,*xc,*xc2;
    float *sq,*score,*gv,*bias,*mu,*rstd;
    int *idx,*sel;
};

static void getbufs(Bufs& P)
{
    cudaGetSymbolAddress((void**)&P.big, g_big);
    cudaGetSymbolAddress((void**)&P.h, g_h);
    cudaGetSymbolAddress((void**)&P.hfull, g_hfull);
    cudaGetSymbolAddress((void**)&P.bq, g_bq);
    cudaGetSymbolAddress((void**)&P.bk, g_bk);
    cudaGetSymbolAddress((void**)&P.bv, g_bv);
    cudaGetSymbolAddress((void**)&P.ba, g_ba);
    cudaGetSymbolAddress((void**)&P.by, g_by);
    cudaGetSymbolAddress((void**)&P.f1, g_f1);
    cudaGetSymbolAddress((void**)&P.s1, g_s1);
    cudaGetSymbolAddress((void**)&P.s2, g_s2);
    cudaGetSymbolAddress((void**)&P.hd, g_hd);
    cudaGetSymbolAddress((void**)&P.hu, g_hu);
    cudaGetSymbolAddress((void**)&P.xtmp, g_xtmp);
    cudaGetSymbolAddress((void**)&P.xh, g_xh);
    cudaGetSymbolAddress((void**)&P.xc, g_xc);
    cudaGetSymbolAddress((void**)&P.xc2, g_xc2);
    cudaGetSymbolAddress((void**)&P.sq, g_sqn);
    cudaGetSymbolAddress((void**)&P.score, g_score);
    cudaGetSymbolAddress((void**)&P.gv, g_gv);
    cudaGetSymbolAddress((void**)&P.bias, g_bias);
    cudaGetSymbolAddress((void**)&P.mu, g_mu);
    cudaGetSymbolAddress((void**)&P.rstd, g_rstd);
    cudaGetSymbolAddress((void**)&P.idx, g_idx);
    cudaGetSymbolAddress((void**)&P.sel, g_sel);
}

static inline size_t cdiv(size_t a, size_t b) { return (a + b - 1)/b; }

static void run_bn(float* x, const float* res, float* out, int Cch, int Np, long bstride, Bufs& P)
{
    bn_stats_kernel<<<Cch, 256>>>(x, P.mu, P.rstd, bstride, Np, 1.0/((double)BB*Np));
    size_t total = (size_t)BB*Cch*Np;
    bn_apply_kernel<<<(unsigned)cdiv(total,256), 256>>>(x, res, out, P.mu, P.rstd, total, Np, Cch, bstride);
}

static void run_knn(const float* xin, long xbs, int cin, int Np, Bufs& P)
{
    dim3 gs((Np+255)/256, BB);
    sqnorm_kernel<<<gs, 256>>>(xin, P.sq, cin, Np, xbs);
    int nt = Np >> 7;
    dim3 grid(nt*(nt+1)/2, 1, BB);
    syrk_kernel<<<grid, 256>>>(xin, P.big, Np, cin, xbs);
    knn_topk_kernel<<<BB*Np, 256>>>(P.big, P.sq, P.idx, Np);
}

static void run_edge(const float* xin, long xbs, int cin, const float* W, int rowlen,
                     float* outslice, long out_bs, Bufs& P)
{
    run_knn(xin, xbs, cin, NPTS, P);
    gemmWn(W,       CF, cin, rowlen, xin, xbs, NPTS, P.bq);
    gemmWn(W + cin, CF, cin, rowlen, xin, xbs, NPTS, P.bk);
    edge_pass1_kernel<<<BB*NPTS, 128>>>(P.bq, P.bk, P.idx, outslice, P.s1, P.s2, NPTS, out_bs);
    size_t total = (size_t)BB*CF*NPTS;
    bn_stats2_kernel<<<CF, 256>>>(P.s1, P.s2, P.mu, P.rstd, (long)CF*NPTS, NPTS,
                                  1.0/((double)BB*NPTS*KNB));
    bn_apply_kernel<<<(unsigned)cdiv(total,256), 256>>>(outslice, nullptr, outslice, P.mu, P.rstd,
                                                        total, NPTS, CF, out_bs);
}

static void run_n2p(const float* xin, long xbs, int cin, int Np,
                    const float* Wq, const float* Wk, const float* Wv, const float* Wo,
                    const float* Wf1, const float* Wf2, float* outp, Bufs& P)
{
    run_knn(xin, xbs, cin, Np, P);
    long fbs = (long)CF*Np;
    size_t wsz = (size_t)CF*cin*sizeof(float);
    cudaMemcpyAsync(P.s1,            Wq, wsz, cudaMemcpyDeviceToDevice);
    cudaMemcpyAsync(P.s1 + CF*cin,   Wk, wsz, cudaMemcpyDeviceToDevice);
    cudaMemcpyAsync(P.s1 + 2*CF*cin, Wv, wsz, cudaMemcpyDeviceToDevice);
    gemmWn(P.s1, 3*CF, cin, cin, xin, xbs, Np, P.f1);
    attn_kernel<<<BB*Np, 128>>>(P.f1, P.idx, P.ba, Np);   // ba is n-major [b,n,128]
    gemmW_nmajorX(Wo, CF, CF, P.ba, Np, P.by, fbs);
    run_bn(P.by, nullptr, P.by, CF, Np, fbs, P);
    long f1bs = 512L*Np;
    gemmW(Wf1, 512, CF, CF, P.by, fbs, Np, P.f1, f1bs);
    run_bn(P.f1, nullptr, P.f1, 512, Np, f1bs, P);
    gemmW(Wf2, CF, 512, 512, P.f1, f1bs, Np, P.bq, fbs);
    bn_stats_kernel<<<CF, 256>>>(P.bq, P.mu, P.rstd, fbs, Np, 1.0/((double)BB*Np));
    size_t total = (size_t)BB*CF*Np;
    bn_apply_kernel<<<(unsigned)cdiv(total,256), 256>>>(P.bq, P.by, outp, P.mu, P.rstd,
                                                        total, Np, CF, fbs);
}

extern "C" void kernel_launch(void* const* d_in, const int* in_sizes, int n_in,
                              void* d_out, int out_size)
{
    const float* x    = (const float*)d_in[0];
    const float* cat  = (const float*)d_in[1];
    const float* We0  = (const float*)d_in[2];
    const float* We1  = (const float*)d_in[3];
    const float *Wq[3], *Wk[3], *Wv[3], *Wo[3], *Wf1[3], *Wf2[3];
    for (int l = 0; l < 3; l++) {
        Wq[l]  = (const float*)d_in[4 + 6*l];
        Wk[l]  = (const float*)d_in[5 + 6*l];
        Wv[l]  = (const float*)d_in[6 + 6*l];
        Wo[l]  = (const float*)d_in[7 + 6*l];
        Wf1[l] = (const float*)d_in[8 + 6*l];
        Wf2[l] = (const float*)d_in[9 + 6*l];
    }
    const float* Wdq = (const float*)d_in[22];
    const float* Wdk = (const float*)d_in[23];
    const float* Wuq = (const float*)d_in[24];
    const float* Wuk = (const float*)d_in[25];
    const float* Wuv = (const float*)d_in[26];
    const float* Wc  = (const float*)d_in[27];
    const float* Wc1 = (const float*)d_in[28];
    const float* Wc2 = (const float*)d_in[29];
    const float* Wc3 = (const float*)d_in[30];
    const float* Wc4 = (const float*)d_in[31];

    Bufs P; getbufs(P);
    const long HBS = 256L*NPTS;
    const long FBS = (long)CF*NPTS;

    run_edge(x,   3L*NPTS, 3,   We0, 6,   P.h,             HBS, P);
    run_edge(P.h, HBS,     128, We1, 256, P.h + 128L*NPTS, HBS, P);

    run_n2p(P.h, HBS, 256, NPTS, Wq[0], Wk[0], Wv[0], Wo[0], Wf1[0], Wf2[0], P.hfull, P);

    // down_global
    gemmW(Wdq, CF, CF, CF, P.hfull, FBS, NPTS, P.bq, FBS);
    gemmW(Wdk, CF, CF, CF, P.hfull, FBS, NPTS, P.bk, FBS);
    gemmTN(P.bq, FBS, NPTS, P.bk, FBS, NPTS, CF, P.big);
    softmax_kernel<<<BB*NPTS, 256>>>(P.big, NPTS, ATTN_SCALE);
    {
        dim3 gs((NPTS+255)/256, BB);
        colmean_kernel<<<gs, 256>>>(P.big, P.score, NPTS, NPTS);
    }
    topm_kernel<<<BB, 1024>>>(P.score, P.sel);
    {
        size_t total = (size_t)BB*CF*MSEL;
        gather_kernel<<<(unsigned)cdiv(total,256), 256>>>(P.hfull, P.sel, P.hd, NPTS, MSEL);
    }

    run_n2p(P.hd, (long)CF*MSEL, CF, MSEL, Wq[1], Wk[1], Wv[1], Wo[1], Wf1[1], Wf2[1], P.hd, P);

    // up_cross
    gemmW(Wuq, CF, CF, CF, P.hfull, FBS, NPTS, P.bq, FBS);
    gemmW(Wuk, CF, CF, CF, P.hd, (long)CF*MSEL, MSEL, P.bk, (long)CF*MSEL);
    gemmW(Wuv, CF, CF, CF, P.hd, (long)CF*MSEL, MSEL, P.bv, (long)CF*MSEL);
    gemmTN(P.bq, FBS, NPTS, P.bk, (long)CF*MSEL, MSEL, CF, P.big);
    softmax_kernel<<<BB*NPTS, 256>>>(P.big, MSEL, ATTN_SCALE);
    gemm_launch(P.bv, P.big, P.hu, BB, CF, NPTS, MSEL,
                (long)CF*MSEL, MSEL, 1,
                (long)NPTS*MSEL, 1, MSEL,
                FBS, NPTS);
    {
        size_t total = (size_t)BB*CF*NPTS;
        add_kernel<<<(unsigned)cdiv(total,256), 256>>>(P.hfull, P.hu, P.hu, total);
    }

    run_n2p(P.hu, FBS, CF, NPTS, Wq[2], Wk[2], Wv[2], Wo[2], Wf1[2], Wf2[2], P.xtmp, P);

    gemmW(Wc, 1024, CF, CF, P.xtmp, FBS, NPTS, P.xh, 1024L*NPTS);
    run_bn(P.xh, nullptr, P.xh, 1024, NPTS, 1024L*NPTS, P);

    maxmean_kernel<<<BB*1024, 256>>>(P.xh, P.gv, NPTS);
    cid_kernel<<<1, 64>>>(cat, Wc1, P.gv);
    bias_kernel<<<1024, 256>>>(Wc2, P.gv, P.bias);

    gemmW(Wc2 + 2112, 1024, CF, 2240, P.xtmp, FBS, NPTS, P.xc, 1024L*NPTS);
    {
        size_t total = (size_t)BB*1024*NPTS;
        addbias_kernel<<<(unsigned)cdiv(total,256), 256>>>(P.xc, P.bias);
    }
    run_bn(P.xc, nullptr, P.xc, 1024, NPTS, 1024L*NPTS, P);

    gemmW(Wc3, 256, 1024, 1024, P.xc, 1024L*NPTS, NPTS, P.xc2, 256L*NPTS);
    run_bn(P.xc2, nullptr, P.xc2, 256, NPTS, 256L*NPTS, P);

    gemmW(Wc4, 50, 256, 256, P.xc2, 256L*NPTS, NPTS, (float*)d_out, 50L*NPTS);

    (void)in_sizes; (void)n_in; (void)out_size;
}